// round 9
// baseline (speedup 1.0000x reference)
#include <cuda_runtime.h>
#include <cuda_bf16.h>
#include <cstdint>

#define Bb 8
#define Nn 2048
#define Mm 2048
#define DIN 512
#define Hh 256

// ---------------- scratch (device globals; no allocs allowed) ----------------
__device__ uint2 g_qf2[(size_t)Bb*Nn*(DIN/2)];
__device__ uint2 g_vr2[(size_t)Bb*Mm*(DIN/2)];
__device__ uint2 g_w2[6*65536 + 131072 + 32768];
__device__ uint4 g_q4[(size_t)Bb*Nn*128];
__device__ uint4 g_k4[(size_t)Bb*Mm*128];
__device__ float g_vs[(size_t)Bb*Mm*Hh], g_ve[(size_t)Bb*Mm*Hh];
__device__ uint4 g_vT4[(size_t)Bb*Hh*1024];
__device__ float g_L[(size_t)Bb*Nn*Mm];
__device__ float g_D[(size_t)Bb*Nn*Mm];
__device__ uint2 g_p2[(size_t)Bb*Nn*1024];
__device__ uint2 g_f2[(size_t)Bb*Nn*512];
__device__ uint2 g_h2[(size_t)Bb*Nn*128];
__device__ float g_q2[Bb*Nn], g_k2[Bb*Mm], g_dsum[Bb], g_scale[Bb];

// ---------------- helpers ----------------
__device__ __forceinline__ void split2(float f0, float f1, uint32_t& H, uint32_t& L) {
    __nv_bfloat16 h0 = __float2bfloat16(f0);
    __nv_bfloat16 h1 = __float2bfloat16(f1);
    __nv_bfloat16 l0 = __float2bfloat16(f0 - __bfloat162float(h0));
    __nv_bfloat16 l1 = __float2bfloat16(f1 - __bfloat162float(h1));
    H = (uint32_t)__bfloat16_as_ushort(h0) | ((uint32_t)__bfloat16_as_ushort(h1) << 16);
    L = (uint32_t)__bfloat16_as_ushort(l0) | ((uint32_t)__bfloat16_as_ushort(l1) << 16);
}
__device__ __forceinline__ float bflo(uint32_t u) {
    return __bfloat162float(__ushort_as_bfloat16((unsigned short)(u & 0xffff)));
}
__device__ __forceinline__ float bfhi(uint32_t u) {
    return __bfloat162float(__ushort_as_bfloat16((unsigned short)(u >> 16)));
}
__device__ __forceinline__ void mmabf(float* d, const uint32_t* a, uint32_t b0, uint32_t b1) {
    asm volatile(
        "mma.sync.aligned.m16n8k16.row.col.f32.bf16.bf16.f32 "
        "{%0,%1,%2,%3}, {%4,%5,%6,%7}, {%8,%9}, {%0,%1,%2,%3};\n"
        : "+f"(d[0]), "+f"(d[1]), "+f"(d[2]), "+f"(d[3])
        : "r"(a[0]), "r"(a[1]), "r"(a[2]), "r"(a[3]), "r"(b0), "r"(b1));
}
__device__ __forceinline__ void cpa16(void* smem, const void* gmem) {
    uint32_t s = (uint32_t)__cvta_generic_to_shared(smem);
    asm volatile("cp.async.cg.shared.global [%0], [%1], 16;\n" :: "r"(s), "l"(gmem));
}
#define CP_COMMIT() asm volatile("cp.async.commit_group;\n")
#define CP_WAIT1()  asm volatile("cp.async.wait_group 1;\n")
#define CP_WAIT0()  asm volatile("cp.async.wait_group 0;\n")

__device__ __forceinline__ float warpRedSum(float v) {
#pragma unroll
    for (int o = 16; o > 0; o >>= 1) v += __shfl_xor_sync(0xffffffffu, v, o);
    return v;
}
__device__ __forceinline__ float warpRedMax(float v) {
#pragma unroll
    for (int o = 16; o > 0; o >>= 1) v = fmaxf(v, __shfl_xor_sync(0xffffffffu, v, o));
    return v;
}

// ---------------- prep kernels ----------------
__global__ void pack_rows_kernel(const float* __restrict__ src,
                                 uint2* __restrict__ dst, int npairs) {
    int i = blockIdx.x * 256 + threadIdx.x;
    if (i >= npairs) return;
    float2 f = ((const float2*)src)[i];
    uint32_t h, l; split2(f.x, f.y, h, l);
    dst[i] = make_uint2(h, l);
}
__global__ void pack_weight_kernel(const float* __restrict__ W,
                                   uint2* __restrict__ dst, int Kp, int Nc) {
    int i = blockIdx.x * 256 + threadIdx.x;
    if (i >= Kp * Nc) return;
    int n = i / Kp, kp = i - n * Kp;
    float f0 = W[(size_t)(2 * kp) * Nc + n];
    float f1 = W[(size_t)(2 * kp + 1) * Nc + n];
    uint32_t h, l; split2(f0, f1, h, l);
    dst[i] = make_uint2(h, l);
}
__global__ void transpose_pack2_kernel(const float* __restrict__ Vs,
                                       const float* __restrict__ Ve,
                                       uint4* __restrict__ T4) {
    __shared__ float ts[64][33], te[64][33];
    const int b = blockIdx.z, m0 = blockIdx.x * 64, h0 = blockIdx.y * 32;
    const int tid = threadIdx.x;
#pragma unroll
    for (int it = 0; it < 2; it++) {
        int i = tid + it * 256;
        int m = i >> 3, h4 = (i & 7) * 4;
        size_t off = ((size_t)b * Mm + m0 + m) * Hh + h0 + h4;
        float4 v = *(const float4*)&Vs[off];
        ts[m][h4 + 0] = v.x; ts[m][h4 + 1] = v.y; ts[m][h4 + 2] = v.z; ts[m][h4 + 3] = v.w;
        v = *(const float4*)&Ve[off];
        te[m][h4 + 0] = v.x; te[m][h4 + 1] = v.y; te[m][h4 + 2] = v.z; te[m][h4 + 3] = v.w;
    }
    __syncthreads();
#pragma unroll
    for (int u = 0; u < 4; u++) {
        int i = tid + u * 256;
        int h = i >> 5, mp = i & 31;
        uint32_t sh, sl, eh, el;
        split2(ts[2 * mp][h], ts[2 * mp + 1][h], sh, sl);
        split2(te[2 * mp][h], te[2 * mp + 1][h], eh, el);
        T4[((size_t)b * Hh + h0 + h) * 1024 + (m0 >> 1) + mp] = make_uint4(sh, sl, eh, el);
    }
}
__global__ void rowsumsq_kernel(const uint4* __restrict__ P4, float* __restrict__ dst) {
    const int row = blockIdx.x, tid = threadIdx.x;
    uint4 q = P4[(size_t)row * 128 + tid];
    float v0 = bflo(q.z) + bflo(q.w), v1 = bfhi(q.z) + bfhi(q.w);
    float s = v0 * v0 + v1 * v1;
    __shared__ float sh[4];
    int lane = tid & 31, wid = tid >> 5;
    float w = warpRedSum(s);
    if (lane == 0) sh[wid] = w;
    __syncthreads();
    if (wid == 0) {
        float t = (lane < 4) ? sh[lane] : 0.0f;
        t = warpRedSum(t);
        if (lane == 0) dst[row] = t;
    }
}
__global__ void zero_dsum_kernel() { if (threadIdx.x < Bb) g_dsum[threadIdx.x] = 0.0f; }
__global__ void finalize_scale_kernel() {
    if (threadIdx.x < Bb)
        g_scale[threadIdx.x] = fmaxf(g_dsum[threadIdx.x] * (1.0f / ((float)Nn * (float)Mm)), 1e-4f);
}

// =============================================================================
// Dual-output projection GEMM (product-outer mma issue).
// =============================================================================
__global__ __launch_bounds__(256, 2) void gemm2_kernel(
    const uint2* __restrict__ a2,
    const uint2* __restrict__ wa, const uint2* __restrict__ wb,
    const float* __restrict__ biasA, const float* __restrict__ biasB,
    uint4* __restrict__ out4,
    float* __restrict__ outFa, float* __restrict__ outFb,
    int Kp)
{
    extern __shared__ uint32_t smu[];
    uint2* smA  = (uint2*)smu;       // [2][128][12]
    uint2* smB1 = smA + 3072;        // [2][64][12]
    uint2* smB2 = smB1 + 1536;       // [2][64][12]

    const int row0 = blockIdx.y * 128;
    const int col0 = blockIdx.x * 64;
    const int tid  = threadIdx.x;
    const int lane = tid & 31, warp = tid >> 5;
    const int wR = warp >> 1, wC = warp & 1;

    float acc1[2][4][4] = {}, acc2[2][4][4] = {};
    const int nk = Kp / 8;

    {   // prologue
#pragma unroll
        for (int it = 0; it < 2; it++) {
            int i = tid + it * 256;
            int r = i >> 2, c2 = (i & 3) * 2;
            cpa16(&smA[(size_t)r * 12 + c2], a2 + (size_t)(row0 + r) * Kp + c2);
        }
        {
            int r = tid >> 2, c2 = (tid & 3) * 2;
            cpa16(&smB1[(size_t)r * 12 + c2], wa + (size_t)(col0 + r) * Kp + c2);
            cpa16(&smB2[(size_t)r * 12 + c2], wb + (size_t)(col0 + r) * Kp + c2);
        }
        CP_COMMIT();
    }

    for (int kt = 0; kt < nk; kt++) {
        const int s = kt & 1;
        if (kt + 1 < nk) {
            const int sn = s ^ 1;
            const int k0 = (kt + 1) * 8;
#pragma unroll
            for (int it = 0; it < 2; it++) {
                int i = tid + it * 256;
                int r = i >> 2, c2 = (i & 3) * 2;
                cpa16(&smA[(size_t)(sn * 128 + r) * 12 + c2],
                      a2 + (size_t)(row0 + r) * Kp + k0 + c2);
            }
            {
                int r = tid >> 2, c2 = (tid & 3) * 2;
                cpa16(&smB1[(size_t)(sn * 64 + r) * 12 + c2],
                      wa + (size_t)(col0 + r) * Kp + k0 + c2);
                cpa16(&smB2[(size_t)(sn * 64 + r) * 12 + c2],
                      wb + (size_t)(col0 + r) * Kp + k0 + c2);
            }
            CP_COMMIT();
            CP_WAIT1();
        } else {
            CP_WAIT0();
        }
        __syncthreads();

        const int kk = lane & 3;
        uint32_t ah[2][4], al[2][4];
#pragma unroll
        for (int i = 0; i < 2; i++) {
            int m = s * 128 + wR * 32 + i * 16 + (lane >> 2);
            uint2 p0 = smA[(size_t)m * 12 + kk];
            uint2 p1 = smA[(size_t)(m + 8) * 12 + kk];
            uint2 p2 = smA[(size_t)m * 12 + kk + 4];
            uint2 p3 = smA[(size_t)(m + 8) * 12 + kk + 4];
            ah[i][0] = p0.x; ah[i][1] = p1.x; ah[i][2] = p2.x; ah[i][3] = p3.x;
            al[i][0] = p0.y; al[i][1] = p1.y; al[i][2] = p2.y; al[i][3] = p3.y;
        }
#pragma unroll
        for (int j = 0; j < 4; j++) {
            int n = s * 64 + wC * 32 + j * 8 + (lane >> 2);
            uint2 b10 = smB1[(size_t)n * 12 + kk];
            uint2 b11 = smB1[(size_t)n * 12 + kk + 4];
            uint2 b20 = smB2[(size_t)n * 12 + kk];
            uint2 b21 = smB2[(size_t)n * 12 + kk + 4];
            // product-outer: same-acc reuse distance = 4 mma
#pragma unroll
            for (int i = 0; i < 2; i++) {
                mmabf(acc1[i][j], ah[i], b10.x, b11.x);
                mmabf(acc2[i][j], ah[i], b20.x, b21.x);
            }
#pragma unroll
            for (int i = 0; i < 2; i++) {
                mmabf(acc1[i][j], ah[i], b10.y, b11.y);
                mmabf(acc2[i][j], ah[i], b20.y, b21.y);
            }
#pragma unroll
            for (int i = 0; i < 2; i++) {
                mmabf(acc1[i][j], al[i], b10.x, b11.x);
                mmabf(acc2[i][j], al[i], b20.x, b21.x);
            }
        }
        __syncthreads();
    }

#pragma unroll
    for (int i = 0; i < 2; i++) {
        int r = row0 + wR * 32 + i * 16 + (lane >> 2);
#pragma unroll
        for (int j = 0; j < 4; j++) {
            int c = col0 + wC * 32 + j * 8 + 2 * (lane & 3);
            float ba0 = biasA[c], ba1 = biasA[c + 1];
            float bb0 = biasB[c], bb1 = biasB[c + 1];
#pragma unroll
            for (int half = 0; half < 2; half++) {
                int rr = r + half * 8;
                float va0 = acc1[i][j][half * 2 + 0] + ba0;
                float va1 = acc1[i][j][half * 2 + 1] + ba1;
                float vb0 = acc2[i][j][half * 2 + 0] + bb0;
                float vb1 = acc2[i][j][half * 2 + 1] + bb1;
                if (out4) {
                    uint32_t sh, sl, eh, el;
                    split2(va0, va1, sh, sl);
                    split2(vb0, vb1, eh, el);
                    out4[(size_t)rr * 128 + (c >> 1)] = make_uint4(sh, sl, eh, el);
                } else {
                    *(float2*)&outFa[(size_t)rr * 256 + c] = make_float2(va0, va1);
                    *(float2*)&outFb[(size_t)rr * 256 + c] = make_float2(vb0, vb1);
                }
            }
        }
    }
}

// =============================================================================
// Single-output GEMM for MLP (product-outer mma issue, j pairs).
// =============================================================================
__global__ __launch_bounds__(256, 2) void gemmP_kernel(
    const uint2* __restrict__ a2, const uint2* __restrict__ w2,
    const float* __restrict__ bias,
    float* __restrict__ outF, uint32_t* __restrict__ outP, int ostride,
    int Kp, int Nc, int act)
{
    extern __shared__ uint32_t smu[];
    uint2* smA = (uint2*)smu;        // [2][128][20]
    uint2* smB = smA + 5120;         // [2][128][20]

    const int row0 = blockIdx.y * 128;
    const int col0 = blockIdx.x * 128;
    const int tid  = threadIdx.x;
    const int lane = tid & 31, warp = tid >> 5;
    const int wR = warp >> 1, wC = warp & 1;

    float acc[2][8][4] = {};
    const int nk = Kp / 16;

    {
#pragma unroll
        for (int it = 0; it < 4; it++) {
            int i = tid + it * 256;
            int r = i >> 3, c2 = (i & 7) * 2;
            cpa16(&smA[(size_t)r * 20 + c2], a2 + (size_t)(row0 + r) * Kp + c2);
            cpa16(&smB[(size_t)r * 20 + c2], w2 + (size_t)(col0 + r) * Kp + c2);
        }
        CP_COMMIT();
    }

    for (int kt = 0; kt < nk; kt++) {
        const int s = kt & 1;
        if (kt + 1 < nk) {
            const int sn = s ^ 1;
            const int k0 = (kt + 1) * 16;
#pragma unroll
            for (int it = 0; it < 4; it++) {
                int i = tid + it * 256;
                int r = i >> 3, c2 = (i & 7) * 2;
                cpa16(&smA[(size_t)(sn * 128 + r) * 20 + c2],
                      a2 + (size_t)(row0 + r) * Kp + k0 + c2);
                cpa16(&smB[(size_t)(sn * 128 + r) * 20 + c2],
                      w2 + (size_t)(col0 + r) * Kp + k0 + c2);
            }
            CP_COMMIT();
            CP_WAIT1();
        } else {
            CP_WAIT0();
        }
        __syncthreads();
#pragma unroll
        for (int ks = 0; ks < 2; ks++) {
            const int kk = ks * 8 + (lane & 3);
            uint32_t ah[2][4], al[2][4];
#pragma unroll
            for (int i = 0; i < 2; i++) {
                int m = s * 128 + wR * 32 + i * 16 + (lane >> 2);
                uint2 p0 = smA[(size_t)m * 20 + kk];
                uint2 p1 = smA[(size_t)(m + 8) * 20 + kk];
                uint2 p2 = smA[(size_t)m * 20 + kk + 4];
                uint2 p3 = smA[(size_t)(m + 8) * 20 + kk + 4];
                ah[i][0] = p0.x; ah[i][1] = p1.x; ah[i][2] = p2.x; ah[i][3] = p3.x;
                al[i][0] = p0.y; al[i][1] = p1.y; al[i][2] = p2.y; al[i][3] = p3.y;
            }
#pragma unroll
            for (int j2 = 0; j2 < 4; j2++) {
                uint2 b0[2], b1[2];
#pragma unroll
                for (int jj = 0; jj < 2; jj++) {
                    int n = s * 128 + wC * 64 + (j2 * 2 + jj) * 8 + (lane >> 2);
                    b0[jj] = smB[(size_t)n * 20 + kk];
                    b1[jj] = smB[(size_t)n * 20 + kk + 4];
                }
                // product-outer over a pair of j: same-acc reuse distance = 4 mma
#pragma unroll
                for (int jj = 0; jj < 2; jj++)
#pragma unroll
                    for (int i = 0; i < 2; i++)
                        mmabf(acc[i][j2 * 2 + jj], ah[i], b0[jj].x, b1[jj].x);
#pragma unroll
                for (int jj = 0; jj < 2; jj++)
#pragma unroll
                    for (int i = 0; i < 2; i++)
                        mmabf(acc[i][j2 * 2 + jj], ah[i], b0[jj].y, b1[jj].y);
#pragma unroll
                for (int jj = 0; jj < 2; jj++)
#pragma unroll
                    for (int i = 0; i < 2; i++)
                        mmabf(acc[i][j2 * 2 + jj], al[i], b0[jj].x, b1[jj].x);
            }
        }
        __syncthreads();
    }
#pragma unroll
    for (int i = 0; i < 2; i++) {
        int r = row0 + wR * 32 + i * 16 + (lane >> 2);
#pragma unroll
        for (int j = 0; j < 8; j++) {
            int c = col0 + wC * 64 + j * 8 + 2 * (lane & 3);
            float b0 = bias[c], b1 = bias[c + 1];
            float v0 = acc[i][j][0] + b0, v1 = acc[i][j][1] + b1;
            float v2 = acc[i][j][2] + b0, v3 = acc[i][j][3] + b1;
            if (act) {
                v0 = v0 / (1.0f + __expf(-v0));
                v1 = v1 / (1.0f + __expf(-v1));
                v2 = v2 / (1.0f + __expf(-v2));
                v3 = v3 / (1.0f + __expf(-v3));
            }
            if (outP) {
                uint32_t hh, ll;
                size_t o0 = ((size_t)r * (Nc >> 1) + (c >> 1)) * ostride;
                split2(v0, v1, hh, ll); *(uint2*)&outP[o0] = make_uint2(hh, ll);
                size_t o1 = ((size_t)(r + 8) * (Nc >> 1) + (c >> 1)) * ostride;
                split2(v2, v3, hh, ll); *(uint2*)&outP[o1] = make_uint2(hh, ll);
            } else {
                *(float2*)&outF[(size_t)r * Nc + c]       = make_float2(v0, v1);
                *(float2*)&outF[(size_t)(r + 8) * Nc + c] = make_float2(v2, v3);
            }
        }
    }
}

// =============================================================================
// Logits: dual bf16x3 NT GEMM (product-outer, S/E interleaved).
// =============================================================================
__global__ __launch_bounds__(256, 2) void logitsP_kernel(
    const float* __restrict__ pi_star, const float* __restrict__ gamma_p)
{
    extern __shared__ uint32_t smu[];
    uint4* smQ = (uint4*)smu;        // [2][128][12]
    uint4* smK = smQ + 3072;         // [2][64][12]

    const int b  = blockIdx.z;
    const int n0 = blockIdx.y * 128;
    const int m0 = blockIdx.x * 64;
    const int tid = threadIdx.x;
    const int lane = tid & 31, warp = tid >> 5;
    const int wR = warp >> 1, wC = warp & 1;

    const uint4* q4 = g_q4 + (size_t)(b * Nn + n0) * 128;
    const uint4* k4 = g_k4 + (size_t)(b * Mm + m0) * 128;

    float accS[2][4][4] = {}, accE[2][4][4] = {};
    const int nk = 16;

    {
#pragma unroll
        for (int it = 0; it < 4; it++) {
            int i = tid + it * 256;
            int r = i >> 3, kp = i & 7;
            cpa16(&smQ[(size_t)r * 12 + kp], q4 + (size_t)r * 128 + kp);
        }
#pragma unroll
        for (int it = 0; it < 2; it++) {
            int i = tid + it * 256;
            int r = i >> 3, kp = i & 7;
            cpa16(&smK[(size_t)r * 12 + kp], k4 + (size_t)r * 128 + kp);
        }
        CP_COMMIT();
    }

    for (int kt = 0; kt < nk; kt++) {
        const int s = kt & 1;
        if (kt + 1 < nk) {
            const int sn = s ^ 1;
            const int k0 = (kt + 1) * 8;
#pragma unroll
            for (int it = 0; it < 4; it++) {
                int i = tid + it * 256;
                int r = i >> 3, kp = i & 7;
                cpa16(&smQ[(size_t)(sn * 128 + r) * 12 + kp], q4 + (size_t)r * 128 + k0 + kp);
            }
#pragma unroll
            for (int it = 0; it < 2; it++) {
                int i = tid + it * 256;
                int r = i >> 3, kp = i & 7;
                cpa16(&smK[(size_t)(sn * 64 + r) * 12 + kp], k4 + (size_t)r * 128 + k0 + kp);
            }
            CP_COMMIT();
            CP_WAIT1();
        } else {
            CP_WAIT0();
        }
        __syncthreads();

        const int kk = lane & 3;
        uint32_t ash[2][4], asl[2][4], aeh[2][4], ael[2][4];
#pragma unroll
        for (int i = 0; i < 2; i++) {
            int m = s * 128 + wR * 32 + i * 16 + (lane >> 2);
            uint4 p0 = smQ[(size_t)m * 12 + kk];
            uint4 p1 = smQ[(size_t)(m + 8) * 12 + kk];
            uint4 p2 = smQ[(size_t)m * 12 + kk + 4];
            uint4 p3 = smQ[(size_t)(m + 8) * 12 + kk + 4];
            ash[i][0] = p0.x; ash[i][1] = p1.x; ash[i][2] = p2.x; ash[i][3] = p3.x;
            asl[i][0] = p0.y; asl[i][1] = p1.y; asl[i][2] = p2.y; asl[i][3] = p3.y;
            aeh[i][0] = p0.z; aeh[i][1] = p1.z; aeh[i][2] = p2.z; aeh[i][3] = p3.z;
            ael[i][0] = p0.w; ael[i][1] = p1.w; ael[i][2] = p2.w; ael[i][3] = p3.w;
        }
#pragma unroll
        for (int j = 0; j < 4; j++) {
            int n = s * 64 + wC * 32 + j * 8 + (lane >> 2);
            uint4 k0v = smK[(size_t)n * 12 + kk];
            uint4 k1v = smK[(size_t)n * 12 + kk + 4];
            // product-outer, S/E interleaved: same-acc reuse distance = 4 mma
#pragma unroll
            for (int i = 0; i < 2; i++) {
                mmabf(accS[i][j], ash[i], k0v.x, k1v.x);
                mmabf(accE[i][j], aeh[i], k0v.z, k1v.z);
            }
#pragma unroll
            for (int i = 0; i < 2; i++) {
                mmabf(accS[i][j], ash[i], k0v.y, k1v.y);
                mmabf(accE[i][j], aeh[i], k0v.w, k1v.w);
            }
#pragma unroll
            for (int i = 0; i < 2; i++) {
                mmabf(accS[i][j], asl[i], k0v.x, k1v.x);
                mmabf(accE[i][j], ael[i], k0v.z, k1v.z);
            }
        }
        __syncthreads();
    }

    const float g = gamma_p[0];
    float sumd = 0.0f;
#pragma unroll
    for (int i = 0; i < 2; i++) {
        int n_lo = n0 + wR * 32 + i * 16 + (lane >> 2);
        float q2a = g_q2[b * Nn + n_lo];
        float q2b = g_q2[b * Nn + n_lo + 8];
#pragma unroll
        for (int j = 0; j < 4; j++) {
            int m = m0 + wC * 32 + j * 8 + 2 * (lane & 3);
            float k2a = g_k2[b * Mm + m], k2b = g_k2[b * Mm + m + 1];
            size_t base0 = ((size_t)b * Nn + n_lo) * Mm + m;
            float2 piv = *(const float2*)&pi_star[base0];
            float d0 = sqrtf(fmaxf(q2a + k2a - 2.0f * accE[i][j][0], 1e-12f));
            float d1 = sqrtf(fmaxf(q2a + k2b - 2.0f * accE[i][j][1], 1e-12f));
            sumd += d0 + d1;
            *(float2*)&g_D[base0] = make_float2(d0, d1);
            float L0 = accS[i][j][0] * 0.0625f + g * __logf(fmaxf(piv.x, 1e-9f));
            float L1 = accS[i][j][1] * 0.0625f + g * __logf(fmaxf(piv.y, 1e-9f));
            *(float2*)&g_L[base0] = make_float2(L0, L1);
            size_t base1 = ((size_t)b * Nn + n_lo + 8) * Mm + m;
            piv = *(const float2*)&pi_star[base1];
            float d2v = sqrtf(fmaxf(q2b + k2a - 2.0f * accE[i][j][2], 1e-12f));
            float d3v = sqrtf(fmaxf(q2b + k2b - 2.0f * accE[i][j][3], 1e-12f));
            sumd += d2v + d3v;
            *(float2*)&g_D[base1] = make_float2(d2v, d3v);
            float L2 = accS[i][j][2] * 0.0625f + g * __logf(fmaxf(piv.x, 1e-9f));
            float L3 = accS[i][j][3] * 0.0625f + g * __logf(fmaxf(piv.y, 1e-9f));
            *(float2*)&g_L[base1] = make_float2(L2, L3);
        }
    }
    float* red = (float*)smu;
    red[tid] = sumd;
    __syncthreads();
    for (int sred = 128; sred > 0; sred >>= 1) {
        if (tid < sred) red[tid] += red[tid + sred];
        __syncthreads();
    }
    if (tid == 0) atomicAdd(&g_dsum[b], red[0]);
}

// =============================================================================
// Ctx: dual bf16x3 NN GEMM (product-outer, S/E interleaved).
// =============================================================================
__global__ __launch_bounds__(256, 2) void ctxP_kernel()
{
    extern __shared__ uint32_t smu[];
    uint2* smP = (uint2*)smu;                // [2][128][20]
    uint4* smV = (uint4*)(smu + 10240);      // [2][64][20]

    const int b  = blockIdx.z;
    const int n0 = blockIdx.y * 128;
    const int h0 = blockIdx.x * 64;
    const int tid = threadIdx.x;
    const int lane = tid & 31, warp = tid >> 5;
    const int wR = warp >> 1, wC = warp & 1;

    const uint2* p2 = g_p2 + (size_t)(b * Nn + n0) * 1024;
    const uint4* v4 = g_vT4 + ((size_t)b * Hh + h0) * 1024;

    float accS[2][4][4] = {}, accE[2][4][4] = {};
    const int nk = 64;

    {
#pragma unroll
        for (int it = 0; it < 4; it++) {
            int i = tid + it * 256;
            int r = i >> 3, c2 = (i & 7) * 2;
            cpa16(&smP[(size_t)r * 20 + c2], p2 + (size_t)r * 1024 + c2);
            int rv = i >> 4, kp = i & 15;
            cpa16(&smV[(size_t)rv * 20 + kp], v4 + (size_t)rv * 1024 + kp);
        }
        CP_COMMIT();
    }

    for (int kt = 0; kt < nk; kt++) {
        const int s = kt & 1;
        if (kt + 1 < nk) {
            const int sn = s ^ 1;
            const int mp0 = (kt + 1) * 16;
#pragma unroll
            for (int it = 0; it < 4; it++) {
                int i = tid + it * 256;
                int r = i >> 3, c2 = (i & 7) * 2;
                cpa16(&smP[(size_t)(sn * 128 + r) * 20 + c2],
                      p2 + (size_t)r * 1024 + mp0 + c2);
                int rv = i >> 4, kp = i & 15;
                cpa16(&smV[(size_t)(sn * 64 + rv) * 20 + kp],
                      v4 + (size_t)rv * 1024 + mp0 + kp);
            }
            CP_COMMIT();
            CP_WAIT1();
        } else {
            CP_WAIT0();
        }
        __syncthreads();
#pragma unroll
        for (int ks = 0; ks < 2; ks++) {
            const int kk = ks * 8 + (lane & 3);
            uint32_t ph[2][4], pl[2][4];
#pragma unroll
            for (int i = 0; i < 2; i++) {
                int m = s * 128 + wR * 32 + i * 16 + (lane >> 2);
                uint2 p0 = smP[(size_t)m * 20 + kk];
                uint2 p1 = smP[(size_t)(m + 8) * 20 + kk];
                uint2 p2v = smP[(size_t)m * 20 + kk + 4];
                uint2 p3 = smP[(size_t)(m + 8) * 20 + kk + 4];
                ph[i][0] = p0.x; ph[i][1] = p1.x; ph[i][2] = p2v.x; ph[i][3] = p3.x;
                pl[i][0] = p0.y; pl[i][1] = p1.y; pl[i][2] = p2v.y; pl[i][3] = p3.y;
            }
#pragma unroll
            for (int j = 0; j < 4; j++) {
                int n = s * 64 + wC * 32 + j * 8 + (lane >> 2);
                uint4 v0 = smV[(size_t)n * 20 + kk];
                uint4 v1 = smV[(size_t)n * 20 + kk + 4];
#pragma unroll
                for (int i = 0; i < 2; i++) {
                    mmabf(accS[i][j], ph[i], v0.x, v1.x);
                    mmabf(accE[i][j], ph[i], v0.z, v1.z);
                }
#pragma unroll
                for (int i = 0; i < 2; i++) {
                    mmabf(accS[i][j], ph[i], v0.y, v1.y);
                    mmabf(accE[i][j], ph[i], v0.w, v1.w);
                }
#pragma unroll
                for (int i = 0; i < 2; i++) {
                    mmabf(accS[i][j], pl[i], v0.x, v1.x);
                    mmabf(accE[i][j], pl[i], v0.z, v1.z);
                }
            }
        }
        __syncthreads();
    }
#pragma unroll
    for (int i = 0; i < 2; i++) {
        int n_lo = n0 + wR * 32 + i * 16 + (lane >> 2);
#pragma unroll
        for (int j = 0; j < 4; j++) {
            int h = h0 + wC * 32 + j * 8 + 2 * (lane & 3);
#pragma unroll
            for (int half = 0; half < 2; half++) {
                int n = n_lo + half * 8;
                float cs0 = accS[i][j][half * 2 + 0], cs1 = accS[i][j][half * 2 + 1];
                float ce0 = accE[i][j][half * 2 + 0], ce1 = accE[i][j][half * 2 + 1];
                size_t fb = ((size_t)b * Nn + n) * 512;
                uint32_t hh, ll;
                split2(cs0, cs1, hh, ll);             g_f2[fb + (h >> 1)]       = make_uint2(hh, ll);
                split2(ce0, ce1, hh, ll);             g_f2[fb + 128 + (h >> 1)] = make_uint2(hh, ll);
                split2(cs0 - ce0, cs1 - ce1, hh, ll); g_f2[fb + 256 + (h >> 1)] = make_uint2(hh, ll);
                split2(cs0 * ce0, cs1 * ce1, hh, ll); g_f2[fb + 384 + (h >> 1)] = make_uint2(hh, ll);
            }
        }
    }
}

// ---------------- softmax ----------------
__global__ void softmax_kernel(const float* __restrict__ ew_p) {
    const int row = blockIdx.x;
    const int b   = row / Nn;
    const float invsc = ew_p[0] / g_scale[b];
    const size_t base = (size_t)row * Mm;
    const int c0 = threadIdx.x * 8;
    float v[8];
    float mx = -1e30f;
#pragma unroll
    for (int q = 0; q < 2; q++) {
        float4 lv = *(const float4*)&g_L[base + c0 + q * 4];
        float4 dv = *(const float4*)&g_D[base + c0 + q * 4];
        v[q*4+0] = lv.x - dv.x * invsc; v[q*4+1] = lv.y - dv.y * invsc;
        v[q*4+2] = lv.z - dv.z * invsc; v[q*4+3] = lv.w - dv.w * invsc;
    }
#pragma unroll
    for (int t = 0; t < 8; t++) mx = fmaxf(mx, v[t]);
    __shared__ float sh[8];
    __shared__ float bc;
    int lane = threadIdx.x & 31, wid = threadIdx.x >> 5;
    float wm = warpRedMax(mx);
    if (lane == 0) sh[wid] = wm;
    __syncthreads();
    if (wid == 0) {
        float t = (lane < 8) ? sh[lane] : -1e30f;
        t = warpRedMax(t);
        if (lane == 0) bc = t;
    }
    __syncthreads();
    mx = bc;
    float sum = 0.0f;
#pragma unroll
    for (int t = 0; t < 8; t++) {
        v[t] = __expf(v[t] - mx);
        sum += v[t];
    }
    __syncthreads();
    float ws = warpRedSum(sum);
    if (lane == 0) sh[wid] = ws;
    __syncthreads();
    if (wid == 0) {
        float t = (lane < 8) ? sh[lane] : 0.0f;
        t = warpRedSum(t);
        if (lane == 0) bc = t;
    }
    __syncthreads();
    const float inv = 1.0f / bc;
    const size_t pbase = (size_t)row * 1024 + threadIdx.x * 4;
#pragma unroll
    for (int p = 0; p < 4; p++) {
        uint32_t hh, ll;
        split2(v[2 * p] * inv, v[2 * p + 1] * inv, hh, ll);
        g_p2[pbase + p] = make_uint2(hh, ll);
    }
}

// ---------------- launch ----------------
extern "C" void kernel_launch(void* const* d_in, const int* in_sizes, int n_in,
                              void* d_out, int out_size) {
    const float* q_fp  = (const float*)d_in[0];
    const float* v_ret = (const float*)d_in[1];
    const float* pi    = (const float*)d_in[2];
    const float* Wqs = (const float*)d_in[3];  const float* bqs = (const float*)d_in[4];
    const float* Wks = (const float*)d_in[5];  const float* bks = (const float*)d_in[6];
    const float* Wvs = (const float*)d_in[7];  const float* bvs = (const float*)d_in[8];
    const float* Wqe = (const float*)d_in[9];  const float* bqe = (const float*)d_in[10];
    const float* Wke = (const float*)d_in[11]; const float* bke = (const float*)d_in[12];
    const float* Wve = (const float*)d_in[13]; const float* bve = (const float*)d_in[14];
    const float* W1  = (const float*)d_in[15]; const float* b1  = (const float*)d_in[16];
    const float* W2  = (const float*)d_in[17]; const float* b2  = (const float*)d_in[18];
    const float* gamma = (const float*)d_in[19];
    const float* ew    = (const float*)d_in[20];
    float* out = (float*)d_out;

    uint2 *qf2, *vr2, *w2, *f2, *h2;
    uint4 *q4, *k4, *vT4;
    float *vs_p, *ve_p, *q2_p, *k2_p;
    cudaGetSymbolAddress((void**)&qf2, g_qf2);
    cudaGetSymbolAddress((void**)&vr2, g_vr2);
    cudaGetSymbolAddress((void**)&w2, g_w2);
    cudaGetSymbolAddress((void**)&q4, g_q4);
    cudaGetSymbolAddress((void**)&k4, g_k4);
    cudaGetSymbolAddress((void**)&vT4, g_vT4);
    cudaGetSymbolAddress((void**)&f2, g_f2);
    cudaGetSymbolAddress((void**)&h2, g_h2);
    cudaGetSymbolAddress((void**)&vs_p, g_vs);
    cudaGetSymbolAddress((void**)&ve_p, g_ve);
    cudaGetSymbolAddress((void**)&q2_p, g_q2);
    cudaGetSymbolAddress((void**)&k2_p, g_k2);

    const int G2_SMEM    = 6144 * 8;
    const int GEMM_SMEM  = 81920;
    const int LOGIT_SMEM = 73728;
    const int CTX_SMEM   = 81920;
    cudaFuncSetAttribute(gemm2_kernel,   cudaFuncAttributeMaxDynamicSharedMemorySize, G2_SMEM);
    cudaFuncSetAttribute(gemmP_kernel,   cudaFuncAttributeMaxDynamicSharedMemorySize, GEMM_SMEM);
    cudaFuncSetAttribute(logitsP_kernel, cudaFuncAttributeMaxDynamicSharedMemorySize, LOGIT_SMEM);
    cudaFuncSetAttribute(ctxP_kernel,    cudaFuncAttributeMaxDynamicSharedMemorySize, CTX_SMEM);

    uint2* wo[8] = {w2, w2+65536, w2+131072, w2+196608, w2+262144, w2+327680,
                    w2+393216, w2+524288};

    dim3 gp(4, (Bb * Nn) / 128);

    // launch order: OUR idx4 = gemm2_q (ncu profiles global launch #5 = our #4)
    pack_rows_kernel<<<(Bb*Nn*DIN/2 + 255)/256, 256>>>(q_fp,  qf2, Bb*Nn*DIN/2);     // 0
    pack_rows_kernel<<<(Bb*Mm*DIN/2 + 255)/256, 256>>>(v_ret, vr2, Bb*Mm*DIN/2);     // 1
    pack_weight_kernel<<<(256*256 + 255)/256, 256>>>(Wqs, wo[0], 256, 256);          // 2
    pack_weight_kernel<<<(256*256 + 255)/256, 256>>>(Wqe, wo[3], 256, 256);          // 3
    gemm2_kernel<<<gp, 256, G2_SMEM>>>(qf2, wo[0], wo[3], bqs, bqe,
                                       q4, nullptr, nullptr, 256);                   // 4 <- profiled
    pack_weight_kernel<<<(256*256 + 255)/256, 256>>>(Wks, wo[1], 256, 256);
    pack_weight_kernel<<<(256*256 + 255)/256, 256>>>(Wke, wo[4], 256, 256);
    gemm2_kernel<<<gp, 256, G2_SMEM>>>(vr2, wo[1], wo[4], bks, bke,
                                       k4, nullptr, nullptr, 256);
    pack_weight_kernel<<<(256*256 + 255)/256, 256>>>(Wvs, wo[2], 256, 256);
    pack_weight_kernel<<<(256*256 + 255)/256, 256>>>(Wve, wo[5], 256, 256);
    gemm2_kernel<<<gp, 256, G2_SMEM>>>(vr2, wo[2], wo[5], bvs, bve,
                                       nullptr, vs_p, ve_p, 256);
    pack_weight_kernel<<<(512*256 + 255)/256, 256>>>(W1, wo[6], 512, 256);
    pack_weight_kernel<<<(128*256 + 255)/256, 256>>>(W2, wo[7], 128, 256);

    dim3 gt(Mm / 64, Hh / 32, Bb);
    transpose_pack2_kernel<<<gt, 256>>>(vs_p, ve_p, vT4);

    rowsumsq_kernel<<<Bb * Nn, 128>>>(q4, q2_p);
    rowsumsq_kernel<<<Bb * Mm, 128>>>(k4, k2_p);

    zero_dsum_kernel<<<1, 32>>>();
    dim3 gl(Mm / 64, Nn / 128, Bb);
    logitsP_kernel<<<gl, 256, LOGIT_SMEM>>>(pi, gamma);
    finalize_scale_kernel<<<1, 32>>>();

    softmax_kernel<<<Bb * Nn, 256>>>(ew);

    dim3 gc(Hh / 64, Nn / 128, Bb);
    ctxP_kernel<<<gc, 256, CTX_SMEM>>>();

    dim3 gm(2, (Bb * Nn) / 128);
    gemmP_kernel<<<gm, 256, GEMM_SMEM>>>(f2, wo[6], b1, nullptr, (uint32_t*)h2, 2, 512, 256, 1);
    gemmP_kernel<<<gm, 256, GEMM_SMEM>>>(h2, wo[7], b2, out, nullptr, 0, 128, 256, 0);
}

// round 10
// speedup vs baseline: 1.2515x; 1.2515x over previous
#include <cuda_runtime.h>
#include <cuda_fp16.h>
#include <cstdint>

#define Bb 8
#define Nn 2048
#define Mm 2048
#define DIN 512
#define Hh 256

// ---------------- scratch (device globals; no allocs allowed) ----------------
__device__ uint2 g_qf2[(size_t)Bb*Nn*(DIN/2)];            // input rows: fp16 {H,L}
__device__ uint2 g_vr2[(size_t)Bb*Mm*(DIN/2)];
__device__ uint32_t g_w1p[6*65536 + 131072 + 32768];      // weights: fp16 hi only, n-major [n][kp]
__device__ uint4 g_q4[(size_t)Bb*Nn*128];                 // {qsH,qsL,qeH,qeL}
__device__ uint2 g_kp2[(size_t)Bb*Mm*128];                // {ksH,keH}
__device__ float g_vs[(size_t)Bb*Mm*Hh], g_ve[(size_t)Bb*Mm*Hh];
__device__ uint2 g_vT2[(size_t)Bb*Hh*1024];               // {vsH,veH} [b][h][mp]
__device__ float g_L[(size_t)Bb*Nn*Mm];
__device__ float g_D[(size_t)Bb*Nn*Mm];
__device__ uint2 g_p2[(size_t)Bb*Nn*1024];                // probs {H,L}
__device__ uint2 g_f2[(size_t)Bb*Nn*512];                 // fused {H,L}
__device__ uint2 g_h2[(size_t)Bb*Nn*128];                 // hidden {H,L}
__device__ float g_q2[Bb*Nn], g_k2[Bb*Mm], g_dsum[Bb], g_scale[Bb];

// ---------------- helpers ----------------
__device__ __forceinline__ void splitH2(float f0, float f1, uint32_t& H, uint32_t& L) {
    __half h0 = __float2half(f0), h1 = __float2half(f1);
    __half l0 = __float2half(f0 - __half2float(h0));
    __half l1 = __float2half(f1 - __half2float(h1));
    H = (uint32_t)__half_as_ushort(h0) | ((uint32_t)__half_as_ushort(h1) << 16);
    L = (uint32_t)__half_as_ushort(l0) | ((uint32_t)__half_as_ushort(l1) << 16);
}
__device__ __forceinline__ uint32_t cvtH2(float f0, float f1) {
    __half h0 = __float2half(f0), h1 = __float2half(f1);
    return (uint32_t)__half_as_ushort(h0) | ((uint32_t)__half_as_ushort(h1) << 16);
}
__device__ __forceinline__ float hlo(uint32_t u) {
    return __half2float(__ushort_as_half((unsigned short)(u & 0xffff)));
}
__device__ __forceinline__ float hhi(uint32_t u) {
    return __half2float(__ushort_as_half((unsigned short)(u >> 16)));
}
__device__ __forceinline__ void mmah(float* d, const uint32_t* a, uint32_t b0, uint32_t b1) {
    asm volatile(
        "mma.sync.aligned.m16n8k16.row.col.f32.f16.f16.f32 "
        "{%0,%1,%2,%3}, {%4,%5,%6,%7}, {%8,%9}, {%0,%1,%2,%3};\n"
        : "+f"(d[0]), "+f"(d[1]), "+f"(d[2]), "+f"(d[3])
        : "r"(a[0]), "r"(a[1]), "r"(a[2]), "r"(a[3]), "r"(b0), "r"(b1));
}
__device__ __forceinline__ void cpa16(void* smem, const void* gmem) {
    uint32_t s = (uint32_t)__cvta_generic_to_shared(smem);
    asm volatile("cp.async.cg.shared.global [%0], [%1], 16;\n" :: "r"(s), "l"(gmem));
}
#define CP_COMMIT() asm volatile("cp.async.commit_group;\n")
#define CP_WAIT1()  asm volatile("cp.async.wait_group 1;\n")
#define CP_WAIT0()  asm volatile("cp.async.wait_group 0;\n")

__device__ __forceinline__ float warpRedSum(float v) {
#pragma unroll
    for (int o = 16; o > 0; o >>= 1) v += __shfl_xor_sync(0xffffffffu, v, o);
    return v;
}
__device__ __forceinline__ float warpRedMax(float v) {
#pragma unroll
    for (int o = 16; o > 0; o >>= 1) v = fmaxf(v, __shfl_xor_sync(0xffffffffu, v, o));
    return v;
}

// ---------------- prep kernels ----------------
__global__ void pack_rows_kernel(const float* __restrict__ src,
                                 uint2* __restrict__ dst, int npairs) {
    int i = blockIdx.x * 256 + threadIdx.x;
    if (i >= npairs) return;
    float2 f = ((const float2*)src)[i];
    uint32_t h, l; splitH2(f.x, f.y, h, l);
    dst[i] = make_uint2(h, l);
}
// weights -> n-major hi-only u32 [n][kp]
__global__ void pack_weight_kernel(const float* __restrict__ W,
                                   uint32_t* __restrict__ dst, int Kp, int Nc) {
    int i = blockIdx.x * 256 + threadIdx.x;
    if (i >= Kp * Nc) return;
    int n = i / Kp, kp = i - n * Kp;
    dst[i] = cvtH2(W[(size_t)(2 * kp) * Nc + n], W[(size_t)(2 * kp + 1) * Nc + n]);
}
// Vs,Ve [b][m][h] fp32 -> uint2{vsH,veH} [b][h][mp]
__global__ void transpose_pack2_kernel(const float* __restrict__ Vs,
                                       const float* __restrict__ Ve,
                                       uint2* __restrict__ T2) {
    __shared__ float ts[64][33], te[64][33];
    const int b = blockIdx.z, m0 = blockIdx.x * 64, h0 = blockIdx.y * 32;
    const int tid = threadIdx.x;
#pragma unroll
    for (int it = 0; it < 2; it++) {
        int i = tid + it * 256;
        int m = i >> 3, h4 = (i & 7) * 4;
        size_t off = ((size_t)b * Mm + m0 + m) * Hh + h0 + h4;
        float4 v = *(const float4*)&Vs[off];
        ts[m][h4 + 0] = v.x; ts[m][h4 + 1] = v.y; ts[m][h4 + 2] = v.z; ts[m][h4 + 3] = v.w;
        v = *(const float4*)&Ve[off];
        te[m][h4 + 0] = v.x; te[m][h4 + 1] = v.y; te[m][h4 + 2] = v.z; te[m][h4 + 3] = v.w;
    }
    __syncthreads();
#pragma unroll
    for (int u = 0; u < 4; u++) {
        int i = tid + u * 256;
        int h = i >> 5, mp = i & 31;
        T2[((size_t)b * Hh + h0 + h) * 1024 + (m0 >> 1) + mp] =
            make_uint2(cvtH2(ts[2 * mp][h], ts[2 * mp + 1][h]),
                       cvtH2(te[2 * mp][h], te[2 * mp + 1][h]));
    }
}
// q2: full reconstructed q_e (planes z,w of q4)
__global__ void rowsumsq_q_kernel(const uint4* __restrict__ P4, float* __restrict__ dst) {
    const int row = blockIdx.x, tid = threadIdx.x;
    uint4 q = P4[(size_t)row * 128 + tid];
    float v0 = hlo(q.z) + hlo(q.w), v1 = hhi(q.z) + hhi(q.w);
    float s = v0 * v0 + v1 * v1;
    __shared__ float sh[4];
    int lane = tid & 31, wid = tid >> 5;
    float w = warpRedSum(s);
    if (lane == 0) sh[wid] = w;
    __syncthreads();
    if (wid == 0) {
        float t = (lane < 4) ? sh[lane] : 0.0f;
        t = warpRedSum(t);
        if (lane == 0) dst[row] = t;
    }
}
// k2: hi plane of k_e only (consistent with dot = q . kH)
__global__ void rowsumsq_k_kernel(const uint2* __restrict__ P2, float* __restrict__ dst) {
    const int row = blockIdx.x, tid = threadIdx.x;
    uint2 q = P2[(size_t)row * 128 + tid];
    float v0 = hlo(q.y), v1 = hhi(q.y);
    float s = v0 * v0 + v1 * v1;
    __shared__ float sh[4];
    int lane = tid & 31, wid = tid >> 5;
    float w = warpRedSum(s);
    if (lane == 0) sh[wid] = w;
    __syncthreads();
    if (wid == 0) {
        float t = (lane < 4) ? sh[lane] : 0.0f;
        t = warpRedSum(t);
        if (lane == 0) dst[row] = t;
    }
}
__global__ void zero_dsum_kernel() { if (threadIdx.x < Bb) g_dsum[threadIdx.x] = 0.0f; }
__global__ void finalize_scale_kernel() {
    if (threadIdx.x < Bb)
        g_scale[threadIdx.x] = fmaxf(g_dsum[threadIdx.x] * (1.0f / ((float)Nn * (float)Mm)), 1e-4f);
}

// =============================================================================
// Dual-output projection GEMM (fp16 2-product; B hi-only).
// Block 128(row) x 64(col), BK=16 (8 kp/stage), 2-stage cp.async.
// =============================================================================
__global__ __launch_bounds__(256, 2) void gemm2_kernel(
    const uint2* __restrict__ a2,
    const uint32_t* __restrict__ wa, const uint32_t* __restrict__ wb,
    const float* __restrict__ biasA, const float* __restrict__ biasB,
    uint4* __restrict__ outQ, uint2* __restrict__ outK,
    float* __restrict__ outFa, float* __restrict__ outFb,
    int Kp)
{
    extern __shared__ uint32_t smu[];
    uint2*     smA  = (uint2*)smu;       // [2][128][12] uint2 (6144 u32)
    uint32_t*  smB1 = smu + 6144;        // [2][64][12] u32
    uint32_t*  smB2 = smu + 7680;        // [2][64][12] u32

    const int row0 = blockIdx.y * 128;
    const int col0 = blockIdx.x * 64;
    const int tid  = threadIdx.x;
    const int lane = tid & 31, warp = tid >> 5;
    const int wR = warp >> 1, wC = warp & 1;

    float acc1[2][4][4] = {}, acc2[2][4][4] = {};
    const int nk = Kp / 8;

    const int bt = tid & 127;
    const int br = bt >> 1, bc4 = (bt & 1) * 4;
    uint32_t* smBsel = (tid < 128) ? smB1 : smB2;
    const uint32_t* wsel = (tid < 128) ? wa : wb;

    {   // prologue
#pragma unroll
        for (int it = 0; it < 2; it++) {
            int i = tid + it * 256;
            int r = i >> 2, c2 = (i & 3) * 2;
            cpa16(&smA[(size_t)r * 12 + c2], a2 + (size_t)(row0 + r) * Kp + c2);
        }
        cpa16(&smBsel[(size_t)br * 12 + bc4], wsel + (size_t)(col0 + br) * Kp + bc4);
        CP_COMMIT();
    }

    for (int kt = 0; kt < nk; kt++) {
        const int s = kt & 1;
        if (kt + 1 < nk) {
            const int sn = s ^ 1;
            const int k0 = (kt + 1) * 8;
#pragma unroll
            for (int it = 0; it < 2; it++) {
                int i = tid + it * 256;
                int r = i >> 2, c2 = (i & 3) * 2;
                cpa16(&smA[(size_t)(sn * 128 + r) * 12 + c2],
                      a2 + (size_t)(row0 + r) * Kp + k0 + c2);
            }
            cpa16(&smBsel[(size_t)(sn * 64 + br) * 12 + bc4],
                  wsel + (size_t)(col0 + br) * Kp + k0 + bc4);
            CP_COMMIT();
            CP_WAIT1();
        } else {
            CP_WAIT0();
        }
        __syncthreads();

        const int kk = lane & 3;
        uint32_t ah[2][4], al[2][4];
#pragma unroll
        for (int i = 0; i < 2; i++) {
            int m = s * 128 + wR * 32 + i * 16 + (lane >> 2);
            uint2 p0 = smA[(size_t)m * 12 + kk];
            uint2 p1 = smA[(size_t)(m + 8) * 12 + kk];
            uint2 p2 = smA[(size_t)m * 12 + kk + 4];
            uint2 p3 = smA[(size_t)(m + 8) * 12 + kk + 4];
            ah[i][0] = p0.x; ah[i][1] = p1.x; ah[i][2] = p2.x; ah[i][3] = p3.x;
            al[i][0] = p0.y; al[i][1] = p1.y; al[i][2] = p2.y; al[i][3] = p3.y;
        }
#pragma unroll
        for (int j = 0; j < 4; j++) {
            int n = s * 64 + wC * 32 + j * 8 + (lane >> 2);
            uint32_t b10 = smB1[(size_t)n * 12 + kk], b11 = smB1[(size_t)n * 12 + kk + 4];
            uint32_t b20 = smB2[(size_t)n * 12 + kk], b21 = smB2[(size_t)n * 12 + kk + 4];
#pragma unroll
            for (int i = 0; i < 2; i++) {
                mmah(acc1[i][j], ah[i], b10, b11);
                mmah(acc2[i][j], ah[i], b20, b21);
            }
#pragma unroll
            for (int i = 0; i < 2; i++) {
                mmah(acc1[i][j], al[i], b10, b11);
                mmah(acc2[i][j], al[i], b20, b21);
            }
        }
        __syncthreads();
    }

#pragma unroll
    for (int i = 0; i < 2; i++) {
        int r = row0 + wR * 32 + i * 16 + (lane >> 2);
#pragma unroll
        for (int j = 0; j < 4; j++) {
            int c = col0 + wC * 32 + j * 8 + 2 * (lane & 3);
            float ba0 = biasA[c], ba1 = biasA[c + 1];
            float bb0 = biasB[c], bb1 = biasB[c + 1];
#pragma unroll
            for (int half = 0; half < 2; half++) {
                int rr = r + half * 8;
                float va0 = acc1[i][j][half * 2 + 0] + ba0;
                float va1 = acc1[i][j][half * 2 + 1] + ba1;
                float vb0 = acc2[i][j][half * 2 + 0] + bb0;
                float vb1 = acc2[i][j][half * 2 + 1] + bb1;
                if (outQ) {
                    uint32_t sh, sl, eh, el;
                    splitH2(va0, va1, sh, sl);
                    splitH2(vb0, vb1, eh, el);
                    outQ[(size_t)rr * 128 + (c >> 1)] = make_uint4(sh, sl, eh, el);
                } else if (outK) {
                    outK[(size_t)rr * 128 + (c >> 1)] =
                        make_uint2(cvtH2(va0, va1), cvtH2(vb0, vb1));
                } else {
                    *(float2*)&outFa[(size_t)rr * 256 + c] = make_float2(va0, va1);
                    *(float2*)&outFb[(size_t)rr * 256 + c] = make_float2(vb0, vb1);
                }
            }
        }
    }
}

// =============================================================================
// Single-output GEMM for MLP (fp16 2-product; B hi-only).
// Tile 128x128, BK=32 (16 kp), 2-stage cp.async.
// =============================================================================
__global__ __launch_bounds__(256, 2) void gemmP_kernel(
    const uint2* __restrict__ a2, const uint32_t* __restrict__ w1p,
    const float* __restrict__ bias,
    float* __restrict__ outF, uint32_t* __restrict__ outP, int ostride,
    int Kp, int Nc, int act)
{
    extern __shared__ uint32_t smu[];
    uint2*    smA = (uint2*)smu;       // [2][128][20] uint2 (10240 u32)
    uint32_t* smB = smu + 10240;       // [2][128][20] u32

    const int row0 = blockIdx.y * 128;
    const int col0 = blockIdx.x * 128;
    const int tid  = threadIdx.x;
    const int lane = tid & 31, warp = tid >> 5;
    const int wR = warp >> 1, wC = warp & 1;

    float acc[2][8][4] = {};
    const int nk = Kp / 16;

    {
#pragma unroll
        for (int it = 0; it < 4; it++) {
            int i = tid + it * 256;
            int r = i >> 3, c2 = (i & 7) * 2;
            cpa16(&smA[(size_t)r * 20 + c2], a2 + (size_t)(row0 + r) * Kp + c2);
        }
#pragma unroll
        for (int it = 0; it < 2; it++) {
            int i = tid + it * 256;
            int r = i >> 2, c4 = (i & 3) * 4;
            cpa16(&smB[(size_t)r * 20 + c4], w1p + (size_t)(col0 + r) * Kp + c4);
        }
        CP_COMMIT();
    }

    for (int kt = 0; kt < nk; kt++) {
        const int s = kt & 1;
        if (kt + 1 < nk) {
            const int sn = s ^ 1;
            const int k0 = (kt + 1) * 16;
#pragma unroll
            for (int it = 0; it < 4; it++) {
                int i = tid + it * 256;
                int r = i >> 3, c2 = (i & 7) * 2;
                cpa16(&smA[(size_t)(sn * 128 + r) * 20 + c2],
                      a2 + (size_t)(row0 + r) * Kp + k0 + c2);
            }
#pragma unroll
            for (int it = 0; it < 2; it++) {
                int i = tid + it * 256;
                int r = i >> 2, c4 = (i & 3) * 4;
                cpa16(&smB[(size_t)(sn * 128 + r) * 20 + c4],
                      w1p + (size_t)(col0 + r) * Kp + k0 + c4);
            }
            CP_COMMIT();
            CP_WAIT1();
        } else {
            CP_WAIT0();
        }
        __syncthreads();
#pragma unroll
        for (int ks = 0; ks < 2; ks++) {
            const int kk = ks * 8 + (lane & 3);
            uint32_t ah[2][4], al[2][4];
#pragma unroll
            for (int i = 0; i < 2; i++) {
                int m = s * 128 + wR * 32 + i * 16 + (lane >> 2);
                uint2 p0 = smA[(size_t)m * 20 + kk];
                uint2 p1 = smA[(size_t)(m + 8) * 20 + kk];
                uint2 p2 = smA[(size_t)m * 20 + kk + 4];
                uint2 p3 = smA[(size_t)(m + 8) * 20 + kk + 4];
                ah[i][0] = p0.x; ah[i][1] = p1.x; ah[i][2] = p2.x; ah[i][3] = p3.x;
                al[i][0] = p0.y; al[i][1] = p1.y; al[i][2] = p2.y; al[i][3] = p3.y;
            }
#pragma unroll
            for (int j = 0; j < 8; j++) {
                int n = s * 128 + wC * 64 + j * 8 + (lane >> 2);
                uint32_t b0 = smB[(size_t)n * 20 + kk];
                uint32_t b1 = smB[(size_t)n * 20 + kk + 4];
#pragma unroll
                for (int i = 0; i < 2; i++) {
                    mmah(acc[i][j], ah[i], b0, b1);
                    mmah(acc[i][j], al[i], b0, b1);
                }
            }
        }
        __syncthreads();
    }
#pragma unroll
    for (int i = 0; i < 2; i++) {
        int r = row0 + wR * 32 + i * 16 + (lane >> 2);
#pragma unroll
        for (int j = 0; j < 8; j++) {
            int c = col0 + wC * 64 + j * 8 + 2 * (lane & 3);
            float b0 = bias[c], b1 = bias[c + 1];
            float v0 = acc[i][j][0] + b0, v1 = acc[i][j][1] + b1;
            float v2 = acc[i][j][2] + b0, v3 = acc[i][j][3] + b1;
            if (act) {
                v0 = v0 / (1.0f + __expf(-v0));
                v1 = v1 / (1.0f + __expf(-v1));
                v2 = v2 / (1.0f + __expf(-v2));
                v3 = v3 / (1.0f + __expf(-v3));
            }
            if (outP) {
                uint32_t hh, ll;
                size_t o0 = ((size_t)r * (Nc >> 1) + (c >> 1)) * ostride;
                splitH2(v0, v1, hh, ll); *(uint2*)&outP[o0] = make_uint2(hh, ll);
                size_t o1 = ((size_t)(r + 8) * (Nc >> 1) + (c >> 1)) * ostride;
                splitH2(v2, v3, hh, ll); *(uint2*)&outP[o1] = make_uint2(hh, ll);
            } else {
                *(float2*)&outF[(size_t)r * Nc + c]       = make_float2(v0, v1);
                *(float2*)&outF[(size_t)(r + 8) * Nc + c] = make_float2(v2, v3);
            }
        }
    }
}

// =============================================================================
// Logits: dual fp16 2-product NT GEMM. A = Q (H+L), B = K (hi only).
// Block 128(n) x 64(m), BK=16 (8 kp/stage), 2-stage cp.async, 61440B smem.
// =============================================================================
__global__ __launch_bounds__(256, 2) void logitsP_kernel(
    const float* __restrict__ pi_star, const float* __restrict__ gamma_p)
{
    extern __shared__ uint32_t smu[];
    uint4* smQ = (uint4*)smu;              // [2][128][12] uint4 (12288 u32)
    uint2* smK = (uint2*)(smu + 12288);    // [2][64][12] uint2

    const int b  = blockIdx.z;
    const int n0 = blockIdx.y * 128;
    const int m0 = blockIdx.x * 64;
    const int tid = threadIdx.x;
    const int lane = tid & 31, warp = tid >> 5;
    const int wR = warp >> 1, wC = warp & 1;

    const uint4* q4 = g_q4 + (size_t)(b * Nn + n0) * 128;
    const uint2* k2 = g_kp2 + (size_t)(b * Mm + m0) * 128;

    float accS[2][4][4] = {}, accE[2][4][4] = {};
    const int nk = 16;

    {
#pragma unroll
        for (int it = 0; it < 4; it++) {
            int i = tid + it * 256;
            int r = i >> 3, kp = i & 7;
            cpa16(&smQ[(size_t)r * 12 + kp], q4 + (size_t)r * 128 + kp);
        }
        {
            int r = tid >> 2, c2 = (tid & 3) * 2;
            cpa16(&smK[(size_t)r * 12 + c2], k2 + (size_t)r * 128 + c2);
        }
        CP_COMMIT();
    }

    for (int kt = 0; kt < nk; kt++) {
        const int s = kt & 1;
        if (kt + 1 < nk) {
            const int sn = s ^ 1;
            const int k0 = (kt + 1) * 8;
#pragma unroll
            for (int it = 0; it < 4; it++) {
                int i = tid + it * 256;
                int r = i >> 3, kp = i & 7;
                cpa16(&smQ[(size_t)(sn * 128 + r) * 12 + kp], q4 + (size_t)r * 128 + k0 + kp);
            }
            {
                int r = tid >> 2, c2 = (tid & 3) * 2;
                cpa16(&smK[(size_t)(sn * 64 + r) * 12 + c2], k2 + (size_t)r * 128 + k0 + c2);
            }
            CP_COMMIT();
            CP_WAIT1();
        } else {
            CP_WAIT0();
        }
        __syncthreads();

        const int kk = lane & 3;
        uint32_t ash[2][4], asl[2][4], aeh[2][4], ael[2][4];
#pragma unroll
        for (int i = 0; i < 2; i++) {
            int m = s * 128 + wR * 32 + i * 16 + (lane >> 2);
            uint4 p0 = smQ[(size_t)m * 12 + kk];
            uint4 p1 = smQ[(size_t)(m + 8) * 12 + kk];
            uint4 p2 = smQ[(size_t)m * 12 + kk + 4];
            uint4 p3 = smQ[(size_t)(m + 8) * 12 + kk + 4];
            ash[i][0] = p0.x; ash[i][1] = p1.x; ash[i][2] = p2.x; ash[i][3] = p3.x;
            asl[i][0] = p0.y; asl[i][1] = p1.y; asl[i][2] = p2.y; asl[i][3] = p3.y;
            aeh[i][0] = p0.z; aeh[i][1] = p1.z; aeh[i][2] = p2.z; aeh[i][3] = p3.z;
            ael[i][0] = p0.w; ael[i][1] = p1.w; ael[i][2] = p2.w; ael[i][3] = p3.w;
        }
#pragma unroll
        for (int j = 0; j < 4; j++) {
            int n = s * 64 + wC * 32 + j * 8 + (lane >> 2);
            uint2 k0v = smK[(size_t)n * 12 + kk];
            uint2 k1v = smK[(size_t)n * 12 + kk + 4];
#pragma unroll
            for (int i = 0; i < 2; i++) {
                mmah(accS[i][j], ash[i], k0v.x, k1v.x);
                mmah(accE[i][j], aeh[i], k0v.y, k1v.y);
            }
#pragma unroll
            for (int i = 0; i < 2; i++) {
                mmah(accS[i][j], asl[i], k0v.x, k1v.x);
                mmah(accE[i][j], ael[i], k0v.y, k1v.y);
            }
        }
        __syncthreads();
    }

    const float g = gamma_p[0];
    float sumd = 0.0f;
#pragma unroll
    for (int i = 0; i < 2; i++) {
        int n_lo = n0 + wR * 32 + i * 16 + (lane >> 2);
        float q2a = g_q2[b * Nn + n_lo];
        float q2b = g_q2[b * Nn + n_lo + 8];
#pragma unroll
        for (int j = 0; j < 4; j++) {
            int m = m0 + wC * 32 + j * 8 + 2 * (lane & 3);
            float k2a = g_k2[b * Mm + m], k2b = g_k2[b * Mm + m + 1];
            size_t base0 = ((size_t)b * Nn + n_lo) * Mm + m;
            float2 piv = *(const float2*)&pi_star[base0];
            float d0 = sqrtf(fmaxf(q2a + k2a - 2.0f * accE[i][j][0], 1e-12f));
            float d1 = sqrtf(fmaxf(q2a + k2b - 2.0f * accE[i][j][1], 1e-12f));
            sumd += d0 + d1;
            *(float2*)&g_D[base0] = make_float2(d0, d1);
            float L0 = accS[i][j][0] * 0.0625f + g * __logf(fmaxf(piv.x, 1e-9f));
            float L1 = accS[i][j][1] * 0.0625f + g * __logf(fmaxf(piv.y, 1e-9f));
            *(float2*)&g_L[base0] = make_float2(L0, L1);
            size_t base1 = ((size_t)b * Nn + n_lo + 8) * Mm + m;
            piv = *(const float2*)&pi_star[base1];
            float d2v = sqrtf(fmaxf(q2b + k2a - 2.0f * accE[i][j][2], 1e-12f));
            float d3v = sqrtf(fmaxf(q2b + k2b - 2.0f * accE[i][j][3], 1e-12f));
            sumd += d2v + d3v;
            *(float2*)&g_D[base1] = make_float2(d2v, d3v);
            float L2 = accS[i][j][2] * 0.0625f + g * __logf(fmaxf(piv.x, 1e-9f));
            float L3 = accS[i][j][3] * 0.0625f + g * __logf(fmaxf(piv.y, 1e-9f));
            *(float2*)&g_L[base1] = make_float2(L2, L3);
        }
    }
    float* red = (float*)smu;
    red[tid] = sumd;
    __syncthreads();
    for (int sred = 128; sred > 0; sred >>= 1) {
        if (tid < sred) red[tid] += red[tid + sred];
        __syncthreads();
    }
    if (tid == 0) atomicAdd(&g_dsum[b], red[0]);
}

// =============================================================================
// Ctx: dual fp16 2-product NN GEMM. A = probs (H+L), B = V^T (hi only).
// Block 128(n) x 64(h), BK=32 (16 kp/stage), 2-stage cp.async, 61440B smem.
// =============================================================================
__global__ __launch_bounds__(256, 2) void ctxP_kernel()
{
    extern __shared__ uint32_t smu[];
    uint2* smP = (uint2*)smu;                // [2][128][20] uint2 (10240 u32)
    uint2* smV = (uint2*)(smu + 10240);      // [2][64][20] uint2

    const int b  = blockIdx.z;
    const int n0 = blockIdx.y * 128;
    const int h0 = blockIdx.x * 64;
    const int tid = threadIdx.x;
    const int lane = tid & 31, warp = tid >> 5;
    const int wR = warp >> 1, wC = warp & 1;

    const uint2* p2 = g_p2 + (size_t)(b * Nn + n0) * 1024;
    const uint2* v2 = g_vT2 + ((size_t)b * Hh + h0) * 1024;

    float accS[2][4][4] = {}, accE[2][4][4] = {};
    const int nk = 64;

    {
#pragma unroll
        for (int it = 0; it < 4; it++) {
            int i = tid + it * 256;
            int r = i >> 3, c2 = (i & 7) * 2;
            cpa16(&smP[(size_t)r * 20 + c2], p2 + (size_t)r * 1024 + c2);
        }
#pragma unroll
        for (int it = 0; it < 2; it++) {
            int i = tid + it * 256;
            int r = i >> 3, c2 = (i & 7) * 2;
            cpa16(&smV[(size_t)r * 20 + c2], v2 + (size_t)r * 1024 + c2);
        }
        CP_COMMIT();
    }

    for (int kt = 0; kt < nk; kt++) {
        const int s = kt & 1;
        if (kt + 1 < nk) {
            const int sn = s ^ 1;
            const int mp0 = (kt + 1) * 16;
#pragma unroll
            for (int it = 0; it < 4; it++) {
                int i = tid + it * 256;
                int r = i >> 3, c2 = (i & 7) * 2;
                cpa16(&smP[(size_t)(sn * 128 + r) * 20 + c2],
                      p2 + (size_t)r * 1024 + mp0 + c2);
            }
#pragma unroll
            for (int it = 0; it < 2; it++) {
                int i = tid + it * 256;
                int r = i >> 3, c2 = (i & 7) * 2;
                cpa16(&smV[(size_t)(sn * 64 + r) * 20 + c2],
                      v2 + (size_t)r * 1024 + mp0 + c2);
            }
            CP_COMMIT();
            CP_WAIT1();
        } else {
            CP_WAIT0();
        }
        __syncthreads();
#pragma unroll
        for (int ks = 0; ks < 2; ks++) {
            const int kk = ks * 8 + (lane & 3);
            uint32_t ph[2][4], pl[2][4];
#pragma unroll
            for (int i = 0; i < 2; i++) {
                int m = s * 128 + wR * 32 + i * 16 + (lane >> 2);
                uint2 p0 = smP[(size_t)m * 20 + kk];
                uint2 p1 = smP[(size_t)(m + 8) * 20 + kk];
                uint2 p2v = smP[(size_t)m * 20 + kk + 4];
                uint2 p3 = smP[(size_t)(m + 8) * 20 + kk + 4];
                ph[i][0] = p0.x; ph[i][1] = p1.x; ph[i][2] = p2v.x; ph[i][3] = p3.x;
                pl[i][0] = p0.y; pl[i][1] = p1.y; pl[i][2] = p2v.y; pl[i][3] = p3.y;
            }
#pragma unroll
            for (int j = 0; j < 4; j++) {
                int n = s * 64 + wC * 32 + j * 8 + (lane >> 2);
                uint2 v0 = smV[(size_t)n * 20 + kk];
                uint2 v1 = smV[(size_t)n * 20 + kk + 4];
#pragma unroll
                for (int i = 0; i < 2; i++) {
                    mmah(accS[i][j], ph[i], v0.x, v1.x);
                    mmah(accE[i][j], ph[i], v0.y, v1.y);
                }
#pragma unroll
                for (int i = 0; i < 2; i++) {
                    mmah(accS[i][j], pl[i], v0.x, v1.x);
                    mmah(accE[i][j], pl[i], v0.y, v1.y);
                }
            }
        }
        __syncthreads();
    }
#pragma unroll
    for (int i = 0; i < 2; i++) {
        int n_lo = n0 + wR * 32 + i * 16 + (lane >> 2);
#pragma unroll
        for (int j = 0; j < 4; j++) {
            int h = h0 + wC * 32 + j * 8 + 2 * (lane & 3);
#pragma unroll
            for (int half = 0; half < 2; half++) {
                int n = n_lo + half * 8;
                float cs0 = accS[i][j][half * 2 + 0], cs1 = accS[i][j][half * 2 + 1];
                float ce0 = accE[i][j][half * 2 + 0], ce1 = accE[i][j][half * 2 + 1];
                size_t fb = ((size_t)b * Nn + n) * 512;
                uint32_t hh, ll;
                splitH2(cs0, cs1, hh, ll);             g_f2[fb + (h >> 1)]       = make_uint2(hh, ll);
                splitH2(ce0, ce1, hh, ll);             g_f2[fb + 128 + (h >> 1)] = make_uint2(hh, ll);
                splitH2(cs0 - ce0, cs1 - ce1, hh, ll); g_f2[fb + 256 + (h >> 1)] = make_uint2(hh, ll);
                splitH2(cs0 * ce0, cs1 * ce1, hh, ll); g_f2[fb + 384 + (h >> 1)] = make_uint2(hh, ll);
            }
        }
    }
}

// ---------------- softmax ----------------
__global__ void softmax_kernel(const float* __restrict__ ew_p) {
    const int row = blockIdx.x;
    const int b   = row / Nn;
    const float invsc = ew_p[0] / g_scale[b];
    const size_t base = (size_t)row * Mm;
    const int c0 = threadIdx.x * 8;
    float v[8];
    float mx = -1e30f;
#pragma unroll
    for (int q = 0; q < 2; q++) {
        float4 lv = *(const float4*)&g_L[base + c0 + q * 4];
        float4 dv = *(const float4*)&g_D[base + c0 + q * 4];
        v[q*4+0] = lv.x - dv.x * invsc; v[q*4+1] = lv.y - dv.y * invsc;
        v[q*4+2] = lv.z - dv.z * invsc; v[q*4+3] = lv.w - dv.w * invsc;
    }
#pragma unroll
    for (int t = 0; t < 8; t++) mx = fmaxf(mx, v[t]);
    __shared__ float sh[8];
    __shared__ float bc;
    int lane = threadIdx.x & 31, wid = threadIdx.x >> 5;
    float wm = warpRedMax(mx);
    if (lane == 0) sh[wid] = wm;
    __syncthreads();
    if (wid == 0) {
        float t = (lane < 8) ? sh[lane] : -1e30f;
        t = warpRedMax(t);
        if (lane == 0) bc = t;
    }
    __syncthreads();
    mx = bc;
    float sum = 0.0f;
#pragma unroll
    for (int t = 0; t < 8; t++) {
        v[t] = __expf(v[t] - mx);
        sum += v[t];
    }
    __syncthreads();
    float ws = warpRedSum(sum);
    if (lane == 0) sh[wid] = ws;
    __syncthreads();
    if (wid == 0) {
        float t = (lane < 8) ? sh[lane] : 0.0f;
        t = warpRedSum(t);
        if (lane == 0) bc = t;
    }
    __syncthreads();
    const float inv = 1.0f / bc;
    const size_t pbase = (size_t)row * 1024 + threadIdx.x * 4;
#pragma unroll
    for (int p = 0; p < 4; p++) {
        uint32_t hh, ll;
        splitH2(v[2 * p] * inv, v[2 * p + 1] * inv, hh, ll);
        g_p2[pbase + p] = make_uint2(hh, ll);
    }
}

// ---------------- launch ----------------
extern "C" void kernel_launch(void* const* d_in, const int* in_sizes, int n_in,
                              void* d_out, int out_size) {
    const float* q_fp  = (const float*)d_in[0];
    const float* v_ret = (const float*)d_in[1];
    const float* pi    = (const float*)d_in[2];
    const float* Wqs = (const float*)d_in[3];  const float* bqs = (const float*)d_in[4];
    const float* Wks = (const float*)d_in[5];  const float* bks = (const float*)d_in[6];
    const float* Wvs = (const float*)d_in[7];  const float* bvs = (const float*)d_in[8];
    const float* Wqe = (const float*)d_in[9];  const float* bqe = (const float*)d_in[10];
    const float* Wke = (const float*)d_in[11]; const float* bke = (const float*)d_in[12];
    const float* Wve = (const float*)d_in[13]; const float* bve = (const float*)d_in[14];
    const float* W1  = (const float*)d_in[15]; const float* b1  = (const float*)d_in[16];
    const float* W2  = (const float*)d_in[17]; const float* b2  = (const float*)d_in[18];
    const float* gamma = (const float*)d_in[19];
    const float* ew    = (const float*)d_in[20];
    float* out = (float*)d_out;

    uint2 *qf2, *vr2, *kp2, *vT2, *f2, *h2;
    uint32_t *w1p;
    uint4 *q4;
    float *vs_p, *ve_p, *q2_p, *k2_p;
    cudaGetSymbolAddress((void**)&qf2, g_qf2);
    cudaGetSymbolAddress((void**)&vr2, g_vr2);
    cudaGetSymbolAddress((void**)&w1p, g_w1p);
    cudaGetSymbolAddress((void**)&q4, g_q4);
    cudaGetSymbolAddress((void**)&kp2, g_kp2);
    cudaGetSymbolAddress((void**)&vT2, g_vT2);
    cudaGetSymbolAddress((void**)&f2, g_f2);
    cudaGetSymbolAddress((void**)&h2, g_h2);
    cudaGetSymbolAddress((void**)&vs_p, g_vs);
    cudaGetSymbolAddress((void**)&ve_p, g_ve);
    cudaGetSymbolAddress((void**)&q2_p, g_q2);
    cudaGetSymbolAddress((void**)&k2_p, g_k2);

    const int G2_SMEM    = 9216 * 4;     // 36864
    const int GEMM_SMEM  = 15360 * 4;    // 61440
    const int LOGIT_SMEM = 15360 * 4;    // 61440
    const int CTX_SMEM   = 15360 * 4;    // 61440
    cudaFuncSetAttribute(gemm2_kernel,   cudaFuncAttributeMaxDynamicSharedMemorySize, G2_SMEM);
    cudaFuncSetAttribute(gemmP_kernel,   cudaFuncAttributeMaxDynamicSharedMemorySize, GEMM_SMEM);
    cudaFuncSetAttribute(logitsP_kernel, cudaFuncAttributeMaxDynamicSharedMemorySize, LOGIT_SMEM);
    cudaFuncSetAttribute(ctxP_kernel,    cudaFuncAttributeMaxDynamicSharedMemorySize, CTX_SMEM);

    // weight slots: qs,ks,vs,qe,ke,ve,W1,W2 (u32 units)
    uint32_t* wo[8] = {w1p, w1p+65536, w1p+131072, w1p+196608, w1p+262144, w1p+327680,
                       w1p+393216, w1p+524288};

    dim3 gp(4, (Bb * Nn) / 128);

    // launch order: OUR idx4 = gemm2_q (ncu profiles global launch #5 = our #4)
    pack_rows_kernel<<<(Bb*Nn*DIN/2 + 255)/256, 256>>>(q_fp,  qf2, Bb*Nn*DIN/2);     // 0
    pack_rows_kernel<<<(Bb*Mm*DIN/2 + 255)/256, 256>>>(v_ret, vr2, Bb*Mm*DIN/2);     // 1
    pack_weight_kernel<<<(256*256 + 255)/256, 256>>>(Wqs, wo[0], 256, 256);          // 2
    pack_weight_kernel<<<(256*256 + 255)/256, 256>>>(Wqe, wo[3], 256, 256);          // 3
    gemm2_kernel<<<gp, 256, G2_SMEM>>>(qf2, wo[0], wo[3], bqs, bqe,
                                       q4, nullptr, nullptr, nullptr, 256);          // 4 <- profiled
    pack_weight_kernel<<<(256*256 + 255)/256, 256>>>(Wks, wo[1], 256, 256);
    pack_weight_kernel<<<(256*256 + 255)/256, 256>>>(Wke, wo[4], 256, 256);
    gemm2_kernel<<<gp, 256, G2_SMEM>>>(vr2, wo[1], wo[4], bks, bke,
                                       nullptr, kp2, nullptr, nullptr, 256);
    pack_weight_kernel<<<(256*256 + 255)/256, 256>>>(Wvs, wo[2], 256, 256);
    pack_weight_kernel<<<(256*256 + 255)/256, 256>>>(Wve, wo[5], 256, 256);
    gemm2_kernel<<<gp, 256, G2_SMEM>>>(vr2, wo[2], wo[5], bvs, bve,
                                       nullptr, nullptr, vs_p, ve_p, 256);
    pack_weight_kernel<<<(512*256 + 255)/256, 256>>>(W1, wo[6], 512, 256);
    pack_weight_kernel<<<(128*256 + 255)/256, 256>>>(W2, wo[7], 128, 256);

    dim3 gt(Mm / 64, Hh / 32, Bb);
    transpose_pack2_kernel<<<gt, 256>>>(vs_p, ve_p, vT2);

    rowsumsq_q_kernel<<<Bb * Nn, 128>>>(q4, q2_p);
    rowsumsq_k_kernel<<<Bb * Mm, 128>>>(kp2, k2_p);

    zero_dsum_kernel<<<1, 32>>>();
    dim3 gl(Mm / 64, Nn / 128, Bb);
    logitsP_kernel<<<gl, 256, LOGIT_SMEM>>>(pi, gamma);
    finalize_scale_kernel<<<1, 32>>>();

    softmax_kernel<<<Bb * Nn, 256>>>(ew);

    dim3 gc(Hh / 64, Nn / 128, Bb);
    ctxP_kernel<<<gc, 256, CTX_SMEM>>>();

    dim3 gm(2, (Bb * Nn) / 128);
    gemmP_kernel<<<gm, 256, GEMM_SMEM>>>(f2, wo[6], b1, nullptr, (uint32_t*)h2, 2, 512, 256, 1);
    gemmP_kernel<<<gm, 256, GEMM_SMEM>>>(h2, wo[7], b2, out, nullptr, 0, 128, 256, 0);
}

// round 11
// speedup vs baseline: 1.9414x; 1.5512x over previous
#include <cuda_runtime.h>
#include <cuda_fp16.h>
#include <cstdint>

#define Bb 8
#define Nn 2048
#define Mm 2048
#define DIN 512
#define Hh 256

// ---------------- scratch (device globals; no allocs allowed) ----------------
__device__ uint32_t g_qf1[(size_t)Bb*Nn*(DIN/2)];         // inputs fp16 hi, packed pairs
__device__ uint32_t g_vr1[(size_t)Bb*Mm*(DIN/2)];
__device__ uint32_t g_w1p[6*65536 + 131072 + 32768];      // weights fp16 hi, n-major [n][kp]
__device__ uint2 g_qp[(size_t)Bb*Nn*128];                 // {qsH, qeH}
__device__ uint2 g_kp[(size_t)Bb*Mm*128];                 // {ksH, keH}
__device__ float g_vs[(size_t)Bb*Mm*Hh], g_ve[(size_t)Bb*Mm*Hh];
__device__ uint2 g_vT2[(size_t)Bb*Hh*1024];               // {vsH, veH} [b][h][mp]
__device__ float g_L[(size_t)Bb*Nn*Mm];
__device__ float g_D[(size_t)Bb*Nn*Mm];
__device__ uint32_t g_p1[(size_t)Bb*Nn*1024];             // probs fp16 hi
__device__ uint32_t g_f1[(size_t)Bb*Nn*512];              // fused fp16 hi
__device__ uint32_t g_h1[(size_t)Bb*Nn*128];              // hidden fp16 hi
__device__ float g_q2[Bb*Nn], g_k2[Bb*Mm], g_dsum[Bb], g_scale[Bb];

// ---------------- helpers ----------------
__device__ __forceinline__ uint32_t cvtH2(float f0, float f1) {
    __half h0 = __float2half(f0), h1 = __float2half(f1);
    return (uint32_t)__half_as_ushort(h0) | ((uint32_t)__half_as_ushort(h1) << 16);
}
__device__ __forceinline__ float hlo(uint32_t u) {
    return __half2float(__ushort_as_half((unsigned short)(u & 0xffff)));
}
__device__ __forceinline__ float hhi(uint32_t u) {
    return __half2float(__ushort_as_half((unsigned short)(u >> 16)));
}
__device__ __forceinline__ void mmah(float* d, const uint32_t* a, uint32_t b0, uint32_t b1) {
    asm volatile(
        "mma.sync.aligned.m16n8k16.row.col.f32.f16.f16.f32 "
        "{%0,%1,%2,%3}, {%4,%5,%6,%7}, {%8,%9}, {%0,%1,%2,%3};\n"
        : "+f"(d[0]), "+f"(d[1]), "+f"(d[2]), "+f"(d[3])
        : "r"(a[0]), "r"(a[1]), "r"(a[2]), "r"(a[3]), "r"(b0), "r"(b1));
}
__device__ __forceinline__ void cpa16(void* smem, const void* gmem) {
    uint32_t s = (uint32_t)__cvta_generic_to_shared(smem);
    asm volatile("cp.async.cg.shared.global [%0], [%1], 16;\n" :: "r"(s), "l"(gmem));
}
#define CP_COMMIT() asm volatile("cp.async.commit_group;\n")
#define CP_WAIT1()  asm volatile("cp.async.wait_group 1;\n")
#define CP_WAIT0()  asm volatile("cp.async.wait_group 0;\n")

__device__ __forceinline__ float warpRedSum(float v) {
#pragma unroll
    for (int o = 16; o > 0; o >>= 1) v += __shfl_xor_sync(0xffffffffu, v, o);
    return v;
}
__device__ __forceinline__ float warpRedMax(float v) {
#pragma unroll
    for (int o = 16; o > 0; o >>= 1) v = fmaxf(v, __shfl_xor_sync(0xffffffffu, v, o));
    return v;
}

// ---------------- prep kernels ----------------
__global__ void pack_rows_kernel(const float* __restrict__ src,
                                 uint32_t* __restrict__ dst, int npairs) {
    int i = blockIdx.x * 256 + threadIdx.x;
    if (i >= npairs) return;
    float2 f = ((const float2*)src)[i];
    dst[i] = cvtH2(f.x, f.y);
}
__global__ void pack_weight_kernel(const float* __restrict__ W,
                                   uint32_t* __restrict__ dst, int Kp, int Nc) {
    int i = blockIdx.x * 256 + threadIdx.x;
    if (i >= Kp * Nc) return;
    int n = i / Kp, kp = i - n * Kp;
    dst[i] = cvtH2(W[(size_t)(2 * kp) * Nc + n], W[(size_t)(2 * kp + 1) * Nc + n]);
}
__global__ void transpose_pack2_kernel(const float* __restrict__ Vs,
                                       const float* __restrict__ Ve,
                                       uint2* __restrict__ T2) {
    __shared__ float ts[64][33], te[64][33];
    const int b = blockIdx.z, m0 = blockIdx.x * 64, h0 = blockIdx.y * 32;
    const int tid = threadIdx.x;
#pragma unroll
    for (int it = 0; it < 2; it++) {
        int i = tid + it * 256;
        int m = i >> 3, h4 = (i & 7) * 4;
        size_t off = ((size_t)b * Mm + m0 + m) * Hh + h0 + h4;
        float4 v = *(const float4*)&Vs[off];
        ts[m][h4 + 0] = v.x; ts[m][h4 + 1] = v.y; ts[m][h4 + 2] = v.z; ts[m][h4 + 3] = v.w;
        v = *(const float4*)&Ve[off];
        te[m][h4 + 0] = v.x; te[m][h4 + 1] = v.y; te[m][h4 + 2] = v.z; te[m][h4 + 3] = v.w;
    }
    __syncthreads();
#pragma unroll
    for (int u = 0; u < 4; u++) {
        int i = tid + u * 256;
        int h = i >> 5, mp = i & 31;
        T2[((size_t)b * Hh + h0 + h) * 1024 + (m0 >> 1) + mp] =
            make_uint2(cvtH2(ts[2 * mp][h], ts[2 * mp + 1][h]),
                       cvtH2(te[2 * mp][h], te[2 * mp + 1][h]));
    }
}
// sum of squares over the e-plane (.y) of a 128-uint2 row
__global__ void rowsumsq_kernel(const uint2* __restrict__ P2, float* __restrict__ dst) {
    const int row = blockIdx.x, tid = threadIdx.x;
    uint2 q = P2[(size_t)row * 128 + tid];
    float v0 = hlo(q.y), v1 = hhi(q.y);
    float s = v0 * v0 + v1 * v1;
    __shared__ float sh[4];
    int lane = tid & 31, wid = tid >> 5;
    float w = warpRedSum(s);
    if (lane == 0) sh[wid] = w;
    __syncthreads();
    if (wid == 0) {
        float t = (lane < 4) ? sh[lane] : 0.0f;
        t = warpRedSum(t);
        if (lane == 0) dst[row] = t;
    }
}
__global__ void zero_dsum_kernel() { if (threadIdx.x < Bb) g_dsum[threadIdx.x] = 0.0f; }
__global__ void finalize_scale_kernel() {
    if (threadIdx.x < Bb)
        g_scale[threadIdx.x] = fmaxf(g_dsum[threadIdx.x] * (1.0f / ((float)Nn * (float)Mm)), 1e-4f);
}

// =============================================================================
// Dual-output projection GEMM (fp16 1-product).
// Block 128(row) x 64(col), BK=16 (8 kp/stage), 2-stage cp.async, 24576B smem.
// =============================================================================
__global__ __launch_bounds__(256, 2) void gemm2_kernel(
    const uint32_t* __restrict__ a1,
    const uint32_t* __restrict__ wa, const uint32_t* __restrict__ wb,
    const float* __restrict__ biasA, const float* __restrict__ biasB,
    uint2* __restrict__ outQK,
    float* __restrict__ outFa, float* __restrict__ outFb,
    int Kp)
{
    extern __shared__ uint32_t smu[];
    uint32_t* smA  = smu;            // [2][128][12]
    uint32_t* smB1 = smu + 3072;     // [2][64][12]
    uint32_t* smB2 = smu + 4608;     // [2][64][12]

    const int row0 = blockIdx.y * 128;
    const int col0 = blockIdx.x * 64;
    const int tid  = threadIdx.x;
    const int lane = tid & 31, warp = tid >> 5;
    const int wR = warp >> 1, wC = warp & 1;

    float acc1[2][4][4] = {}, acc2[2][4][4] = {};
    const int nk = Kp / 8;

    const int ar = tid >> 1, ac4 = (tid & 1) * 4;
    const int bt = tid & 127;
    const int br = bt >> 1, bc4 = (bt & 1) * 4;
    uint32_t* smBsel = (tid < 128) ? smB1 : smB2;
    const uint32_t* wsel = (tid < 128) ? wa : wb;

    {   // prologue
        cpa16(&smA[(size_t)ar * 12 + ac4], a1 + (size_t)(row0 + ar) * Kp + ac4);
        cpa16(&smBsel[(size_t)br * 12 + bc4], wsel + (size_t)(col0 + br) * Kp + bc4);
        CP_COMMIT();
    }

    for (int kt = 0; kt < nk; kt++) {
        const int s = kt & 1;
        if (kt + 1 < nk) {
            const int sn = s ^ 1;
            const int k0 = (kt + 1) * 8;
            cpa16(&smA[(size_t)(sn * 128 + ar) * 12 + ac4],
                  a1 + (size_t)(row0 + ar) * Kp + k0 + ac4);
            cpa16(&smBsel[(size_t)(sn * 64 + br) * 12 + bc4],
                  wsel + (size_t)(col0 + br) * Kp + k0 + bc4);
            CP_COMMIT();
            CP_WAIT1();
        } else {
            CP_WAIT0();
        }
        __syncthreads();

        const int kk = lane & 3;
        uint32_t ah[2][4];
#pragma unroll
        for (int i = 0; i < 2; i++) {
            int m = s * 128 + wR * 32 + i * 16 + (lane >> 2);
            ah[i][0] = smA[(size_t)m * 12 + kk];
            ah[i][1] = smA[(size_t)(m + 8) * 12 + kk];
            ah[i][2] = smA[(size_t)m * 12 + kk + 4];
            ah[i][3] = smA[(size_t)(m + 8) * 12 + kk + 4];
        }
#pragma unroll
        for (int j = 0; j < 4; j++) {
            int n = s * 64 + wC * 32 + j * 8 + (lane >> 2);
            uint32_t b10 = smB1[(size_t)n * 12 + kk], b11 = smB1[(size_t)n * 12 + kk + 4];
            uint32_t b20 = smB2[(size_t)n * 12 + kk], b21 = smB2[(size_t)n * 12 + kk + 4];
#pragma unroll
            for (int i = 0; i < 2; i++) {
                mmah(acc1[i][j], ah[i], b10, b11);
                mmah(acc2[i][j], ah[i], b20, b21);
            }
        }
        __syncthreads();
    }

#pragma unroll
    for (int i = 0; i < 2; i++) {
        int r = row0 + wR * 32 + i * 16 + (lane >> 2);
#pragma unroll
        for (int j = 0; j < 4; j++) {
            int c = col0 + wC * 32 + j * 8 + 2 * (lane & 3);
            float ba0 = biasA[c], ba1 = biasA[c + 1];
            float bb0 = biasB[c], bb1 = biasB[c + 1];
#pragma unroll
            for (int half = 0; half < 2; half++) {
                int rr = r + half * 8;
                float va0 = acc1[i][j][half * 2 + 0] + ba0;
                float va1 = acc1[i][j][half * 2 + 1] + ba1;
                float vb0 = acc2[i][j][half * 2 + 0] + bb0;
                float vb1 = acc2[i][j][half * 2 + 1] + bb1;
                if (outQK) {
                    outQK[(size_t)rr * 128 + (c >> 1)] =
                        make_uint2(cvtH2(va0, va1), cvtH2(vb0, vb1));
                } else {
                    *(float2*)&outFa[(size_t)rr * 256 + c] = make_float2(va0, va1);
                    *(float2*)&outFb[(size_t)rr * 256 + c] = make_float2(vb0, vb1);
                }
            }
        }
    }
}

// =============================================================================
// Single-output GEMM for MLP (fp16 1-product).
// Tile 128x128, BK=32 (16 kp), 2-stage cp.async, 40960B smem.
// =============================================================================
__global__ __launch_bounds__(256, 2) void gemmP_kernel(
    const uint32_t* __restrict__ a1, const uint32_t* __restrict__ w1p,
    const float* __restrict__ bias,
    float* __restrict__ outF, uint32_t* __restrict__ outP,
    int Kp, int Nc, int act)
{
    extern __shared__ uint32_t smu[];
    uint32_t* smA = smu;             // [2][128][20]
    uint32_t* smB = smu + 5120;      // [2][128][20]

    const int row0 = blockIdx.y * 128;
    const int col0 = blockIdx.x * 128;
    const int tid  = threadIdx.x;
    const int lane = tid & 31, warp = tid >> 5;
    const int wR = warp >> 1, wC = warp & 1;

    float acc[2][8][4] = {};
    const int nk = Kp / 16;

    {
#pragma unroll
        for (int it = 0; it < 2; it++) {
            int i = tid + it * 256;
            int r = i >> 2, c4 = (i & 3) * 4;
            cpa16(&smA[(size_t)r * 20 + c4], a1 + (size_t)(row0 + r) * Kp + c4);
            cpa16(&smB[(size_t)r * 20 + c4], w1p + (size_t)(col0 + r) * Kp + c4);
        }
        CP_COMMIT();
    }

    for (int kt = 0; kt < nk; kt++) {
        const int s = kt & 1;
        if (kt + 1 < nk) {
            const int sn = s ^ 1;
            const int k0 = (kt + 1) * 16;
#pragma unroll
            for (int it = 0; it < 2; it++) {
                int i = tid + it * 256;
                int r = i >> 2, c4 = (i & 3) * 4;
                cpa16(&smA[(size_t)(sn * 128 + r) * 20 + c4],
                      a1 + (size_t)(row0 + r) * Kp + k0 + c4);
                cpa16(&smB[(size_t)(sn * 128 + r) * 20 + c4],
                      w1p + (size_t)(col0 + r) * Kp + k0 + c4);
            }
            CP_COMMIT();
            CP_WAIT1();
        } else {
            CP_WAIT0();
        }
        __syncthreads();
#pragma unroll
        for (int ks = 0; ks < 2; ks++) {
            const int kk = ks * 8 + (lane & 3);
            uint32_t ah[2][4];
#pragma unroll
            for (int i = 0; i < 2; i++) {
                int m = s * 128 + wR * 32 + i * 16 + (lane >> 2);
                ah[i][0] = smA[(size_t)m * 20 + kk];
                ah[i][1] = smA[(size_t)(m + 8) * 20 + kk];
                ah[i][2] = smA[(size_t)m * 20 + kk + 4];
                ah[i][3] = smA[(size_t)(m + 8) * 20 + kk + 4];
            }
#pragma unroll
            for (int j = 0; j < 8; j++) {
                int n = s * 128 + wC * 64 + j * 8 + (lane >> 2);
                uint32_t b0 = smB[(size_t)n * 20 + kk];
                uint32_t b1 = smB[(size_t)n * 20 + kk + 4];
#pragma unroll
                for (int i = 0; i < 2; i++)
                    mmah(acc[i][j], ah[i], b0, b1);
            }
        }
        __syncthreads();
    }
#pragma unroll
    for (int i = 0; i < 2; i++) {
        int r = row0 + wR * 32 + i * 16 + (lane >> 2);
#pragma unroll
        for (int j = 0; j < 8; j++) {
            int c = col0 + wC * 64 + j * 8 + 2 * (lane & 3);
            float b0 = bias[c], b1 = bias[c + 1];
            float v0 = acc[i][j][0] + b0, v1 = acc[i][j][1] + b1;
            float v2 = acc[i][j][2] + b0, v3 = acc[i][j][3] + b1;
            if (act) {
                v0 = v0 / (1.0f + __expf(-v0));
                v1 = v1 / (1.0f + __expf(-v1));
                v2 = v2 / (1.0f + __expf(-v2));
                v3 = v3 / (1.0f + __expf(-v3));
            }
            if (outP) {
                outP[(size_t)r * (Nc >> 1) + (c >> 1)]       = cvtH2(v0, v1);
                outP[(size_t)(r + 8) * (Nc >> 1) + (c >> 1)] = cvtH2(v2, v3);
            } else {
                *(float2*)&outF[(size_t)r * Nc + c]       = make_float2(v0, v1);
                *(float2*)&outF[(size_t)(r + 8) * Nc + c] = make_float2(v2, v3);
            }
        }
    }
}

// =============================================================================
// Logits: dual fp16 1-product NT GEMM. A = {qs,qe} uint2, B = {ks,ke} uint2.
// Block 128(n) x 64(m), BK=16 (8 kp/stage), 2-stage cp.async, 36864B smem.
// =============================================================================
__global__ __launch_bounds__(256, 2) void logitsP_kernel(
    const float* __restrict__ pi_star, const float* __restrict__ gamma_p)
{
    extern __shared__ uint32_t smu[];
    uint2* smQ = (uint2*)smu;              // [2][128][12]
    uint2* smK = (uint2*)(smu + 6144);     // [2][64][12]

    const int b  = blockIdx.z;
    const int n0 = blockIdx.y * 128;
    const int m0 = blockIdx.x * 64;
    const int tid = threadIdx.x;
    const int lane = tid & 31, warp = tid >> 5;
    const int wR = warp >> 1, wC = warp & 1;

    const uint2* q2p = g_qp + (size_t)(b * Nn + n0) * 128;
    const uint2* k2p = g_kp + (size_t)(b * Mm + m0) * 128;

    float accS[2][4][4] = {}, accE[2][4][4] = {};
    const int nk = 16;

    {
#pragma unroll
        for (int it = 0; it < 2; it++) {
            int i = tid + it * 256;
            int r = i >> 2, c2 = (i & 3) * 2;
            cpa16(&smQ[(size_t)r * 12 + c2], q2p + (size_t)r * 128 + c2);
        }
        {
            int r = tid >> 2, c2 = (tid & 3) * 2;
            cpa16(&smK[(size_t)r * 12 + c2], k2p + (size_t)r * 128 + c2);
        }
        CP_COMMIT();
    }

    for (int kt = 0; kt < nk; kt++) {
        const int s = kt & 1;
        if (kt + 1 < nk) {
            const int sn = s ^ 1;
            const int k0 = (kt + 1) * 8;
#pragma unroll
            for (int it = 0; it < 2; it++) {
                int i = tid + it * 256;
                int r = i >> 2, c2 = (i & 3) * 2;
                cpa16(&smQ[(size_t)(sn * 128 + r) * 12 + c2],
                      q2p + (size_t)r * 128 + k0 + c2);
            }
            {
                int r = tid >> 2, c2 = (tid & 3) * 2;
                cpa16(&smK[(size_t)(sn * 64 + r) * 12 + c2],
                      k2p + (size_t)r * 128 + k0 + c2);
            }
            CP_COMMIT();
            CP_WAIT1();
        } else {
            CP_WAIT0();
        }
        __syncthreads();

        const int kk = lane & 3;
        uint32_t ash[2][4], aeh[2][4];
#pragma unroll
        for (int i = 0; i < 2; i++) {
            int m = s * 128 + wR * 32 + i * 16 + (lane >> 2);
            uint2 p0 = smQ[(size_t)m * 12 + kk];
            uint2 p1 = smQ[(size_t)(m + 8) * 12 + kk];
            uint2 p2 = smQ[(size_t)m * 12 + kk + 4];
            uint2 p3 = smQ[(size_t)(m + 8) * 12 + kk + 4];
            ash[i][0] = p0.x; ash[i][1] = p1.x; ash[i][2] = p2.x; ash[i][3] = p3.x;
            aeh[i][0] = p0.y; aeh[i][1] = p1.y; aeh[i][2] = p2.y; aeh[i][3] = p3.y;
        }
#pragma unroll
        for (int j = 0; j < 4; j++) {
            int n = s * 64 + wC * 32 + j * 8 + (lane >> 2);
            uint2 k0v = smK[(size_t)n * 12 + kk];
            uint2 k1v = smK[(size_t)n * 12 + kk + 4];
#pragma unroll
            for (int i = 0; i < 2; i++) {
                mmah(accS[i][j], ash[i], k0v.x, k1v.x);
                mmah(accE[i][j], aeh[i], k0v.y, k1v.y);
            }
        }
        __syncthreads();
    }

    const float g = gamma_p[0];
    float sumd = 0.0f;
#pragma unroll
    for (int i = 0; i < 2; i++) {
        int n_lo = n0 + wR * 32 + i * 16 + (lane >> 2);
        float q2a = g_q2[b * Nn + n_lo];
        float q2b = g_q2[b * Nn + n_lo + 8];
#pragma unroll
        for (int j = 0; j < 4; j++) {
            int m = m0 + wC * 32 + j * 8 + 2 * (lane & 3);
            float k2a = g_k2[b * Mm + m], k2b = g_k2[b * Mm + m + 1];
            size_t base0 = ((size_t)b * Nn + n_lo) * Mm + m;
            float2 piv = *(const float2*)&pi_star[base0];
            float d0 = sqrtf(fmaxf(q2a + k2a - 2.0f * accE[i][j][0], 1e-12f));
            float d1 = sqrtf(fmaxf(q2a + k2b - 2.0f * accE[i][j][1], 1e-12f));
            sumd += d0 + d1;
            *(float2*)&g_D[base0] = make_float2(d0, d1);
            float L0 = accS[i][j][0] * 0.0625f + g * __logf(fmaxf(piv.x, 1e-9f));
            float L1 = accS[i][j][1] * 0.0625f + g * __logf(fmaxf(piv.y, 1e-9f));
            *(float2*)&g_L[base0] = make_float2(L0, L1);
            size_t base1 = ((size_t)b * Nn + n_lo + 8) * Mm + m;
            piv = *(const float2*)&pi_star[base1];
            float d2v = sqrtf(fmaxf(q2b + k2a - 2.0f * accE[i][j][2], 1e-12f));
            float d3v = sqrtf(fmaxf(q2b + k2b - 2.0f * accE[i][j][3], 1e-12f));
            sumd += d2v + d3v;
            *(float2*)&g_D[base1] = make_float2(d2v, d3v);
            float L2 = accS[i][j][2] * 0.0625f + g * __logf(fmaxf(piv.x, 1e-9f));
            float L3 = accS[i][j][3] * 0.0625f + g * __logf(fmaxf(piv.y, 1e-9f));
            *(float2*)&g_L[base1] = make_float2(L2, L3);
        }
    }
    float* red = (float*)smu;
    red[tid] = sumd;
    __syncthreads();
    for (int sred = 128; sred > 0; sred >>= 1) {
        if (tid < sred) red[tid] += red[tid + sred];
        __syncthreads();
    }
    if (tid == 0) atomicAdd(&g_dsum[b], red[0]);
}

// =============================================================================
// Ctx: dual fp16 1-product NN GEMM. A = probs u32, B = {vs,ve} uint2.
// Block 128(n) x 64(h), BK=32 (16 kp/stage), 2-stage cp.async, 40960B smem.
// =============================================================================
__global__ __launch_bounds__(256, 2) void ctxP_kernel()
{
    extern __shared__ uint32_t smu[];
    uint32_t* smP = smu;                   // [2][128][20]
    uint2*    smV = (uint2*)(smu + 5120);  // [2][64][20]

    const int b  = blockIdx.z;
    const int n0 = blockIdx.y * 128;
    const int h0 = blockIdx.x * 64;
    const int tid = threadIdx.x;
    const int lane = tid & 31, warp = tid >> 5;
    const int wR = warp >> 1, wC = warp & 1;

    const uint32_t* p1 = g_p1 + (size_t)(b * Nn + n0) * 1024;
    const uint2* v2 = g_vT2 + ((size_t)b * Hh + h0) * 1024;

    float accS[2][4][4] = {}, accE[2][4][4] = {};
    const int nk = 64;

    {
#pragma unroll
        for (int it = 0; it < 2; it++) {
            int i = tid + it * 256;
            int r = i >> 2, c4 = (i & 3) * 4;
            cpa16(&smP[(size_t)r * 20 + c4], p1 + (size_t)r * 1024 + c4);
            int rv = i >> 3, c2 = (i & 7) * 2;
            cpa16(&smV[(size_t)rv * 20 + c2], v2 + (size_t)rv * 1024 + c2);
        }
        CP_COMMIT();
    }

    for (int kt = 0; kt < nk; kt++) {
        const int s = kt & 1;
        if (kt + 1 < nk) {
            const int sn = s ^ 1;
            const int mp0 = (kt + 1) * 16;
#pragma unroll
            for (int it = 0; it < 2; it++) {
                int i = tid + it * 256;
                int r = i >> 2, c4 = (i & 3) * 4;
                cpa16(&smP[(size_t)(sn * 128 + r) * 20 + c4],
                      p1 + (size_t)r * 1024 + mp0 + c4);
                int rv = i >> 3, c2 = (i & 7) * 2;
                cpa16(&smV[(size_t)(sn * 64 + rv) * 20 + c2],
                      v2 + (size_t)rv * 1024 + mp0 + c2);
            }
            CP_COMMIT();
            CP_WAIT1();
        } else {
            CP_WAIT0();
        }
        __syncthreads();
#pragma unroll
        for (int ks = 0; ks < 2; ks++) {
            const int kk = ks * 8 + (lane & 3);
            uint32_t ph[2][4];
#pragma unroll
            for (int i = 0; i < 2; i++) {
                int m = s * 128 + wR * 32 + i * 16 + (lane >> 2);
                ph[i][0] = smP[(size_t)m * 20 + kk];
                ph[i][1] = smP[(size_t)(m + 8) * 20 + kk];
                ph[i][2] = smP[(size_t)m * 20 + kk + 4];
                ph[i][3] = smP[(size_t)(m + 8) * 20 + kk + 4];
            }
#pragma unroll
            for (int j = 0; j < 4; j++) {
                int n = s * 64 + wC * 32 + j * 8 + (lane >> 2);
                uint2 v0 = smV[(size_t)n * 20 + kk];
                uint2 v1 = smV[(size_t)n * 20 + kk + 4];
#pragma unroll
                for (int i = 0; i < 2; i++) {
                    mmah(accS[i][j], ph[i], v0.x, v1.x);
                    mmah(accE[i][j], ph[i], v0.y, v1.y);
                }
            }
        }
        __syncthreads();
    }
#pragma unroll
    for (int i = 0; i < 2; i++) {
        int n_lo = n0 + wR * 32 + i * 16 + (lane >> 2);
#pragma unroll
        for (int j = 0; j < 4; j++) {
            int h = h0 + wC * 32 + j * 8 + 2 * (lane & 3);
#pragma unroll
            for (int half = 0; half < 2; half++) {
                int n = n_lo + half * 8;
                float cs0 = accS[i][j][half * 2 + 0], cs1 = accS[i][j][half * 2 + 1];
                float ce0 = accE[i][j][half * 2 + 0], ce1 = accE[i][j][half * 2 + 1];
                size_t fb = ((size_t)b * Nn + n) * 512;
                g_f1[fb + (h >> 1)]       = cvtH2(cs0, cs1);
                g_f1[fb + 128 + (h >> 1)] = cvtH2(ce0, ce1);
                g_f1[fb + 256 + (h >> 1)] = cvtH2(cs0 - ce0, cs1 - ce1);
                g_f1[fb + 384 + (h >> 1)] = cvtH2(cs0 * ce0, cs1 * ce1);
            }
        }
    }
}

// ---------------- softmax ----------------
__global__ void softmax_kernel(const float* __restrict__ ew_p) {
    const int row = blockIdx.x;
    const int b   = row / Nn;
    const float invsc = ew_p[0] / g_scale[b];
    const size_t base = (size_t)row * Mm;
    const int c0 = threadIdx.x * 8;
    float v[8];
    float mx = -1e30f;
#pragma unroll
    for (int q = 0; q < 2; q++) {
        float4 lv = *(const float4*)&g_L[base + c0 + q * 4];
        float4 dv = *(const float4*)&g_D[base + c0 + q * 4];
        v[q*4+0] = lv.x - dv.x * invsc; v[q*4+1] = lv.y - dv.y * invsc;
        v[q*4+2] = lv.z - dv.z * invsc; v[q*4+3] = lv.w - dv.w * invsc;
    }
#pragma unroll
    for (int t = 0; t < 8; t++) mx = fmaxf(mx, v[t]);
    __shared__ float sh[8];
    __shared__ float bc;
    int lane = threadIdx.x & 31, wid = threadIdx.x >> 5;
    float wm = warpRedMax(mx);
    if (lane == 0) sh[wid] = wm;
    __syncthreads();
    if (wid == 0) {
        float t = (lane < 8) ? sh[lane] : -1e30f;
        t = warpRedMax(t);
        if (lane == 0) bc = t;
    }
    __syncthreads();
    mx = bc;
    float sum = 0.0f;
#pragma unroll
    for (int t = 0; t < 8; t++) {
        v[t] = __expf(v[t] - mx);
        sum += v[t];
    }
    __syncthreads();
    float ws = warpRedSum(sum);
    if (lane == 0) sh[wid] = ws;
    __syncthreads();
    if (wid == 0) {
        float t = (lane < 8) ? sh[lane] : 0.0f;
        t = warpRedSum(t);
        if (lane == 0) bc = t;
    }
    __syncthreads();
    const float inv = 1.0f / bc;
    const size_t pbase = (size_t)row * 1024 + threadIdx.x * 4;
#pragma unroll
    for (int p = 0; p < 4; p++)
        g_p1[pbase + p] = cvtH2(v[2 * p] * inv, v[2 * p + 1] * inv);
}

// ---------------- launch ----------------
extern "C" void kernel_launch(void* const* d_in, const int* in_sizes, int n_in,
                              void* d_out, int out_size) {
    const float* q_fp  = (const float*)d_in[0];
    const float* v_ret = (const float*)d_in[1];
    const float* pi    = (const float*)d_in[2];
    const float* Wqs = (const float*)d_in[3];  const float* bqs = (const float*)d_in[4];
    const float* Wks = (const float*)d_in[5];  const float* bks = (const float*)d_in[6];
    const float* Wvs = (const float*)d_in[7];  const float* bvs = (const float*)d_in[8];
    const float* Wqe = (const float*)d_in[9];  const float* bqe = (const float*)d_in[10];
    const float* Wke = (const float*)d_in[11]; const float* bke = (const float*)d_in[12];
    const float* Wve = (const float*)d_in[13]; const float* bve = (const float*)d_in[14];
    const float* W1  = (const float*)d_in[15]; const float* b1  = (const float*)d_in[16];
    const float* W2  = (const float*)d_in[17]; const float* b2  = (const float*)d_in[18];
    const float* gamma = (const float*)d_in[19];
    const float* ew    = (const float*)d_in[20];
    float* out = (float*)d_out;

    uint32_t *qf1, *vr1, *w1p, *p1_, *f1, *h1;
    uint2 *qp, *kp, *vT2;
    float *vs_p, *ve_p, *q2_p, *k2_p;
    cudaGetSymbolAddress((void**)&qf1, g_qf1);
    cudaGetSymbolAddress((void**)&vr1, g_vr1);
    cudaGetSymbolAddress((void**)&w1p, g_w1p);
    cudaGetSymbolAddress((void**)&qp, g_qp);
    cudaGetSymbolAddress((void**)&kp, g_kp);
    cudaGetSymbolAddress((void**)&vT2, g_vT2);
    cudaGetSymbolAddress((void**)&p1_, g_p1);
    cudaGetSymbolAddress((void**)&f1, g_f1);
    cudaGetSymbolAddress((void**)&h1, g_h1);
    cudaGetSymbolAddress((void**)&vs_p, g_vs);
    cudaGetSymbolAddress((void**)&ve_p, g_ve);
    cudaGetSymbolAddress((void**)&q2_p, g_q2);
    cudaGetSymbolAddress((void**)&k2_p, g_k2);

    const int G2_SMEM    = 6144 * 4;     // 24576
    const int GEMM_SMEM  = 10240 * 4;    // 40960
    const int LOGIT_SMEM = 9216 * 4;     // 36864
    const int CTX_SMEM   = 10240 * 4;    // 40960
    cudaFuncSetAttribute(gemm2_kernel,   cudaFuncAttributeMaxDynamicSharedMemorySize, G2_SMEM);
    cudaFuncSetAttribute(gemmP_kernel,   cudaFuncAttributeMaxDynamicSharedMemorySize, GEMM_SMEM);
    cudaFuncSetAttribute(logitsP_kernel, cudaFuncAttributeMaxDynamicSharedMemorySize, LOGIT_SMEM);
    cudaFuncSetAttribute(ctxP_kernel,    cudaFuncAttributeMaxDynamicSharedMemorySize, CTX_SMEM);

    uint32_t* wo[8] = {w1p, w1p+65536, w1p+131072, w1p+196608, w1p+262144, w1p+327680,
                       w1p+393216, w1p+524288};

    dim3 gp(4, (Bb * Nn) / 128);

    // launch order: OUR idx4 = gemm2_q (ncu profiles global launch #5 = our #4)
    pack_rows_kernel<<<(Bb*Nn*DIN/2 + 255)/256, 256>>>(q_fp,  qf1, Bb*Nn*DIN/2);     // 0
    pack_rows_kernel<<<(Bb*Mm*DIN/2 + 255)/256, 256>>>(v_ret, vr1, Bb*Mm*DIN/2);     // 1
    pack_weight_kernel<<<(256*256 + 255)/256, 256>>>(Wqs, wo[0], 256, 256);          // 2
    pack_weight_kernel<<<(256*256 + 255)/256, 256>>>(Wqe, wo[3], 256, 256);          // 3
    gemm2_kernel<<<gp, 256, G2_SMEM>>>(qf1, wo[0], wo[3], bqs, bqe,
                                       qp, nullptr, nullptr, 256);                   // 4 <- profiled
    pack_weight_kernel<<<(256*256 + 255)/256, 256>>>(Wks, wo[1], 256, 256);
    pack_weight_kernel<<<(256*256 + 255)/256, 256>>>(Wke, wo[4], 256, 256);
    gemm2_kernel<<<gp, 256, G2_SMEM>>>(vr1, wo[1], wo[4], bks, bke,
                                       kp, nullptr, nullptr, 256);
    pack_weight_kernel<<<(256*256 + 255)/256, 256>>>(Wvs, wo[2], 256, 256);
    pack_weight_kernel<<<(256*256 + 255)/256, 256>>>(Wve, wo[5], 256, 256);
    gemm2_kernel<<<gp, 256, G2_SMEM>>>(vr1, wo[2], wo[5], bvs, bve,
                                       nullptr, vs_p, ve_p, 256);
    pack_weight_kernel<<<(512*256 + 255)/256, 256>>>(W1, wo[6], 512, 256);
    pack_weight_kernel<<<(128*256 + 255)/256, 256>>>(W2, wo[7], 128, 256);

    dim3 gt(Mm / 64, Hh / 32, Bb);
    transpose_pack2_kernel<<<gt, 256>>>(vs_p, ve_p, vT2);

    rowsumsq_kernel<<<Bb * Nn, 128>>>(qp, q2_p);
    rowsumsq_kernel<<<Bb * Mm, 128>>>(kp, k2_p);

    zero_dsum_kernel<<<1, 32>>>();
    dim3 gl(Mm / 64, Nn / 128, Bb);
    logitsP_kernel<<<gl, 256, LOGIT_SMEM>>>(pi, gamma);
    finalize_scale_kernel<<<1, 32>>>();

    softmax_kernel<<<Bb * Nn, 256>>>(ew);

    dim3 gc(Hh / 64, Nn / 128, Bb);
    ctxP_kernel<<<gc, 256, CTX_SMEM>>>();

    dim3 gm(2, (Bb * Nn) / 128);
    gemmP_kernel<<<gm, 256, GEMM_SMEM>>>(f1, wo[6], b1, nullptr, h1, 512, 256, 1);
    gemmP_kernel<<<gm, 256, GEMM_SMEM>>>(h1, wo[7], b2, out, nullptr, 128, 256, 0);
}

// round 12
// speedup vs baseline: 1.9805x; 1.0201x over previous
#include <cuda_runtime.h>
#include <cuda_fp16.h>
#include <cstdint>

#define Bb 8
#define Nn 2048
#define Mm 2048
#define DIN 512
#define Hh 256

// ---------------- scratch (device globals; no allocs allowed) ----------------
__device__ uint32_t g_qf1[(size_t)Bb*Nn*(DIN/2)];
__device__ uint32_t g_vr1[(size_t)Bb*Mm*(DIN/2)];
__device__ uint32_t g_w1p[6*65536 + 131072 + 32768];
__device__ uint2 g_qp[(size_t)Bb*Nn*128];                 // {qsH, qeH}
__device__ uint2 g_kp[(size_t)Bb*Mm*128];                 // {ksH, keH}
__device__ uint2 g_vT2[(size_t)Bb*Hh*1024];               // {vsH, veH} [b][h][mp]
__device__ float g_L[(size_t)Bb*Nn*Mm];
__device__ float g_D[(size_t)Bb*Nn*Mm];
__device__ uint32_t g_p1[(size_t)Bb*Nn*1024];
__device__ uint32_t g_f1[(size_t)Bb*Nn*512];
__device__ uint32_t g_h1[(size_t)Bb*Nn*128];
__device__ float g_q2[Bb*Nn], g_k2[Bb*Mm], g_dsum[Bb];

// ---------------- helpers ----------------
__device__ __forceinline__ uint32_t cvtH2(float f0, float f1) {
    __half h0 = __float2half(f0), h1 = __float2half(f1);
    return (uint32_t)__half_as_ushort(h0) | ((uint32_t)__half_as_ushort(h1) << 16);
}
__device__ __forceinline__ float hlo(uint32_t u) {
    return __half2float(__ushort_as_half((unsigned short)(u & 0xffff)));
}
__device__ __forceinline__ float hhi(uint32_t u) {
    return __half2float(__ushort_as_half((unsigned short)(u >> 16)));
}
__device__ __forceinline__ void mmah(float* d, const uint32_t* a, uint32_t b0, uint32_t b1) {
    asm volatile(
        "mma.sync.aligned.m16n8k16.row.col.f32.f16.f16.f32 "
        "{%0,%1,%2,%3}, {%4,%5,%6,%7}, {%8,%9}, {%0,%1,%2,%3};\n"
        : "+f"(d[0]), "+f"(d[1]), "+f"(d[2]), "+f"(d[3])
        : "r"(a[0]), "r"(a[1]), "r"(a[2]), "r"(a[3]), "r"(b0), "r"(b1));
}
__device__ __forceinline__ void cpa16(void* smem, const void* gmem) {
    uint32_t s = (uint32_t)__cvta_generic_to_shared(smem);
    asm volatile("cp.async.cg.shared.global [%0], [%1], 16;\n" :: "r"(s), "l"(gmem));
}
#define CP_COMMIT() asm volatile("cp.async.commit_group;\n")
#define CP_WAIT2()  asm volatile("cp.async.wait_group 2;\n")
#define CP_WAIT1()  asm volatile("cp.async.wait_group 1;\n")
#define CP_WAIT0()  asm volatile("cp.async.wait_group 0;\n")

__device__ __forceinline__ float warpRedSum(float v) {
#pragma unroll
    for (int o = 16; o > 0; o >>= 1) v += __shfl_xor_sync(0xffffffffu, v, o);
    return v;
}
__device__ __forceinline__ float warpRedMax(float v) {
#pragma unroll
    for (int o = 16; o > 0; o >>= 1) v = fmaxf(v, __shfl_xor_sync(0xffffffffu, v, o));
    return v;
}

// ---------------- prep kernels ----------------
__global__ void pack_rows_kernel(const float* __restrict__ src,
                                 uint32_t* __restrict__ dst, int npairs) {
    int i = blockIdx.x * 256 + threadIdx.x;
    if (i >= npairs) return;
    float2 f = ((const float2*)src)[i];
    dst[i] = cvtH2(f.x, f.y);
}
__global__ void pack_weight_kernel(const float* __restrict__ W,
                                   uint32_t* __restrict__ dst, int Kp, int Nc) {
    int i = blockIdx.x * 256 + threadIdx.x;
    if (i >= Kp * Nc) return;
    int n = i / Kp, kp = i - n * Kp;
    dst[i] = cvtH2(W[(size_t)(2 * kp) * Nc + n], W[(size_t)(2 * kp + 1) * Nc + n]);
}
__global__ void rowsumsq_kernel(const uint2* __restrict__ P2, float* __restrict__ dst) {
    const int row = blockIdx.x, tid = threadIdx.x;
    uint2 q = P2[(size_t)row * 128 + tid];
    float v0 = hlo(q.y), v1 = hhi(q.y);
    float s = v0 * v0 + v1 * v1;
    __shared__ float sh[4];
    int lane = tid & 31, wid = tid >> 5;
    float w = warpRedSum(s);
    if (lane == 0) sh[wid] = w;
    __syncthreads();
    if (wid == 0) {
        float t = (lane < 4) ? sh[lane] : 0.0f;
        t = warpRedSum(t);
        if (lane == 0) dst[row] = t;
    }
}
__global__ void zero_dsum_kernel() { if (threadIdx.x < Bb) g_dsum[threadIdx.x] = 0.0f; }

// =============================================================================
// Dual-output projection GEMM (fp16 1-product).
// outQK: interleaved uint2 per row. outT: V^T path (transposed packed write).
// =============================================================================
__global__ __launch_bounds__(256, 2) void gemm2_kernel(
    const uint32_t* __restrict__ a1,
    const uint32_t* __restrict__ wa, const uint32_t* __restrict__ wb,
    const float* __restrict__ biasA, const float* __restrict__ biasB,
    uint2* __restrict__ outQK, uint2* __restrict__ outT,
    int Kp)
{
    extern __shared__ uint32_t smu[];
    uint32_t* smA  = smu;            // [2][128][12]
    uint32_t* smB1 = smu + 3072;     // [2][64][12]
    uint32_t* smB2 = smu + 4608;     // [2][64][12]

    const int row0 = blockIdx.y * 128;
    const int col0 = blockIdx.x * 64;
    const int tid  = threadIdx.x;
    const int lane = tid & 31, warp = tid >> 5;
    const int wR = warp >> 1, wC = warp & 1;

    float acc1[2][4][4] = {}, acc2[2][4][4] = {};
    const int nk = Kp / 8;

    const int ar = tid >> 1, ac4 = (tid & 1) * 4;
    const int bt = tid & 127;
    const int br = bt >> 1, bc4 = (bt & 1) * 4;
    uint32_t* smBsel = (tid < 128) ? smB1 : smB2;
    const uint32_t* wsel = (tid < 128) ? wa : wb;

    {
        cpa16(&smA[(size_t)ar * 12 + ac4], a1 + (size_t)(row0 + ar) * Kp + ac4);
        cpa16(&smBsel[(size_t)br * 12 + bc4], wsel + (size_t)(col0 + br) * Kp + bc4);
        CP_COMMIT();
    }

    for (int kt = 0; kt < nk; kt++) {
        const int s = kt & 1;
        if (kt + 1 < nk) {
            const int sn = s ^ 1;
            const int k0 = (kt + 1) * 8;
            cpa16(&smA[(size_t)(sn * 128 + ar) * 12 + ac4],
                  a1 + (size_t)(row0 + ar) * Kp + k0 + ac4);
            cpa16(&smBsel[(size_t)(sn * 64 + br) * 12 + bc4],
                  wsel + (size_t)(col0 + br) * Kp + k0 + bc4);
            CP_COMMIT();
            CP_WAIT1();
        } else {
            CP_WAIT0();
        }
        __syncthreads();

        const int kk = lane & 3;
        uint32_t ah[2][4];
#pragma unroll
        for (int i = 0; i < 2; i++) {
            int m = s * 128 + wR * 32 + i * 16 + (lane >> 2);
            ah[i][0] = smA[(size_t)m * 12 + kk];
            ah[i][1] = smA[(size_t)(m + 8) * 12 + kk];
            ah[i][2] = smA[(size_t)m * 12 + kk + 4];
            ah[i][3] = smA[(size_t)(m + 8) * 12 + kk + 4];
        }
#pragma unroll
        for (int j = 0; j < 4; j++) {
            int n = s * 64 + wC * 32 + j * 8 + (lane >> 2);
            uint32_t b10 = smB1[(size_t)n * 12 + kk], b11 = smB1[(size_t)n * 12 + kk + 4];
            uint32_t b20 = smB2[(size_t)n * 12 + kk], b21 = smB2[(size_t)n * 12 + kk + 4];
#pragma unroll
            for (int i = 0; i < 2; i++) {
                mmah(acc1[i][j], ah[i], b10, b11);
                mmah(acc2[i][j], ah[i], b20, b21);
            }
        }
        __syncthreads();
    }

#pragma unroll
    for (int i = 0; i < 2; i++) {
        int r = row0 + wR * 32 + i * 16 + (lane >> 2);
#pragma unroll
        for (int j = 0; j < 4; j++) {
            int c = col0 + wC * 32 + j * 8 + 2 * (lane & 3);
            float ba0 = biasA[c], ba1 = biasA[c + 1];
            float bb0 = biasB[c], bb1 = biasB[c + 1];
#pragma unroll
            for (int half = 0; half < 2; half++) {
                int rr = r + half * 8;
                float va0 = acc1[i][j][half * 2 + 0] + ba0;
                float va1 = acc1[i][j][half * 2 + 1] + ba1;
                float vb0 = acc2[i][j][half * 2 + 0] + bb0;
                float vb1 = acc2[i][j][half * 2 + 1] + bb1;
                if (outQK) {
                    outQK[(size_t)rr * 128 + (c >> 1)] =
                        make_uint2(cvtH2(va0, va1), cvtH2(vb0, vb1));
                } else {
                    // V^T path: pair adjacent m rows via shuffle, write [b][h][mp]
                    float pva0 = __shfl_xor_sync(0xffffffffu, va0, 4);
                    float pva1 = __shfl_xor_sync(0xffffffffu, va1, 4);
                    float pvb0 = __shfl_xor_sync(0xffffffffu, vb0, 4);
                    float pvb1 = __shfl_xor_sync(0xffffffffu, vb1, 4);
                    if (((lane >> 2) & 1) == 0) {
                        int bb = rr >> 11;                 // rr / Mm
                        int mp = (rr & 2047) >> 1;
                        size_t base = ((size_t)bb * Hh + c) * 1024 + mp;
                        outT[base]        = make_uint2(cvtH2(va0, pva0), cvtH2(vb0, pvb0));
                        outT[base + 1024] = make_uint2(cvtH2(va1, pva1), cvtH2(vb1, pvb1));
                    }
                }
            }
        }
    }
}

// =============================================================================
// Single-output GEMM for MLP (fp16 1-product). Tile 128x128, BK=32, 2-stage.
// =============================================================================
__global__ __launch_bounds__(256, 2) void gemmP_kernel(
    const uint32_t* __restrict__ a1, const uint32_t* __restrict__ w1p,
    const float* __restrict__ bias,
    float* __restrict__ outF, uint32_t* __restrict__ outP,
    int Kp, int Nc, int act)
{
    extern __shared__ uint32_t smu[];
    uint32_t* smA = smu;             // [2][128][20]
    uint32_t* smB = smu + 5120;      // [2][128][20]

    const int row0 = blockIdx.y * 128;
    const int col0 = blockIdx.x * 128;
    const int tid  = threadIdx.x;
    const int lane = tid & 31, warp = tid >> 5;
    const int wR = warp >> 1, wC = warp & 1;

    float acc[2][8][4] = {};
    const int nk = Kp / 16;

    {
#pragma unroll
        for (int it = 0; it < 2; it++) {
            int i = tid + it * 256;
            int r = i >> 2, c4 = (i & 3) * 4;
            cpa16(&smA[(size_t)r * 20 + c4], a1 + (size_t)(row0 + r) * Kp + c4);
            cpa16(&smB[(size_t)r * 20 + c4], w1p + (size_t)(col0 + r) * Kp + c4);
        }
        CP_COMMIT();
    }

    for (int kt = 0; kt < nk; kt++) {
        const int s = kt & 1;
        if (kt + 1 < nk) {
            const int sn = s ^ 1;
            const int k0 = (kt + 1) * 16;
#pragma unroll
            for (int it = 0; it < 2; it++) {
                int i = tid + it * 256;
                int r = i >> 2, c4 = (i & 3) * 4;
                cpa16(&smA[(size_t)(sn * 128 + r) * 20 + c4],
                      a1 + (size_t)(row0 + r) * Kp + k0 + c4);
                cpa16(&smB[(size_t)(sn * 128 + r) * 20 + c4],
                      w1p + (size_t)(col0 + r) * Kp + k0 + c4);
            }
            CP_COMMIT();
            CP_WAIT1();
        } else {
            CP_WAIT0();
        }
        __syncthreads();
#pragma unroll
        for (int ks = 0; ks < 2; ks++) {
            const int kk = ks * 8 + (lane & 3);
            uint32_t ah[2][4];
#pragma unroll
            for (int i = 0; i < 2; i++) {
                int m = s * 128 + wR * 32 + i * 16 + (lane >> 2);
                ah[i][0] = smA[(size_t)m * 20 + kk];
                ah[i][1] = smA[(size_t)(m + 8) * 20 + kk];
                ah[i][2] = smA[(size_t)m * 20 + kk + 4];
                ah[i][3] = smA[(size_t)(m + 8) * 20 + kk + 4];
            }
#pragma unroll
            for (int j = 0; j < 8; j++) {
                int n = s * 128 + wC * 64 + j * 8 + (lane >> 2);
                uint32_t b0 = smB[(size_t)n * 20 + kk];
                uint32_t b1 = smB[(size_t)n * 20 + kk + 4];
#pragma unroll
                for (int i = 0; i < 2; i++)
                    mmah(acc[i][j], ah[i], b0, b1);
            }
        }
        __syncthreads();
    }
#pragma unroll
    for (int i = 0; i < 2; i++) {
        int r = row0 + wR * 32 + i * 16 + (lane >> 2);
#pragma unroll
        for (int j = 0; j < 8; j++) {
            int c = col0 + wC * 64 + j * 8 + 2 * (lane & 3);
            float b0 = bias[c], b1 = bias[c + 1];
            float v0 = acc[i][j][0] + b0, v1 = acc[i][j][1] + b1;
            float v2 = acc[i][j][2] + b0, v3 = acc[i][j][3] + b1;
            if (act) {
                v0 = v0 / (1.0f + __expf(-v0));
                v1 = v1 / (1.0f + __expf(-v1));
                v2 = v2 / (1.0f + __expf(-v2));
                v3 = v3 / (1.0f + __expf(-v3));
            }
            if (outP) {
                outP[(size_t)r * (Nc >> 1) + (c >> 1)]       = cvtH2(v0, v1);
                outP[(size_t)(r + 8) * (Nc >> 1) + (c >> 1)] = cvtH2(v2, v3);
            } else {
                *(float2*)&outF[(size_t)r * Nc + c]       = make_float2(v0, v1);
                *(float2*)&outF[(size_t)(r + 8) * Nc + c] = make_float2(v2, v3);
            }
        }
    }
}

// =============================================================================
// Logits: dual fp16 1-product NT GEMM (R11, unchanged).
// =============================================================================
__global__ __launch_bounds__(256, 2) void logitsP_kernel(
    const float* __restrict__ pi_star, const float* __restrict__ gamma_p)
{
    extern __shared__ uint32_t smu[];
    uint2* smQ = (uint2*)smu;              // [2][128][12]
    uint2* smK = (uint2*)(smu + 6144);     // [2][64][12]

    const int b  = blockIdx.z;
    const int n0 = blockIdx.y * 128;
    const int m0 = blockIdx.x * 64;
    const int tid = threadIdx.x;
    const int lane = tid & 31, warp = tid >> 5;
    const int wR = warp >> 1, wC = warp & 1;

    const uint2* q2p = g_qp + (size_t)(b * Nn + n0) * 128;
    const uint2* k2p = g_kp + (size_t)(b * Mm + m0) * 128;

    float accS[2][4][4] = {}, accE[2][4][4] = {};
    const int nk = 16;

    {
#pragma unroll
        for (int it = 0; it < 2; it++) {
            int i = tid + it * 256;
            int r = i >> 2, c2 = (i & 3) * 2;
            cpa16(&smQ[(size_t)r * 12 + c2], q2p + (size_t)r * 128 + c2);
        }
        {
            int r = tid >> 2, c2 = (tid & 3) * 2;
            cpa16(&smK[(size_t)r * 12 + c2], k2p + (size_t)r * 128 + c2);
        }
        CP_COMMIT();
    }

    for (int kt = 0; kt < nk; kt++) {
        const int s = kt & 1;
        if (kt + 1 < nk) {
            const int sn = s ^ 1;
            const int k0 = (kt + 1) * 8;
#pragma unroll
            for (int it = 0; it < 2; it++) {
                int i = tid + it * 256;
                int r = i >> 2, c2 = (i & 3) * 2;
                cpa16(&smQ[(size_t)(sn * 128 + r) * 12 + c2],
                      q2p + (size_t)r * 128 + k0 + c2);
            }
            {
                int r = tid >> 2, c2 = (tid & 3) * 2;
                cpa16(&smK[(size_t)(sn * 64 + r) * 12 + c2],
                      k2p + (size_t)r * 128 + k0 + c2);
            }
            CP_COMMIT();
            CP_WAIT1();
        } else {
            CP_WAIT0();
        }
        __syncthreads();

        const int kk = lane & 3;
        uint32_t ash[2][4], aeh[2][4];
#pragma unroll
        for (int i = 0; i < 2; i++) {
            int m = s * 128 + wR * 32 + i * 16 + (lane >> 2);
            uint2 p0 = smQ[(size_t)m * 12 + kk];
            uint2 p1 = smQ[(size_t)(m + 8) * 12 + kk];
            uint2 p2 = smQ[(size_t)m * 12 + kk + 4];
            uint2 p3 = smQ[(size_t)(m + 8) * 12 + kk + 4];
            ash[i][0] = p0.x; ash[i][1] = p1.x; ash[i][2] = p2.x; ash[i][3] = p3.x;
            aeh[i][0] = p0.y; aeh[i][1] = p1.y; aeh[i][2] = p2.y; aeh[i][3] = p3.y;
        }
#pragma unroll
        for (int j = 0; j < 4; j++) {
            int n = s * 64 + wC * 32 + j * 8 + (lane >> 2);
            uint2 k0v = smK[(size_t)n * 12 + kk];
            uint2 k1v = smK[(size_t)n * 12 + kk + 4];
#pragma unroll
            for (int i = 0; i < 2; i++) {
                mmah(accS[i][j], ash[i], k0v.x, k1v.x);
                mmah(accE[i][j], aeh[i], k0v.y, k1v.y);
            }
        }
        __syncthreads();
    }

    const float g = gamma_p[0];
    float sumd = 0.0f;
#pragma unroll
    for (int i = 0; i < 2; i++) {
        int n_lo = n0 + wR * 32 + i * 16 + (lane >> 2);
        float q2a = g_q2[b * Nn + n_lo];
        float q2b = g_q2[b * Nn + n_lo + 8];
#pragma unroll
        for (int j = 0; j < 4; j++) {
            int m = m0 + wC * 32 + j * 8 + 2 * (lane & 3);
            float k2a = g_k2[b * Mm + m], k2b = g_k2[b * Mm + m + 1];
            size_t base0 = ((size_t)b * Nn + n_lo) * Mm + m;
            float2 piv = *(const float2*)&pi_star[base0];
            float d0 = sqrtf(fmaxf(q2a + k2a - 2.0f * accE[i][j][0], 1e-12f));
            float d1 = sqrtf(fmaxf(q2a + k2b - 2.0f * accE[i][j][1], 1e-12f));
            sumd += d0 + d1;
            *(float2*)&g_D[base0] = make_float2(d0, d1);
            float L0 = accS[i][j][0] * 0.0625f + g * __logf(fmaxf(piv.x, 1e-9f));
            float L1 = accS[i][j][1] * 0.0625f + g * __logf(fmaxf(piv.y, 1e-9f));
            *(float2*)&g_L[base0] = make_float2(L0, L1);
            size_t base1 = ((size_t)b * Nn + n_lo + 8) * Mm + m;
            piv = *(const float2*)&pi_star[base1];
            float d2v = sqrtf(fmaxf(q2b + k2a - 2.0f * accE[i][j][2], 1e-12f));
            float d3v = sqrtf(fmaxf(q2b + k2b - 2.0f * accE[i][j][3], 1e-12f));
            sumd += d2v + d3v;
            *(float2*)&g_D[base1] = make_float2(d2v, d3v);
            float L2 = accS[i][j][2] * 0.0625f + g * __logf(fmaxf(piv.x, 1e-9f));
            float L3 = accS[i][j][3] * 0.0625f + g * __logf(fmaxf(piv.y, 1e-9f));
            *(float2*)&g_L[base1] = make_float2(L2, L3);
        }
    }
    float* red = (float*)smu;
    red[tid] = sumd;
    __syncthreads();
    for (int sred = 128; sred > 0; sred >>= 1) {
        if (tid < sred) red[tid] += red[tid + sred];
        __syncthreads();
    }
    if (tid == 0) atomicAdd(&g_dsum[b], red[0]);
}

// =============================================================================
// Ctx: dual fp16 1-product NN GEMM, 3-stage cp.async pipeline.
// Block 128(n) x 64(h), BK=32 (16 kp/stage), 61440B smem.
// =============================================================================
__global__ __launch_bounds__(256, 2) void ctxP_kernel()
{
    extern __shared__ uint32_t smu[];
    uint32_t* smP = smu;                   // [3][128][20]
    uint2*    smV = (uint2*)(smu + 7680);  // [3][64][20]

    const int b  = blockIdx.z;
    const int n0 = blockIdx.y * 128;
    const int h0 = blockIdx.x * 64;
    const int tid = threadIdx.x;
    const int lane = tid & 31, warp = tid >> 5;
    const int wR = warp >> 1, wC = warp & 1;

    const uint32_t* p1 = g_p1 + (size_t)(b * Nn + n0) * 1024;
    const uint2* v2 = g_vT2 + ((size_t)b * Hh + h0) * 1024;

    float accS[2][4][4] = {}, accE[2][4][4] = {};
    const int nk = 64;

    // prologue: stages 0, 1
#pragma unroll
    for (int st = 0; st < 2; st++) {
        const int mp0 = st * 16;
#pragma unroll
        for (int it = 0; it < 2; it++) {
            int i = tid + it * 256;
            int r = i >> 2, c4 = (i & 3) * 4;
            cpa16(&smP[(size_t)(st * 128 + r) * 20 + c4], p1 + (size_t)r * 1024 + mp0 + c4);
            int rv = i >> 3, c2 = (i & 7) * 2;
            cpa16(&smV[(size_t)(st * 64 + rv) * 20 + c2], v2 + (size_t)rv * 1024 + mp0 + c2);
        }
        CP_COMMIT();
    }

    int s = 0;
    for (int kt = 0; kt < nk; kt++) {
        if (kt + 2 < nk) {
            const int sn = (s + 2 >= 3) ? s - 1 : s + 2;
            const int mp0 = (kt + 2) * 16;
#pragma unroll
            for (int it = 0; it < 2; it++) {
                int i = tid + it * 256;
                int r = i >> 2, c4 = (i & 3) * 4;
                cpa16(&smP[(size_t)(sn * 128 + r) * 20 + c4],
                      p1 + (size_t)r * 1024 + mp0 + c4);
                int rv = i >> 3, c2 = (i & 7) * 2;
                cpa16(&smV[(size_t)(sn * 64 + rv) * 20 + c2],
                      v2 + (size_t)rv * 1024 + mp0 + c2);
            }
            CP_COMMIT();
            CP_WAIT2();
        } else {
            CP_WAIT0();
        }
        __syncthreads();
#pragma unroll
        for (int ks = 0; ks < 2; ks++) {
            const int kk = ks * 8 + (lane & 3);
            uint32_t ph[2][4];
#pragma unroll
            for (int i = 0; i < 2; i++) {
                int m = s * 128 + wR * 32 + i * 16 + (lane >> 2);
                ph[i][0] = smP[(size_t)m * 20 + kk];
                ph[i][1] = smP[(size_t)(m + 8) * 20 + kk];
                ph[i][2] = smP[(size_t)m * 20 + kk + 4];
                ph[i][3] = smP[(size_t)(m + 8) * 20 + kk + 4];
            }
#pragma unroll
            for (int j = 0; j < 4; j++) {
                int n = s * 64 + wC * 32 + j * 8 + (lane >> 2);
                uint2 v0 = smV[(size_t)n * 20 + kk];
                uint2 v1 = smV[(size_t)n * 20 + kk + 4];
#pragma unroll
                for (int i = 0; i < 2; i++) {
                    mmah(accS[i][j], ph[i], v0.x, v1.x);
                    mmah(accE[i][j], ph[i], v0.y, v1.y);
                }
            }
        }
        __syncthreads();
        s = (s + 1 >= 3) ? 0 : s + 1;
    }
#pragma unroll
    for (int i = 0; i < 2; i++) {
        int n_lo = n0 + wR * 32 + i * 16 + (lane >> 2);
#pragma unroll
        for (int j = 0; j < 4; j++) {
            int h = h0 + wC * 32 + j * 8 + 2 * (lane & 3);
#pragma unroll
            for (int half = 0; half < 2; half++) {
                int n = n_lo + half * 8;
                float cs0 = accS[i][j][half * 2 + 0], cs1 = accS[i][j][half * 2 + 1];
                float ce0 = accE[i][j][half * 2 + 0], ce1 = accE[i][j][half * 2 + 1];
                size_t fb = ((size_t)b * Nn + n) * 512;
                g_f1[fb + (h >> 1)]       = cvtH2(cs0, cs1);
                g_f1[fb + 128 + (h >> 1)] = cvtH2(ce0, ce1);
                g_f1[fb + 256 + (h >> 1)] = cvtH2(cs0 - ce0, cs1 - ce1);
                g_f1[fb + 384 + (h >> 1)] = cvtH2(cs0 * ce0, cs1 * ce1);
            }
        }
    }
}

// ---------------- softmax (scale computed inline) ----------------
__global__ void softmax_kernel(const float* __restrict__ ew_p) {
    const int row = blockIdx.x;
    const int b   = row / Nn;
    const float sc = fmaxf(g_dsum[b] * (1.0f / ((float)Nn * (float)Mm)), 1e-4f);
    const float invsc = ew_p[0] / sc;
    const size_t base = (size_t)row * Mm;
    const int c0 = threadIdx.x * 8;
    float v[8];
    float mx = -1e30f;
#pragma unroll
    for (int q = 0; q < 2; q++) {
        float4 lv = *(const float4*)&g_L[base + c0 + q * 4];
        float4 dv = *(const float4*)&g_D[base + c0 + q * 4];
        v[q*4+0] = lv.x - dv.x * invsc; v[q*4+1] = lv.y - dv.y * invsc;
        v[q*4+2] = lv.z - dv.z * invsc; v[q*4+3] = lv.w - dv.w * invsc;
    }
#pragma unroll
    for (int t = 0; t < 8; t++) mx = fmaxf(mx, v[t]);
    __shared__ float sh[8];
    __shared__ float bc;
    int lane = threadIdx.x & 31, wid = threadIdx.x >> 5;
    float wm = warpRedMax(mx);
    if (lane == 0) sh[wid] = wm;
    __syncthreads();
    if (wid == 0) {
        float t = (lane < 8) ? sh[lane] : -1e30f;
        t = warpRedMax(t);
        if (lane == 0) bc = t;
    }
    __syncthreads();
    mx = bc;
    float sum = 0.0f;
#pragma unroll
    for (int t = 0; t < 8; t++) {
        v[t] = __expf(v[t] - mx);
        sum += v[t];
    }
    __syncthreads();
    float ws = warpRedSum(sum);
    if (lane == 0) sh[wid] = ws;
    __syncthreads();
    if (wid == 0) {
        float t = (lane < 8) ? sh[lane] : 0.0f;
        t = warpRedSum(t);
        if (lane == 0) bc = t;
    }
    __syncthreads();
    const float inv = 1.0f / bc;
    const size_t pbase = (size_t)row * 1024 + threadIdx.x * 4;
#pragma unroll
    for (int p = 0; p < 4; p++)
        g_p1[pbase + p] = cvtH2(v[2 * p] * inv, v[2 * p + 1] * inv);
}

// ---------------- launch ----------------
extern "C" void kernel_launch(void* const* d_in, const int* in_sizes, int n_in,
                              void* d_out, int out_size) {
    const float* q_fp  = (const float*)d_in[0];
    const float* v_ret = (const float*)d_in[1];
    const float* pi    = (const float*)d_in[2];
    const float* Wqs = (const float*)d_in[3];  const float* bqs = (const float*)d_in[4];
    const float* Wks = (const float*)d_in[5];  const float* bks = (const float*)d_in[6];
    const float* Wvs = (const float*)d_in[7];  const float* bvs = (const float*)d_in[8];
    const float* Wqe = (const float*)d_in[9];  const float* bqe = (const float*)d_in[10];
    const float* Wke = (const float*)d_in[11]; const float* bke = (const float*)d_in[12];
    const float* Wve = (const float*)d_in[13]; const float* bve = (const float*)d_in[14];
    const float* W1  = (const float*)d_in[15]; const float* b1  = (const float*)d_in[16];
    const float* W2  = (const float*)d_in[17]; const float* b2  = (const float*)d_in[18];
    const float* gamma = (const float*)d_in[19];
    const float* ew    = (const float*)d_in[20];
    float* out = (float*)d_out;

    uint32_t *qf1, *vr1, *w1p, *p1_, *f1, *h1;
    uint2 *qp, *kp, *vT2;
    float *q2_p, *k2_p;
    cudaGetSymbolAddress((void**)&qf1, g_qf1);
    cudaGetSymbolAddress((void**)&vr1, g_vr1);
    cudaGetSymbolAddress((void**)&w1p, g_w1p);
    cudaGetSymbolAddress((void**)&qp, g_qp);
    cudaGetSymbolAddress((void**)&kp, g_kp);
    cudaGetSymbolAddress((void**)&vT2, g_vT2);
    cudaGetSymbolAddress((void**)&p1_, g_p1);
    cudaGetSymbolAddress((void**)&f1, g_f1);
    cudaGetSymbolAddress((void**)&h1, g_h1);
    cudaGetSymbolAddress((void**)&q2_p, g_q2);
    cudaGetSymbolAddress((void**)&k2_p, g_k2);

    const int G2_SMEM    = 6144 * 4;     // 24576
    const int GEMM_SMEM  = 10240 * 4;    // 40960
    const int LOGIT_SMEM = 9216 * 4;     // 36864
    const int CTX_SMEM   = 15360 * 4;    // 61440 (3-stage)
    cudaFuncSetAttribute(gemm2_kernel,   cudaFuncAttributeMaxDynamicSharedMemorySize, G2_SMEM);
    cudaFuncSetAttribute(gemmP_kernel,   cudaFuncAttributeMaxDynamicSharedMemorySize, GEMM_SMEM);
    cudaFuncSetAttribute(logitsP_kernel, cudaFuncAttributeMaxDynamicSharedMemorySize, LOGIT_SMEM);
    cudaFuncSetAttribute(ctxP_kernel,    cudaFuncAttributeMaxDynamicSharedMemorySize, CTX_SMEM);

    uint32_t* wo[8] = {w1p, w1p+65536, w1p+131072, w1p+196608, w1p+262144, w1p+327680,
                       w1p+393216, w1p+524288};

    dim3 gp(4, (Bb * Nn) / 128);

    // launch order: OUR idx5 = gemm2_q is the profiled launch
    pack_rows_kernel<<<(Bb*Nn*DIN/2 + 255)/256, 256>>>(q_fp,  qf1, Bb*Nn*DIN/2);     // 0
    pack_rows_kernel<<<(Bb*Mm*DIN/2 + 255)/256, 256>>>(v_ret, vr1, Bb*Mm*DIN/2);     // 1
    pack_weight_kernel<<<(256*256 + 255)/256, 256>>>(Wqs, wo[0], 256, 256);          // 2
    pack_weight_kernel<<<(256*256 + 255)/256, 256>>>(Wqe, wo[3], 256, 256);          // 3
    pack_weight_kernel<<<(256*256 + 255)/256, 256>>>(Wks, wo[1], 256, 256);          // 4
    gemm2_kernel<<<gp, 256, G2_SMEM>>>(qf1, wo[0], wo[3], bqs, bqe,
                                       qp, nullptr, 256);                            // 5 <- profiled
    pack_weight_kernel<<<(256*256 + 255)/256, 256>>>(Wke, wo[4], 256, 256);
    gemm2_kernel<<<gp, 256, G2_SMEM>>>(vr1, wo[1], wo[4], bks, bke,
                                       kp, nullptr, 256);
    pack_weight_kernel<<<(256*256 + 255)/256, 256>>>(Wvs, wo[2], 256, 256);
    pack_weight_kernel<<<(256*256 + 255)/256, 256>>>(Wve, wo[5], 256, 256);
    gemm2_kernel<<<gp, 256, G2_SMEM>>>(vr1, wo[2], wo[5], bvs, bve,
                                       nullptr, vT2, 256);
    pack_weight_kernel<<<(512*256 + 255)/256, 256>>>(W1, wo[6], 512, 256);
    pack_weight_kernel<<<(128*256 + 255)/256, 256>>>(W2, wo[7], 128, 256);

    rowsumsq_kernel<<<Bb * Nn, 128>>>(qp, q2_p);
    rowsumsq_kernel<<<Bb * Mm, 128>>>(kp, k2_p);

    zero_dsum_kernel<<<1, 32>>>();
    dim3 gl(Mm / 64, Nn / 128, Bb);
    logitsP_kernel<<<gl, 256, LOGIT_SMEM>>>(pi, gamma);

    softmax_kernel<<<Bb * Nn, 256>>>(ew);

    dim3 gc(Hh / 64, Nn / 128, Bb);
    ctxP_kernel<<<gc, 256, CTX_SMEM>>>();

    dim3 gm(2, (Bb * Nn) / 128);
    gemmP_kernel<<<gm, 256, GEMM_SMEM>>>(f1, wo[6], b1, nullptr, h1, 512, 256, 1);
    gemmP_kernel<<<gm, 256, GEMM_SMEM>>>(h1, wo[7], b2, out, nullptr, 128, 256, 0);
}

// round 13
// speedup vs baseline: 2.0658x; 1.0431x over previous
#include <cuda_runtime.h>
#include <cuda_fp16.h>
#include <cstdint>

#define Bb 8
#define Nn 2048
#define Mm 2048
#define DIN 512
#define Hh 256

// ---------------- scratch (device globals; no allocs allowed) ----------------
__device__ uint32_t g_qf1[(size_t)Bb*Nn*(DIN/2)];
__device__ uint32_t g_vr1[(size_t)Bb*Mm*(DIN/2)];
__device__ uint32_t g_w1p[6*65536 + 131072 + 32768];
__device__ uint2 g_qp[(size_t)Bb*Nn*128];                 // {qsH, qeH}
__device__ uint2 g_kp[(size_t)Bb*Mm*128];                 // {ksH, keH}
__device__ uint2 g_vT2[(size_t)Bb*Hh*1024];               // {vsH, veH} [b][h][mp]
__device__ uint32_t g_SE[(size_t)Bb*Nn*Mm];               // {S_scaled fp16, E fp16}
__device__ uint32_t g_p1[(size_t)Bb*Nn*1024];
__device__ uint32_t g_f1[(size_t)Bb*Nn*512];
__device__ uint32_t g_h1[(size_t)Bb*Nn*128];
__device__ float g_q2[Bb*Nn], g_k2[Bb*Mm], g_dsum[Bb];

// ---------------- helpers ----------------
__device__ __forceinline__ uint32_t cvtH2(float f0, float f1) {
    __half h0 = __float2half(f0), h1 = __float2half(f1);
    return (uint32_t)__half_as_ushort(h0) | ((uint32_t)__half_as_ushort(h1) << 16);
}
__device__ __forceinline__ float hlo(uint32_t u) {
    return __half2float(__ushort_as_half((unsigned short)(u & 0xffff)));
}
__device__ __forceinline__ float hhi(uint32_t u) {
    return __half2float(__ushort_as_half((unsigned short)(u >> 16)));
}
__device__ __forceinline__ void mmah(float* d, const uint32_t* a, uint32_t b0, uint32_t b1) {
    asm volatile(
        "mma.sync.aligned.m16n8k16.row.col.f32.f16.f16.f32 "
        "{%0,%1,%2,%3}, {%4,%5,%6,%7}, {%8,%9}, {%0,%1,%2,%3};\n"
        : "+f"(d[0]), "+f"(d[1]), "+f"(d[2]), "+f"(d[3])
        : "r"(a[0]), "r"(a[1]), "r"(a[2]), "r"(a[3]), "r"(b0), "r"(b1));
}
__device__ __forceinline__ void cpa16(void* smem, const void* gmem) {
    uint32_t s = (uint32_t)__cvta_generic_to_shared(smem);
    asm volatile("cp.async.cg.shared.global [%0], [%1], 16;\n" :: "r"(s), "l"(gmem));
}
#define CP_COMMIT() asm volatile("cp.async.commit_group;\n")
#define CP_WAIT2()  asm volatile("cp.async.wait_group 2;\n")
#define CP_WAIT1()  asm volatile("cp.async.wait_group 1;\n")
#define CP_WAIT0()  asm volatile("cp.async.wait_group 0;\n")

__device__ __forceinline__ float warpRedSum(float v) {
#pragma unroll
    for (int o = 16; o > 0; o >>= 1) v += __shfl_xor_sync(0xffffffffu, v, o);
    return v;
}
__device__ __forceinline__ float warpRedMax(float v) {
#pragma unroll
    for (int o = 16; o > 0; o >>= 1) v = fmaxf(v, __shfl_xor_sync(0xffffffffu, v, o));
    return v;
}

// ---------------- prep kernels ----------------
__global__ void pack_rows_kernel(const float* __restrict__ src,
                                 uint32_t* __restrict__ dst, int npairs) {
    int i = blockIdx.x * 256 + threadIdx.x;
    if (i >= npairs) return;
    float2 f = ((const float2*)src)[i];
    dst[i] = cvtH2(f.x, f.y);
}
__global__ void pack_weight_kernel(const float* __restrict__ W,
                                   uint32_t* __restrict__ dst, int Kp, int Nc) {
    int i = blockIdx.x * 256 + threadIdx.x;
    if (i >= Kp * Nc) return;
    int n = i / Kp, kp = i - n * Kp;
    dst[i] = cvtH2(W[(size_t)(2 * kp) * Nc + n], W[(size_t)(2 * kp + 1) * Nc + n]);
}
__global__ void rowsumsq_kernel(const uint2* __restrict__ P2, float* __restrict__ dst) {
    const int row = blockIdx.x, tid = threadIdx.x;
    uint2 q = P2[(size_t)row * 128 + tid];
    float v0 = hlo(q.y), v1 = hhi(q.y);
    float s = v0 * v0 + v1 * v1;
    __shared__ float sh[4];
    int lane = tid & 31, wid = tid >> 5;
    float w = warpRedSum(s);
    if (lane == 0) sh[wid] = w;
    __syncthreads();
    if (wid == 0) {
        float t = (lane < 4) ? sh[lane] : 0.0f;
        t = warpRedSum(t);
        if (lane == 0) dst[row] = t;
    }
}
__global__ void zero_dsum_kernel() { if (threadIdx.x < Bb) g_dsum[threadIdx.x] = 0.0f; }

// =============================================================================
// Dual-output projection GEMM (fp16 1-product). R12 unchanged.
// =============================================================================
__global__ __launch_bounds__(256, 2) void gemm2_kernel(
    const uint32_t* __restrict__ a1,
    const uint32_t* __restrict__ wa, const uint32_t* __restrict__ wb,
    const float* __restrict__ biasA, const float* __restrict__ biasB,
    uint2* __restrict__ outQK, uint2* __restrict__ outT,
    int Kp)
{
    extern __shared__ uint32_t smu[];
    uint32_t* smA  = smu;            // [2][128][12]
    uint32_t* smB1 = smu + 3072;     // [2][64][12]
    uint32_t* smB2 = smu + 4608;     // [2][64][12]

    const int row0 = blockIdx.y * 128;
    const int col0 = blockIdx.x * 64;
    const int tid  = threadIdx.x;
    const int lane = tid & 31, warp = tid >> 5;
    const int wR = warp >> 1, wC = warp & 1;

    float acc1[2][4][4] = {}, acc2[2][4][4] = {};
    const int nk = Kp / 8;

    const int ar = tid >> 1, ac4 = (tid & 1) * 4;
    const int bt = tid & 127;
    const int br = bt >> 1, bc4 = (bt & 1) * 4;
    uint32_t* smBsel = (tid < 128) ? smB1 : smB2;
    const uint32_t* wsel = (tid < 128) ? wa : wb;

    {
        cpa16(&smA[(size_t)ar * 12 + ac4], a1 + (size_t)(row0 + ar) * Kp + ac4);
        cpa16(&smBsel[(size_t)br * 12 + bc4], wsel + (size_t)(col0 + br) * Kp + bc4);
        CP_COMMIT();
    }

    for (int kt = 0; kt < nk; kt++) {
        const int s = kt & 1;
        if (kt + 1 < nk) {
            const int sn = s ^ 1;
            const int k0 = (kt + 1) * 8;
            cpa16(&smA[(size_t)(sn * 128 + ar) * 12 + ac4],
                  a1 + (size_t)(row0 + ar) * Kp + k0 + ac4);
            cpa16(&smBsel[(size_t)(sn * 64 + br) * 12 + bc4],
                  wsel + (size_t)(col0 + br) * Kp + k0 + bc4);
            CP_COMMIT();
            CP_WAIT1();
        } else {
            CP_WAIT0();
        }
        __syncthreads();

        const int kk = lane & 3;
        uint32_t ah[2][4];
#pragma unroll
        for (int i = 0; i < 2; i++) {
            int m = s * 128 + wR * 32 + i * 16 + (lane >> 2);
            ah[i][0] = smA[(size_t)m * 12 + kk];
            ah[i][1] = smA[(size_t)(m + 8) * 12 + kk];
            ah[i][2] = smA[(size_t)m * 12 + kk + 4];
            ah[i][3] = smA[(size_t)(m + 8) * 12 + kk + 4];
        }
#pragma unroll
        for (int j = 0; j < 4; j++) {
            int n = s * 64 + wC * 32 + j * 8 + (lane >> 2);
            uint32_t b10 = smB1[(size_t)n * 12 + kk], b11 = smB1[(size_t)n * 12 + kk + 4];
            uint32_t b20 = smB2[(size_t)n * 12 + kk], b21 = smB2[(size_t)n * 12 + kk + 4];
#pragma unroll
            for (int i = 0; i < 2; i++) {
                mmah(acc1[i][j], ah[i], b10, b11);
                mmah(acc2[i][j], ah[i], b20, b21);
            }
        }
        __syncthreads();
    }

#pragma unroll
    for (int i = 0; i < 2; i++) {
        int r = row0 + wR * 32 + i * 16 + (lane >> 2);
#pragma unroll
        for (int j = 0; j < 4; j++) {
            int c = col0 + wC * 32 + j * 8 + 2 * (lane & 3);
            float ba0 = biasA[c], ba1 = biasA[c + 1];
            float bb0 = biasB[c], bb1 = biasB[c + 1];
#pragma unroll
            for (int half = 0; half < 2; half++) {
                int rr = r + half * 8;
                float va0 = acc1[i][j][half * 2 + 0] + ba0;
                float va1 = acc1[i][j][half * 2 + 1] + ba1;
                float vb0 = acc2[i][j][half * 2 + 0] + bb0;
                float vb1 = acc2[i][j][half * 2 + 1] + bb1;
                if (outQK) {
                    outQK[(size_t)rr * 128 + (c >> 1)] =
                        make_uint2(cvtH2(va0, va1), cvtH2(vb0, vb1));
                } else {
                    float pva0 = __shfl_xor_sync(0xffffffffu, va0, 4);
                    float pva1 = __shfl_xor_sync(0xffffffffu, va1, 4);
                    float pvb0 = __shfl_xor_sync(0xffffffffu, vb0, 4);
                    float pvb1 = __shfl_xor_sync(0xffffffffu, vb1, 4);
                    if (((lane >> 2) & 1) == 0) {
                        int bb = rr >> 11;
                        int mp = (rr & 2047) >> 1;
                        size_t base = ((size_t)bb * Hh + c) * 1024 + mp;
                        outT[base]        = make_uint2(cvtH2(va0, pva0), cvtH2(vb0, pvb0));
                        outT[base + 1024] = make_uint2(cvtH2(va1, pva1), cvtH2(vb1, pvb1));
                    }
                }
            }
        }
    }
}

// =============================================================================
// Single-output GEMM for MLP (fp16 1-product). R12 unchanged.
// =============================================================================
__global__ __launch_bounds__(256, 2) void gemmP_kernel(
    const uint32_t* __restrict__ a1, const uint32_t* __restrict__ w1p,
    const float* __restrict__ bias,
    float* __restrict__ outF, uint32_t* __restrict__ outP,
    int Kp, int Nc, int act)
{
    extern __shared__ uint32_t smu[];
    uint32_t* smA = smu;             // [2][128][20]
    uint32_t* smB = smu + 5120;      // [2][128][20]

    const int row0 = blockIdx.y * 128;
    const int col0 = blockIdx.x * 128;
    const int tid  = threadIdx.x;
    const int lane = tid & 31, warp = tid >> 5;
    const int wR = warp >> 1, wC = warp & 1;

    float acc[2][8][4] = {};
    const int nk = Kp / 16;

    {
#pragma unroll
        for (int it = 0; it < 2; it++) {
            int i = tid + it * 256;
            int r = i >> 2, c4 = (i & 3) * 4;
            cpa16(&smA[(size_t)r * 20 + c4], a1 + (size_t)(row0 + r) * Kp + c4);
            cpa16(&smB[(size_t)r * 20 + c4], w1p + (size_t)(col0 + r) * Kp + c4);
        }
        CP_COMMIT();
    }

    for (int kt = 0; kt < nk; kt++) {
        const int s = kt & 1;
        if (kt + 1 < nk) {
            const int sn = s ^ 1;
            const int k0 = (kt + 1) * 16;
#pragma unroll
            for (int it = 0; it < 2; it++) {
                int i = tid + it * 256;
                int r = i >> 2, c4 = (i & 3) * 4;
                cpa16(&smA[(size_t)(sn * 128 + r) * 20 + c4],
                      a1 + (size_t)(row0 + r) * Kp + k0 + c4);
                cpa16(&smB[(size_t)(sn * 128 + r) * 20 + c4],
                      w1p + (size_t)(col0 + r) * Kp + k0 + c4);
            }
            CP_COMMIT();
            CP_WAIT1();
        } else {
            CP_WAIT0();
        }
        __syncthreads();
#pragma unroll
        for (int ks = 0; ks < 2; ks++) {
            const int kk = ks * 8 + (lane & 3);
            uint32_t ah[2][4];
#pragma unroll
            for (int i = 0; i < 2; i++) {
                int m = s * 128 + wR * 32 + i * 16 + (lane >> 2);
                ah[i][0] = smA[(size_t)m * 20 + kk];
                ah[i][1] = smA[(size_t)(m + 8) * 20 + kk];
                ah[i][2] = smA[(size_t)m * 20 + kk + 4];
                ah[i][3] = smA[(size_t)(m + 8) * 20 + kk + 4];
            }
#pragma unroll
            for (int j = 0; j < 8; j++) {
                int n = s * 128 + wC * 64 + j * 8 + (lane >> 2);
                uint32_t b0 = smB[(size_t)n * 20 + kk];
                uint32_t b1 = smB[(size_t)n * 20 + kk + 4];
#pragma unroll
                for (int i = 0; i < 2; i++)
                    mmah(acc[i][j], ah[i], b0, b1);
            }
        }
        __syncthreads();
    }
#pragma unroll
    for (int i = 0; i < 2; i++) {
        int r = row0 + wR * 32 + i * 16 + (lane >> 2);
#pragma unroll
        for (int j = 0; j < 8; j++) {
            int c = col0 + wC * 64 + j * 8 + 2 * (lane & 3);
            float b0 = bias[c], b1 = bias[c + 1];
            float v0 = acc[i][j][0] + b0, v1 = acc[i][j][1] + b1;
            float v2 = acc[i][j][2] + b0, v3 = acc[i][j][3] + b1;
            if (act) {
                v0 = v0 / (1.0f + __expf(-v0));
                v1 = v1 / (1.0f + __expf(-v1));
                v2 = v2 / (1.0f + __expf(-v2));
                v3 = v3 / (1.0f + __expf(-v3));
            }
            if (outP) {
                outP[(size_t)r * (Nc >> 1) + (c >> 1)]       = cvtH2(v0, v1);
                outP[(size_t)(r + 8) * (Nc >> 1) + (c >> 1)] = cvtH2(v2, v3);
            } else {
                *(float2*)&outF[(size_t)r * Nc + c]       = make_float2(v0, v1);
                *(float2*)&outF[(size_t)(r + 8) * Nc + c] = make_float2(v2, v3);
            }
        }
    }
}

// =============================================================================
// Logits: dual fp16 1-product NT GEMM -> packed {S_scaled, E} fp16 + dist-sum.
// =============================================================================
__global__ __launch_bounds__(256, 2) void logitsP_kernel()
{
    extern __shared__ uint32_t smu[];
    uint2* smQ = (uint2*)smu;              // [2][128][12]
    uint2* smK = (uint2*)(smu + 6144);     // [2][64][12]

    const int b  = blockIdx.z;
    const int n0 = blockIdx.y * 128;
    const int m0 = blockIdx.x * 64;
    const int tid = threadIdx.x;
    const int lane = tid & 31, warp = tid >> 5;
    const int wR = warp >> 1, wC = warp & 1;

    const uint2* q2p = g_qp + (size_t)(b * Nn + n0) * 128;
    const uint2* k2p = g_kp + (size_t)(b * Mm + m0) * 128;

    float accS[2][4][4] = {}, accE[2][4][4] = {};
    const int nk = 16;

    {
#pragma unroll
        for (int it = 0; it < 2; it++) {
            int i = tid + it * 256;
            int r = i >> 2, c2 = (i & 3) * 2;
            cpa16(&smQ[(size_t)r * 12 + c2], q2p + (size_t)r * 128 + c2);
        }
        {
            int r = tid >> 2, c2 = (tid & 3) * 2;
            cpa16(&smK[(size_t)r * 12 + c2], k2p + (size_t)r * 128 + c2);
        }
        CP_COMMIT();
    }

    for (int kt = 0; kt < nk; kt++) {
        const int s = kt & 1;
        if (kt + 1 < nk) {
            const int sn = s ^ 1;
            const int k0 = (kt + 1) * 8;
#pragma unroll
            for (int it = 0; it < 2; it++) {
                int i = tid + it * 256;
                int r = i >> 2, c2 = (i & 3) * 2;
                cpa16(&smQ[(size_t)(sn * 128 + r) * 12 + c2],
                      q2p + (size_t)r * 128 + k0 + c2);
            }
            {
                int r = tid >> 2, c2 = (tid & 3) * 2;
                cpa16(&smK[(size_t)(sn * 64 + r) * 12 + c2],
                      k2p + (size_t)r * 128 + k0 + c2);
            }
            CP_COMMIT();
            CP_WAIT1();
        } else {
            CP_WAIT0();
        }
        __syncthreads();

        const int kk = lane & 3;
        uint32_t ash[2][4], aeh[2][4];
#pragma unroll
        for (int i = 0; i < 2; i++) {
            int m = s * 128 + wR * 32 + i * 16 + (lane >> 2);
            uint2 p0 = smQ[(size_t)m * 12 + kk];
            uint2 p1 = smQ[(size_t)(m + 8) * 12 + kk];
            uint2 p2 = smQ[(size_t)m * 12 + kk + 4];
            uint2 p3 = smQ[(size_t)(m + 8) * 12 + kk + 4];
            ash[i][0] = p0.x; ash[i][1] = p1.x; ash[i][2] = p2.x; ash[i][3] = p3.x;
            aeh[i][0] = p0.y; aeh[i][1] = p1.y; aeh[i][2] = p2.y; aeh[i][3] = p3.y;
        }
#pragma unroll
        for (int j = 0; j < 4; j++) {
            int n = s * 64 + wC * 32 + j * 8 + (lane >> 2);
            uint2 k0v = smK[(size_t)n * 12 + kk];
            uint2 k1v = smK[(size_t)n * 12 + kk + 4];
#pragma unroll
            for (int i = 0; i < 2; i++) {
                mmah(accS[i][j], ash[i], k0v.x, k1v.x);
                mmah(accE[i][j], aeh[i], k0v.y, k1v.y);
            }
        }
        __syncthreads();
    }

    float sumd = 0.0f;
#pragma unroll
    for (int i = 0; i < 2; i++) {
        int n_lo = n0 + wR * 32 + i * 16 + (lane >> 2);
        float q2a = g_q2[b * Nn + n_lo];
        float q2b = g_q2[b * Nn + n_lo + 8];
#pragma unroll
        for (int j = 0; j < 4; j++) {
            int m = m0 + wC * 32 + j * 8 + 2 * (lane & 3);
            float k2a = g_k2[b * Mm + m], k2b = g_k2[b * Mm + m + 1];
            size_t base0 = ((size_t)b * Nn + n_lo) * Mm + m;
            float e0 = accE[i][j][0], e1 = accE[i][j][1];
            sumd += sqrtf(fmaxf(q2a + k2a - 2.0f * e0, 1e-12f))
                  + sqrtf(fmaxf(q2a + k2b - 2.0f * e1, 1e-12f));
            *(uint2*)&g_SE[base0] = make_uint2(cvtH2(accS[i][j][0] * 0.0625f, e0),
                                               cvtH2(accS[i][j][1] * 0.0625f, e1));
            size_t base1 = ((size_t)b * Nn + n_lo + 8) * Mm + m;
            float e2 = accE[i][j][2], e3 = accE[i][j][3];
            sumd += sqrtf(fmaxf(q2b + k2a - 2.0f * e2, 1e-12f))
                  + sqrtf(fmaxf(q2b + k2b - 2.0f * e3, 1e-12f));
            *(uint2*)&g_SE[base1] = make_uint2(cvtH2(accS[i][j][2] * 0.0625f, e2),
                                               cvtH2(accS[i][j][3] * 0.0625f, e3));
        }
    }
    float* red = (float*)smu;
    red[tid] = sumd;
    __syncthreads();
    for (int sred = 128; sred > 0; sred >>= 1) {
        if (tid < sred) red[tid] += red[tid + sred];
        __syncthreads();
    }
    if (tid == 0) atomicAdd(&g_dsum[b], red[0]);
}

// =============================================================================
// Ctx: dual fp16 1-product NN GEMM, 3-stage cp.async. R12 unchanged.
// =============================================================================
__global__ __launch_bounds__(256, 2) void ctxP_kernel()
{
    extern __shared__ uint32_t smu[];
    uint32_t* smP = smu;                   // [3][128][20]
    uint2*    smV = (uint2*)(smu + 7680);  // [3][64][20]

    const int b  = blockIdx.z;
    const int n0 = blockIdx.y * 128;
    const int h0 = blockIdx.x * 64;
    const int tid = threadIdx.x;
    const int lane = tid & 31, warp = tid >> 5;
    const int wR = warp >> 1, wC = warp & 1;

    const uint32_t* p1 = g_p1 + (size_t)(b * Nn + n0) * 1024;
    const uint2* v2 = g_vT2 + ((size_t)b * Hh + h0) * 1024;

    float accS[2][4][4] = {}, accE[2][4][4] = {};
    const int nk = 64;

#pragma unroll
    for (int st = 0; st < 2; st++) {
        const int mp0 = st * 16;
#pragma unroll
        for (int it = 0; it < 2; it++) {
            int i = tid + it * 256;
            int r = i >> 2, c4 = (i & 3) * 4;
            cpa16(&smP[(size_t)(st * 128 + r) * 20 + c4], p1 + (size_t)r * 1024 + mp0 + c4);
            int rv = i >> 3, c2 = (i & 7) * 2;
            cpa16(&smV[(size_t)(st * 64 + rv) * 20 + c2], v2 + (size_t)rv * 1024 + mp0 + c2);
        }
        CP_COMMIT();
    }

    int s = 0;
    for (int kt = 0; kt < nk; kt++) {
        if (kt + 2 < nk) {
            const int sn = (s + 2 >= 3) ? s - 1 : s + 2;
            const int mp0 = (kt + 2) * 16;
#pragma unroll
            for (int it = 0; it < 2; it++) {
                int i = tid + it * 256;
                int r = i >> 2, c4 = (i & 3) * 4;
                cpa16(&smP[(size_t)(sn * 128 + r) * 20 + c4],
                      p1 + (size_t)r * 1024 + mp0 + c4);
                int rv = i >> 3, c2 = (i & 7) * 2;
                cpa16(&smV[(size_t)(sn * 64 + rv) * 20 + c2],
                      v2 + (size_t)rv * 1024 + mp0 + c2);
            }
            CP_COMMIT();
            CP_WAIT2();
        } else {
            CP_WAIT0();
        }
        __syncthreads();
#pragma unroll
        for (int ks = 0; ks < 2; ks++) {
            const int kk = ks * 8 + (lane & 3);
            uint32_t ph[2][4];
#pragma unroll
            for (int i = 0; i < 2; i++) {
                int m = s * 128 + wR * 32 + i * 16 + (lane >> 2);
                ph[i][0] = smP[(size_t)m * 20 + kk];
                ph[i][1] = smP[(size_t)(m + 8) * 20 + kk];
                ph[i][2] = smP[(size_t)m * 20 + kk + 4];
                ph[i][3] = smP[(size_t)(m + 8) * 20 + kk + 4];
            }
#pragma unroll
            for (int j = 0; j < 4; j++) {
                int n = s * 64 + wC * 32 + j * 8 + (lane >> 2);
                uint2 v0 = smV[(size_t)n * 20 + kk];
                uint2 v1 = smV[(size_t)n * 20 + kk + 4];
#pragma unroll
                for (int i = 0; i < 2; i++) {
                    mmah(accS[i][j], ph[i], v0.x, v1.x);
                    mmah(accE[i][j], ph[i], v0.y, v1.y);
                }
            }
        }
        __syncthreads();
        s = (s + 1 >= 3) ? 0 : s + 1;
    }
#pragma unroll
    for (int i = 0; i < 2; i++) {
        int n_lo = n0 + wR * 32 + i * 16 + (lane >> 2);
#pragma unroll
        for (int j = 0; j < 4; j++) {
            int h = h0 + wC * 32 + j * 8 + 2 * (lane & 3);
#pragma unroll
            for (int half = 0; half < 2; half++) {
                int n = n_lo + half * 8;
                float cs0 = accS[i][j][half * 2 + 0], cs1 = accS[i][j][half * 2 + 1];
                float ce0 = accE[i][j][half * 2 + 0], ce1 = accE[i][j][half * 2 + 1];
                size_t fb = ((size_t)b * Nn + n) * 512;
                g_f1[fb + (h >> 1)]       = cvtH2(cs0, cs1);
                g_f1[fb + 128 + (h >> 1)] = cvtH2(ce0, ce1);
                g_f1[fb + 256 + (h >> 1)] = cvtH2(cs0 - ce0, cs1 - ce1);
                g_f1[fb + 384 + (h >> 1)] = cvtH2(cs0 * ce0, cs1 * ce1);
            }
        }
    }
}

// ---------------- softmax: rebuild logits from packed {S,E} + pi ----------------
__global__ void softmax_kernel(const float* __restrict__ pi_star,
                               const float* __restrict__ gamma_p,
                               const float* __restrict__ ew_p) {
    const int row = blockIdx.x;
    const int b   = row / Nn;
    const float sc = fmaxf(g_dsum[b] * (1.0f / ((float)Nn * (float)Mm)), 1e-4f);
    const float invsc = ew_p[0] / sc;
    const float g = gamma_p[0];
    const float q2v = g_q2[row];
    const size_t base = (size_t)row * Mm;
    const int c0 = threadIdx.x * 8;
    float v[8];
    float mx = -1e30f;
#pragma unroll
    for (int q = 0; q < 2; q++) {
        uint4 se = *(const uint4*)&g_SE[base + c0 + q * 4];
        float4 piv = *(const float4*)&pi_star[base + c0 + q * 4];
        float4 k2v = *(const float4*)&g_k2[b * Mm + c0 + q * 4];
        uint32_t ses[4] = {se.x, se.y, se.z, se.w};
        float pis[4] = {piv.x, piv.y, piv.z, piv.w};
        float k2s[4] = {k2v.x, k2v.y, k2v.z, k2v.w};
#pragma unroll
        for (int t = 0; t < 4; t++) {
            float S = hlo(ses[t]), E = hhi(ses[t]);
            float d = sqrtf(fmaxf(q2v + k2s[t] - 2.0f * E, 1e-12f));
            v[q * 4 + t] = S + g * __logf(fmaxf(pis[t], 1e-9f)) - d * invsc;
        }
    }
#pragma unroll
    for (int t = 0; t < 8; t++) mx = fmaxf(mx, v[t]);
    __shared__ float sh[8];
    __shared__ float bc;
    int lane = threadIdx.x & 31, wid = threadIdx.x >> 5;
    float wm = warpRedMax(mx);
    if (lane == 0) sh[wid] = wm;
    __syncthreads();
    if (wid == 0) {
        float t = (lane < 8) ? sh[lane] : -1e30f;
        t = warpRedMax(t);
        if (lane == 0) bc = t;
    }
    __syncthreads();
    mx = bc;
    float sum = 0.0f;
#pragma unroll
    for (int t = 0; t < 8; t++) {
        v[t] = __expf(v[t] - mx);
        sum += v[t];
    }
    __syncthreads();
    float ws = warpRedSum(sum);
    if (lane == 0) sh[wid] = ws;
    __syncthreads();
    if (wid == 0) {
        float t = (lane < 8) ? sh[lane] : 0.0f;
        t = warpRedSum(t);
        if (lane == 0) bc = t;
    }
    __syncthreads();
    const float inv = 1.0f / bc;
    const size_t pbase = (size_t)row * 1024 + threadIdx.x * 4;
#pragma unroll
    for (int p = 0; p < 4; p++)
        g_p1[pbase + p] = cvtH2(v[2 * p] * inv, v[2 * p + 1] * inv);
}

// ---------------- launch ----------------
extern "C" void kernel_launch(void* const* d_in, const int* in_sizes, int n_in,
                              void* d_out, int out_size) {
    const float* q_fp  = (const float*)d_in[0];
    const float* v_ret = (const float*)d_in[1];
    const float* pi    = (const float*)d_in[2];
    const float* Wqs = (const float*)d_in[3];  const float* bqs = (const float*)d_in[4];
    const float* Wks = (const float*)d_in[5];  const float* bks = (const float*)d_in[6];
    const float* Wvs = (const float*)d_in[7];  const float* bvs = (const float*)d_in[8];
    const float* Wqe = (const float*)d_in[9];  const float* bqe = (const float*)d_in[10];
    const float* Wke = (const float*)d_in[11]; const float* bke = (const float*)d_in[12];
    const float* Wve = (const float*)d_in[13]; const float* bve = (const float*)d_in[14];
    const float* W1  = (const float*)d_in[15]; const float* b1  = (const float*)d_in[16];
    const float* W2  = (const float*)d_in[17]; const float* b2  = (const float*)d_in[18];
    const float* gamma = (const float*)d_in[19];
    const float* ew    = (const float*)d_in[20];
    float* out = (float*)d_out;

    uint32_t *qf1, *vr1, *w1p, *f1, *h1;
    uint2 *qp, *kp, *vT2;
    float *q2_p, *k2_p;
    cudaGetSymbolAddress((void**)&qf1, g_qf1);
    cudaGetSymbolAddress((void**)&vr1, g_vr1);
    cudaGetSymbolAddress((void**)&w1p, g_w1p);
    cudaGetSymbolAddress((void**)&qp, g_qp);
    cudaGetSymbolAddress((void**)&kp, g_kp);
    cudaGetSymbolAddress((void**)&vT2, g_vT2);
    cudaGetSymbolAddress((void**)&f1, g_f1);
    cudaGetSymbolAddress((void**)&h1, g_h1);
    cudaGetSymbolAddress((void**)&q2_p, g_q2);
    cudaGetSymbolAddress((void**)&k2_p, g_k2);

    const int G2_SMEM    = 6144 * 4;
    const int GEMM_SMEM  = 10240 * 4;
    const int LOGIT_SMEM = 9216 * 4;
    const int CTX_SMEM   = 15360 * 4;
    cudaFuncSetAttribute(gemm2_kernel,   cudaFuncAttributeMaxDynamicSharedMemorySize, G2_SMEM);
    cudaFuncSetAttribute(gemmP_kernel,   cudaFuncAttributeMaxDynamicSharedMemorySize, GEMM_SMEM);
    cudaFuncSetAttribute(logitsP_kernel, cudaFuncAttributeMaxDynamicSharedMemorySize, LOGIT_SMEM);
    cudaFuncSetAttribute(ctxP_kernel,    cudaFuncAttributeMaxDynamicSharedMemorySize, CTX_SMEM);

    uint32_t* wo[8] = {w1p, w1p+65536, w1p+131072, w1p+196608, w1p+262144, w1p+327680,
                       w1p+393216, w1p+524288};

    dim3 gp(4, (Bb * Nn) / 128);

    pack_rows_kernel<<<(Bb*Nn*DIN/2 + 255)/256, 256>>>(q_fp,  qf1, Bb*Nn*DIN/2);
    pack_rows_kernel<<<(Bb*Mm*DIN/2 + 255)/256, 256>>>(v_ret, vr1, Bb*Mm*DIN/2);
    pack_weight_kernel<<<(256*256 + 255)/256, 256>>>(Wqs, wo[0], 256, 256);
    pack_weight_kernel<<<(256*256 + 255)/256, 256>>>(Wqe, wo[3], 256, 256);
    gemm2_kernel<<<gp, 256, G2_SMEM>>>(qf1, wo[0], wo[3], bqs, bqe, qp, nullptr, 256);
    pack_weight_kernel<<<(256*256 + 255)/256, 256>>>(Wks, wo[1], 256, 256);
    pack_weight_kernel<<<(256*256 + 255)/256, 256>>>(Wke, wo[4], 256, 256);
    gemm2_kernel<<<gp, 256, G2_SMEM>>>(vr1, wo[1], wo[4], bks, bke, kp, nullptr, 256);
    pack_weight_kernel<<<(256*256 + 255)/256, 256>>>(Wvs, wo[2], 256, 256);
    pack_weight_kernel<<<(256*256 + 255)/256, 256>>>(Wve, wo[5], 256, 256);
    gemm2_kernel<<<gp, 256, G2_SMEM>>>(vr1, wo[2], wo[5], bvs, bve, nullptr, vT2, 256);
    pack_weight_kernel<<<(512*256 + 255)/256, 256>>>(W1, wo[6], 512, 256);
    pack_weight_kernel<<<(128*256 + 255)/256, 256>>>(W2, wo[7], 128, 256);

    rowsumsq_kernel<<<Bb * Nn, 128>>>(qp, q2_p);
    rowsumsq_kernel<<<Bb * Mm, 128>>>(kp, k2_p);

    zero_dsum_kernel<<<1, 32>>>();
    dim3 gl(Mm / 64, Nn / 128, Bb);
    logitsP_kernel<<<gl, 256, LOGIT_SMEM>>>();

    softmax_kernel<<<Bb * Nn, 256>>>(pi, gamma, ew);

    dim3 gc(Hh / 64, Nn / 128, Bb);
    ctxP_kernel<<<gc, 256, CTX_SMEM>>>();

    dim3 gm(2, (Bb * Nn) / 128);
    gemmP_kernel<<<gm, 256, GEMM_SMEM>>>(f1, wo[6], b1, nullptr, h1, 512, 256, 1);
    gemmP_kernel<<<gm, 256, GEMM_SMEM>>>(h1, wo[7], b2, out, nullptr, 128, 256, 0);
}

// round 14
// speedup vs baseline: 2.1041x; 1.0185x over previous
#include <cuda_runtime.h>
#include <cuda_fp16.h>
#include <cstdint>

#define Bb 8
#define Nn 2048
#define Mm 2048
#define DIN 512
#define Hh 256

// ---------------- scratch (device globals; no allocs allowed) ----------------
__device__ uint32_t g_qf1[(size_t)Bb*Nn*(DIN/2)];
__device__ uint32_t g_vr1[(size_t)Bb*Mm*(DIN/2)];
__device__ uint32_t g_w1p[6*65536 + 131072 + 32768];
__device__ uint2 g_qp[(size_t)Bb*Nn*128];                 // {qsH, qeH}
__device__ uint2 g_kp[(size_t)Bb*Mm*128];                 // {ksH, keH}
__device__ uint2 g_vT2[(size_t)Bb*Hh*1024];               // {vsH, veH} [b][h][mp]
__device__ uint32_t g_SE[(size_t)Bb*Nn*Mm];               // {S_scaled fp16, E fp16}
__device__ uint32_t g_p1[(size_t)Bb*Nn*1024];
__device__ uint32_t g_f1[(size_t)Bb*Nn*512];
__device__ uint32_t g_h1[(size_t)Bb*Nn*128];
__device__ float g_q2[Bb*Nn], g_k2[Bb*Mm], g_dsum[Bb];

// ---------------- helpers ----------------
__device__ __forceinline__ uint32_t cvtH2(float f0, float f1) {
    __half h0 = __float2half(f0), h1 = __float2half(f1);
    return (uint32_t)__half_as_ushort(h0) | ((uint32_t)__half_as_ushort(h1) << 16);
}
__device__ __forceinline__ float hlo(uint32_t u) {
    return __half2float(__ushort_as_half((unsigned short)(u & 0xffff)));
}
__device__ __forceinline__ float hhi(uint32_t u) {
    return __half2float(__ushort_as_half((unsigned short)(u >> 16)));
}
__device__ __forceinline__ void mmah(float* d, const uint32_t* a, uint32_t b0, uint32_t b1) {
    asm volatile(
        "mma.sync.aligned.m16n8k16.row.col.f32.f16.f16.f32 "
        "{%0,%1,%2,%3}, {%4,%5,%6,%7}, {%8,%9}, {%0,%1,%2,%3};\n"
        : "+f"(d[0]), "+f"(d[1]), "+f"(d[2]), "+f"(d[3])
        : "r"(a[0]), "r"(a[1]), "r"(a[2]), "r"(a[3]), "r"(b0), "r"(b1));
}
__device__ __forceinline__ void cpa16(void* smem, const void* gmem) {
    uint32_t s = (uint32_t)__cvta_generic_to_shared(smem);
    asm volatile("cp.async.cg.shared.global [%0], [%1], 16;\n" :: "r"(s), "l"(gmem));
}
#define CP_COMMIT() asm volatile("cp.async.commit_group;\n")
#define CP_WAIT2()  asm volatile("cp.async.wait_group 2;\n")
#define CP_WAIT1()  asm volatile("cp.async.wait_group 1;\n")
#define CP_WAIT0()  asm volatile("cp.async.wait_group 0;\n")

__device__ __forceinline__ float warpRedSum(float v) {
#pragma unroll
    for (int o = 16; o > 0; o >>= 1) v += __shfl_xor_sync(0xffffffffu, v, o);
    return v;
}
__device__ __forceinline__ float warpRedMax(float v) {
#pragma unroll
    for (int o = 16; o > 0; o >>= 1) v = fmaxf(v, __shfl_xor_sync(0xffffffffu, v, o));
    return v;
}

// ---------------- merged prep kernels ----------------
// both input tensors in one launch (grid.y selects)
__global__ void pack_rows_kernel(const float* __restrict__ srcA,
                                 const float* __restrict__ srcB,
                                 uint32_t* __restrict__ dstA,
                                 uint32_t* __restrict__ dstB, int npairs) {
    int i = blockIdx.x * 256 + threadIdx.x;
    if (i >= npairs) return;
    const float* src = blockIdx.y ? srcB : srcA;
    uint32_t* dst = blockIdx.y ? dstB : dstA;
    float2 f = ((const float2*)src)[i];
    dst[i] = cvtH2(f.x, f.y);
}
// all 8 weights in one launch; dst index == global index (slots contiguous)
__global__ void pack_all_weights_kernel(
    const float* __restrict__ W0, const float* __restrict__ W1_,
    const float* __restrict__ W2_, const float* __restrict__ W3,
    const float* __restrict__ W4, const float* __restrict__ W5,
    const float* __restrict__ W6, const float* __restrict__ W7,
    uint32_t* __restrict__ dst) {
    int i = blockIdx.x * 256 + threadIdx.x;
    if (i >= 557056) return;
    const float* W;
    int n, kp;
    if (i < 393216) {             // 6 x (256 n x 256 kp)
        const float* Ws[6] = {W0, W1_, W2_, W3, W4, W5};
        W = Ws[i >> 16];
        int li = i & 65535;
        n = li >> 8; kp = li & 255;
    } else if (i < 524288) {      // W1: 256 n x 512 kp
        W = W6;
        int li = i - 393216;
        n = li >> 9; kp = li & 511;
    } else {                      // W2: 256 n x 128 kp
        W = W7;
        int li = i - 524288;
        n = li >> 7; kp = li & 127;
    }
    dst[i] = cvtH2(W[(size_t)(2 * kp) * 256 + n], W[(size_t)(2 * kp + 1) * 256 + n]);
}
// q and k sums in one launch (grid.y selects); also zeroes dsum
__global__ void rowsumsq_kernel(const uint2* __restrict__ QP, const uint2* __restrict__ KP,
                                float* __restrict__ q2, float* __restrict__ k2) {
    const int row = blockIdx.x, tid = threadIdx.x;
    if (blockIdx.x == 0 && blockIdx.y == 0 && tid < Bb) g_dsum[tid] = 0.0f;
    const uint2* P2 = blockIdx.y ? KP : QP;
    float* dst = blockIdx.y ? k2 : q2;
    uint2 q = P2[(size_t)row * 128 + tid];
    float v0 = hlo(q.y), v1 = hhi(q.y);
    float s = v0 * v0 + v1 * v1;
    __shared__ float sh[4];
    int lane = tid & 31, wid = tid >> 5;
    float w = warpRedSum(s);
    if (lane == 0) sh[wid] = w;
    __syncthreads();
    if (wid == 0) {
        float t = (lane < 4) ? sh[lane] : 0.0f;
        t = warpRedSum(t);
        if (lane == 0) dst[row] = t;
    }
}

// =============================================================================
// Dual-output projection GEMM (fp16 1-product). R13 unchanged.
// =============================================================================
__global__ __launch_bounds__(256, 2) void gemm2_kernel(
    const uint32_t* __restrict__ a1,
    const uint32_t* __restrict__ wa, const uint32_t* __restrict__ wb,
    const float* __restrict__ biasA, const float* __restrict__ biasB,
    uint2* __restrict__ outQK, uint2* __restrict__ outT,
    int Kp)
{
    extern __shared__ uint32_t smu[];
    uint32_t* smA  = smu;            // [2][128][12]
    uint32_t* smB1 = smu + 3072;     // [2][64][12]
    uint32_t* smB2 = smu + 4608;     // [2][64][12]

    const int row0 = blockIdx.y * 128;
    const int col0 = blockIdx.x * 64;
    const int tid  = threadIdx.x;
    const int lane = tid & 31, warp = tid >> 5;
    const int wR = warp >> 1, wC = warp & 1;

    float acc1[2][4][4] = {}, acc2[2][4][4] = {};
    const int nk = Kp / 8;

    const int ar = tid >> 1, ac4 = (tid & 1) * 4;
    const int bt = tid & 127;
    const int br = bt >> 1, bc4 = (bt & 1) * 4;
    uint32_t* smBsel = (tid < 128) ? smB1 : smB2;
    const uint32_t* wsel = (tid < 128) ? wa : wb;

    {
        cpa16(&smA[(size_t)ar * 12 + ac4], a1 + (size_t)(row0 + ar) * Kp + ac4);
        cpa16(&smBsel[(size_t)br * 12 + bc4], wsel + (size_t)(col0 + br) * Kp + bc4);
        CP_COMMIT();
    }

    for (int kt = 0; kt < nk; kt++) {
        const int s = kt & 1;
        if (kt + 1 < nk) {
            const int sn = s ^ 1;
            const int k0 = (kt + 1) * 8;
            cpa16(&smA[(size_t)(sn * 128 + ar) * 12 + ac4],
                  a1 + (size_t)(row0 + ar) * Kp + k0 + ac4);
            cpa16(&smBsel[(size_t)(sn * 64 + br) * 12 + bc4],
                  wsel + (size_t)(col0 + br) * Kp + k0 + bc4);
            CP_COMMIT();
            CP_WAIT1();
        } else {
            CP_WAIT0();
        }
        __syncthreads();

        const int kk = lane & 3;
        uint32_t ah[2][4];
#pragma unroll
        for (int i = 0; i < 2; i++) {
            int m = s * 128 + wR * 32 + i * 16 + (lane >> 2);
            ah[i][0] = smA[(size_t)m * 12 + kk];
            ah[i][1] = smA[(size_t)(m + 8) * 12 + kk];
            ah[i][2] = smA[(size_t)m * 12 + kk + 4];
            ah[i][3] = smA[(size_t)(m + 8) * 12 + kk + 4];
        }
#pragma unroll
        for (int j = 0; j < 4; j++) {
            int n = s * 64 + wC * 32 + j * 8 + (lane >> 2);
            uint32_t b10 = smB1[(size_t)n * 12 + kk], b11 = smB1[(size_t)n * 12 + kk + 4];
            uint32_t b20 = smB2[(size_t)n * 12 + kk], b21 = smB2[(size_t)n * 12 + kk + 4];
#pragma unroll
            for (int i = 0; i < 2; i++) {
                mmah(acc1[i][j], ah[i], b10, b11);
                mmah(acc2[i][j], ah[i], b20, b21);
            }
        }
        __syncthreads();
    }

#pragma unroll
    for (int i = 0; i < 2; i++) {
        int r = row0 + wR * 32 + i * 16 + (lane >> 2);
#pragma unroll
        for (int j = 0; j < 4; j++) {
            int c = col0 + wC * 32 + j * 8 + 2 * (lane & 3);
            float ba0 = biasA[c], ba1 = biasA[c + 1];
            float bb0 = biasB[c], bb1 = biasB[c + 1];
#pragma unroll
            for (int half = 0; half < 2; half++) {
                int rr = r + half * 8;
                float va0 = acc1[i][j][half * 2 + 0] + ba0;
                float va1 = acc1[i][j][half * 2 + 1] + ba1;
                float vb0 = acc2[i][j][half * 2 + 0] + bb0;
                float vb1 = acc2[i][j][half * 2 + 1] + bb1;
                if (outQK) {
                    outQK[(size_t)rr * 128 + (c >> 1)] =
                        make_uint2(cvtH2(va0, va1), cvtH2(vb0, vb1));
                } else {
                    float pva0 = __shfl_xor_sync(0xffffffffu, va0, 4);
                    float pva1 = __shfl_xor_sync(0xffffffffu, va1, 4);
                    float pvb0 = __shfl_xor_sync(0xffffffffu, vb0, 4);
                    float pvb1 = __shfl_xor_sync(0xffffffffu, vb1, 4);
                    if (((lane >> 2) & 1) == 0) {
                        int bb = rr >> 11;
                        int mp = (rr & 2047) >> 1;
                        size_t base = ((size_t)bb * Hh + c) * 1024 + mp;
                        outT[base]        = make_uint2(cvtH2(va0, pva0), cvtH2(vb0, pvb0));
                        outT[base + 1024] = make_uint2(cvtH2(va1, pva1), cvtH2(vb1, pvb1));
                    }
                }
            }
        }
    }
}

// =============================================================================
// Single-output GEMM for MLP (fp16 1-product). R13 unchanged.
// =============================================================================
__global__ __launch_bounds__(256, 2) void gemmP_kernel(
    const uint32_t* __restrict__ a1, const uint32_t* __restrict__ w1p,
    const float* __restrict__ bias,
    float* __restrict__ outF, uint32_t* __restrict__ outP,
    int Kp, int Nc, int act)
{
    extern __shared__ uint32_t smu[];
    uint32_t* smA = smu;             // [2][128][20]
    uint32_t* smB = smu + 5120;      // [2][128][20]

    const int row0 = blockIdx.y * 128;
    const int col0 = blockIdx.x * 128;
    const int tid  = threadIdx.x;
    const int lane = tid & 31, warp = tid >> 5;
    const int wR = warp >> 1, wC = warp & 1;

    float acc[2][8][4] = {};
    const int nk = Kp / 16;

    {
#pragma unroll
        for (int it = 0; it < 2; it++) {
            int i = tid + it * 256;
            int r = i >> 2, c4 = (i & 3) * 4;
            cpa16(&smA[(size_t)r * 20 + c4], a1 + (size_t)(row0 + r) * Kp + c4);
            cpa16(&smB[(size_t)r * 20 + c4], w1p + (size_t)(col0 + r) * Kp + c4);
        }
        CP_COMMIT();
    }

    for (int kt = 0; kt < nk; kt++) {
        const int s = kt & 1;
        if (kt + 1 < nk) {
            const int sn = s ^ 1;
            const int k0 = (kt + 1) * 16;
#pragma unroll
            for (int it = 0; it < 2; it++) {
                int i = tid + it * 256;
                int r = i >> 2, c4 = (i & 3) * 4;
                cpa16(&smA[(size_t)(sn * 128 + r) * 20 + c4],
                      a1 + (size_t)(row0 + r) * Kp + k0 + c4);
                cpa16(&smB[(size_t)(sn * 128 + r) * 20 + c4],
                      w1p + (size_t)(col0 + r) * Kp + k0 + c4);
            }
            CP_COMMIT();
            CP_WAIT1();
        } else {
            CP_WAIT0();
        }
        __syncthreads();
#pragma unroll
        for (int ks = 0; ks < 2; ks++) {
            const int kk = ks * 8 + (lane & 3);
            uint32_t ah[2][4];
#pragma unroll
            for (int i = 0; i < 2; i++) {
                int m = s * 128 + wR * 32 + i * 16 + (lane >> 2);
                ah[i][0] = smA[(size_t)m * 20 + kk];
                ah[i][1] = smA[(size_t)(m + 8) * 20 + kk];
                ah[i][2] = smA[(size_t)m * 20 + kk + 4];
                ah[i][3] = smA[(size_t)(m + 8) * 20 + kk + 4];
            }
#pragma unroll
            for (int j = 0; j < 8; j++) {
                int n = s * 128 + wC * 64 + j * 8 + (lane >> 2);
                uint32_t b0 = smB[(size_t)n * 20 + kk];
                uint32_t b1 = smB[(size_t)n * 20 + kk + 4];
#pragma unroll
                for (int i = 0; i < 2; i++)
                    mmah(acc[i][j], ah[i], b0, b1);
            }
        }
        __syncthreads();
    }
#pragma unroll
    for (int i = 0; i < 2; i++) {
        int r = row0 + wR * 32 + i * 16 + (lane >> 2);
#pragma unroll
        for (int j = 0; j < 8; j++) {
            int c = col0 + wC * 64 + j * 8 + 2 * (lane & 3);
            float b0 = bias[c], b1 = bias[c + 1];
            float v0 = acc[i][j][0] + b0, v1 = acc[i][j][1] + b1;
            float v2 = acc[i][j][2] + b0, v3 = acc[i][j][3] + b1;
            if (act) {
                v0 = v0 / (1.0f + __expf(-v0));
                v1 = v1 / (1.0f + __expf(-v1));
                v2 = v2 / (1.0f + __expf(-v2));
                v3 = v3 / (1.0f + __expf(-v3));
            }
            if (outP) {
                outP[(size_t)r * (Nc >> 1) + (c >> 1)]       = cvtH2(v0, v1);
                outP[(size_t)(r + 8) * (Nc >> 1) + (c >> 1)] = cvtH2(v2, v3);
            } else {
                *(float2*)&outF[(size_t)r * Nc + c]       = make_float2(v0, v1);
                *(float2*)&outF[(size_t)(r + 8) * Nc + c] = make_float2(v2, v3);
            }
        }
    }
}

// =============================================================================
// Logits: dual fp16 1-product NT GEMM -> packed {S_scaled, E} fp16 + dist-sum.
// R13 unchanged.
// =============================================================================
__global__ __launch_bounds__(256, 2) void logitsP_kernel()
{
    extern __shared__ uint32_t smu[];
    uint2* smQ = (uint2*)smu;              // [2][128][12]
    uint2* smK = (uint2*)(smu + 6144);     // [2][64][12]

    const int b  = blockIdx.z;
    const int n0 = blockIdx.y * 128;
    const int m0 = blockIdx.x * 64;
    const int tid = threadIdx.x;
    const int lane = tid & 31, warp = tid >> 5;
    const int wR = warp >> 1, wC = warp & 1;

    const uint2* q2p = g_qp + (size_t)(b * Nn + n0) * 128;
    const uint2* k2p = g_kp + (size_t)(b * Mm + m0) * 128;

    float accS[2][4][4] = {}, accE[2][4][4] = {};
    const int nk = 16;

    {
#pragma unroll
        for (int it = 0; it < 2; it++) {
            int i = tid + it * 256;
            int r = i >> 2, c2 = (i & 3) * 2;
            cpa16(&smQ[(size_t)r * 12 + c2], q2p + (size_t)r * 128 + c2);
        }
        {
            int r = tid >> 2, c2 = (tid & 3) * 2;
            cpa16(&smK[(size_t)r * 12 + c2], k2p + (size_t)r * 128 + c2);
        }
        CP_COMMIT();
    }

    for (int kt = 0; kt < nk; kt++) {
        const int s = kt & 1;
        if (kt + 1 < nk) {
            const int sn = s ^ 1;
            const int k0 = (kt + 1) * 8;
#pragma unroll
            for (int it = 0; it < 2; it++) {
                int i = tid + it * 256;
                int r = i >> 2, c2 = (i & 3) * 2;
                cpa16(&smQ[(size_t)(sn * 128 + r) * 12 + c2],
                      q2p + (size_t)r * 128 + k0 + c2);
            }
            {
                int r = tid >> 2, c2 = (tid & 3) * 2;
                cpa16(&smK[(size_t)(sn * 64 + r) * 12 + c2],
                      k2p + (size_t)r * 128 + k0 + c2);
            }
            CP_COMMIT();
            CP_WAIT1();
        } else {
            CP_WAIT0();
        }
        __syncthreads();

        const int kk = lane & 3;
        uint32_t ash[2][4], aeh[2][4];
#pragma unroll
        for (int i = 0; i < 2; i++) {
            int m = s * 128 + wR * 32 + i * 16 + (lane >> 2);
            uint2 p0 = smQ[(size_t)m * 12 + kk];
            uint2 p1 = smQ[(size_t)(m + 8) * 12 + kk];
            uint2 p2 = smQ[(size_t)m * 12 + kk + 4];
            uint2 p3 = smQ[(size_t)(m + 8) * 12 + kk + 4];
            ash[i][0] = p0.x; ash[i][1] = p1.x; ash[i][2] = p2.x; ash[i][3] = p3.x;
            aeh[i][0] = p0.y; aeh[i][1] = p1.y; aeh[i][2] = p2.y; aeh[i][3] = p3.y;
        }
#pragma unroll
        for (int j = 0; j < 4; j++) {
            int n = s * 64 + wC * 32 + j * 8 + (lane >> 2);
            uint2 k0v = smK[(size_t)n * 12 + kk];
            uint2 k1v = smK[(size_t)n * 12 + kk + 4];
#pragma unroll
            for (int i = 0; i < 2; i++) {
                mmah(accS[i][j], ash[i], k0v.x, k1v.x);
                mmah(accE[i][j], aeh[i], k0v.y, k1v.y);
            }
        }
        __syncthreads();
    }

    float sumd = 0.0f;
#pragma unroll
    for (int i = 0; i < 2; i++) {
        int n_lo = n0 + wR * 32 + i * 16 + (lane >> 2);
        float q2a = g_q2[b * Nn + n_lo];
        float q2b = g_q2[b * Nn + n_lo + 8];
#pragma unroll
        for (int j = 0; j < 4; j++) {
            int m = m0 + wC * 32 + j * 8 + 2 * (lane & 3);
            float k2a = g_k2[b * Mm + m], k2b = g_k2[b * Mm + m + 1];
            size_t base0 = ((size_t)b * Nn + n_lo) * Mm + m;
            float e0 = accE[i][j][0], e1 = accE[i][j][1];
            sumd += sqrtf(fmaxf(q2a + k2a - 2.0f * e0, 1e-12f))
                  + sqrtf(fmaxf(q2a + k2b - 2.0f * e1, 1e-12f));
            *(uint2*)&g_SE[base0] = make_uint2(cvtH2(accS[i][j][0] * 0.0625f, e0),
                                               cvtH2(accS[i][j][1] * 0.0625f, e1));
            size_t base1 = ((size_t)b * Nn + n_lo + 8) * Mm + m;
            float e2 = accE[i][j][2], e3 = accE[i][j][3];
            sumd += sqrtf(fmaxf(q2b + k2a - 2.0f * e2, 1e-12f))
                  + sqrtf(fmaxf(q2b + k2b - 2.0f * e3, 1e-12f));
            *(uint2*)&g_SE[base1] = make_uint2(cvtH2(accS[i][j][2] * 0.0625f, e2),
                                               cvtH2(accS[i][j][3] * 0.0625f, e3));
        }
    }
    float* red = (float*)smu;
    red[tid] = sumd;
    __syncthreads();
    for (int sred = 128; sred > 0; sred >>= 1) {
        if (tid < sred) red[tid] += red[tid + sred];
        __syncthreads();
    }
    if (tid == 0) atomicAdd(&g_dsum[b], red[0]);
}

// =============================================================================
// Ctx: dual fp16 1-product NN GEMM, 3-stage cp.async. R13 unchanged.
// =============================================================================
__global__ __launch_bounds__(256, 2) void ctxP_kernel()
{
    extern __shared__ uint32_t smu[];
    uint32_t* smP = smu;                   // [3][128][20]
    uint2*    smV = (uint2*)(smu + 7680);  // [3][64][20]

    const int b  = blockIdx.z;
    const int n0 = blockIdx.y * 128;
    const int h0 = blockIdx.x * 64;
    const int tid = threadIdx.x;
    const int lane = tid & 31, warp = tid >> 5;
    const int wR = warp >> 1, wC = warp & 1;

    const uint32_t* p1 = g_p1 + (size_t)(b * Nn + n0) * 1024;
    const uint2* v2 = g_vT2 + ((size_t)b * Hh + h0) * 1024;

    float accS[2][4][4] = {}, accE[2][4][4] = {};
    const int nk = 64;

#pragma unroll
    for (int st = 0; st < 2; st++) {
        const int mp0 = st * 16;
#pragma unroll
        for (int it = 0; it < 2; it++) {
            int i = tid + it * 256;
            int r = i >> 2, c4 = (i & 3) * 4;
            cpa16(&smP[(size_t)(st * 128 + r) * 20 + c4], p1 + (size_t)r * 1024 + mp0 + c4);
            int rv = i >> 3, c2 = (i & 7) * 2;
            cpa16(&smV[(size_t)(st * 64 + rv) * 20 + c2], v2 + (size_t)rv * 1024 + mp0 + c2);
        }
        CP_COMMIT();
    }

    int s = 0;
    for (int kt = 0; kt < nk; kt++) {
        if (kt + 2 < nk) {
            const int sn = (s + 2 >= 3) ? s - 1 : s + 2;
            const int mp0 = (kt + 2) * 16;
#pragma unroll
            for (int it = 0; it < 2; it++) {
                int i = tid + it * 256;
                int r = i >> 2, c4 = (i & 3) * 4;
                cpa16(&smP[(size_t)(sn * 128 + r) * 20 + c4],
                      p1 + (size_t)r * 1024 + mp0 + c4);
                int rv = i >> 3, c2 = (i & 7) * 2;
                cpa16(&smV[(size_t)(sn * 64 + rv) * 20 + c2],
                      v2 + (size_t)rv * 1024 + mp0 + c2);
            }
            CP_COMMIT();
            CP_WAIT2();
        } else {
            CP_WAIT0();
        }
        __syncthreads();
#pragma unroll
        for (int ks = 0; ks < 2; ks++) {
            const int kk = ks * 8 + (lane & 3);
            uint32_t ph[2][4];
#pragma unroll
            for (int i = 0; i < 2; i++) {
                int m = s * 128 + wR * 32 + i * 16 + (lane >> 2);
                ph[i][0] = smP[(size_t)m * 20 + kk];
                ph[i][1] = smP[(size_t)(m + 8) * 20 + kk];
                ph[i][2] = smP[(size_t)m * 20 + kk + 4];
                ph[i][3] = smP[(size_t)(m + 8) * 20 + kk + 4];
            }
#pragma unroll
            for (int j = 0; j < 4; j++) {
                int n = s * 64 + wC * 32 + j * 8 + (lane >> 2);
                uint2 v0 = smV[(size_t)n * 20 + kk];
                uint2 v1 = smV[(size_t)n * 20 + kk + 4];
#pragma unroll
                for (int i = 0; i < 2; i++) {
                    mmah(accS[i][j], ph[i], v0.x, v1.x);
                    mmah(accE[i][j], ph[i], v0.y, v1.y);
                }
            }
        }
        __syncthreads();
        s = (s + 1 >= 3) ? 0 : s + 1;
    }
#pragma unroll
    for (int i = 0; i < 2; i++) {
        int n_lo = n0 + wR * 32 + i * 16 + (lane >> 2);
#pragma unroll
        for (int j = 0; j < 4; j++) {
            int h = h0 + wC * 32 + j * 8 + 2 * (lane & 3);
#pragma unroll
            for (int half = 0; half < 2; half++) {
                int n = n_lo + half * 8;
                float cs0 = accS[i][j][half * 2 + 0], cs1 = accS[i][j][half * 2 + 1];
                float ce0 = accE[i][j][half * 2 + 0], ce1 = accE[i][j][half * 2 + 1];
                size_t fb = ((size_t)b * Nn + n) * 512;
                g_f1[fb + (h >> 1)]       = cvtH2(cs0, cs1);
                g_f1[fb + 128 + (h >> 1)] = cvtH2(ce0, ce1);
                g_f1[fb + 256 + (h >> 1)] = cvtH2(cs0 - ce0, cs1 - ce1);
                g_f1[fb + 384 + (h >> 1)] = cvtH2(cs0 * ce0, cs1 * ce1);
            }
        }
    }
}

// ---------------- softmax: rebuild logits from packed {S,E} + pi ----------------
__global__ void softmax_kernel(const float* __restrict__ pi_star,
                               const float* __restrict__ gamma_p,
                               const float* __restrict__ ew_p) {
    const int row = blockIdx.x;
    const int b   = row / Nn;
    const float sc = fmaxf(g_dsum[b] * (1.0f / ((float)Nn * (float)Mm)), 1e-4f);
    const float invsc = ew_p[0] / sc;
    const float g = gamma_p[0];
    const float q2v = g_q2[row];
    const size_t base = (size_t)row * Mm;
    const int c0 = threadIdx.x * 8;
    float v[8];
    float mx = -1e30f;
#pragma unroll
    for (int q = 0; q < 2; q++) {
        uint4 se = *(const uint4*)&g_SE[base + c0 + q * 4];
        float4 piv = *(const float4*)&pi_star[base + c0 + q * 4];
        float4 k2v = *(const float4*)&g_k2[b * Mm + c0 + q * 4];
        uint32_t ses[4] = {se.x, se.y, se.z, se.w};
        float pis[4] = {piv.x, piv.y, piv.z, piv.w};
        float k2s[4] = {k2v.x, k2v.y, k2v.z, k2v.w};
#pragma unroll
        for (int t = 0; t < 4; t++) {
            float S = hlo(ses[t]), E = hhi(ses[t]);
            float d = sqrtf(fmaxf(q2v + k2s[t] - 2.0f * E, 1e-12f));
            v[q * 4 + t] = S + g * __logf(fmaxf(pis[t], 1e-9f)) - d * invsc;
        }
    }
#pragma unroll
    for (int t = 0; t < 8; t++) mx = fmaxf(mx, v[t]);
    __shared__ float sh[8];
    __shared__ float bc;
    int lane = threadIdx.x & 31, wid = threadIdx.x >> 5;
    float wm = warpRedMax(mx);
    if (lane == 0) sh[wid] = wm;
    __syncthreads();
    if (wid == 0) {
        float t = (lane < 8) ? sh[lane] : -1e30f;
        t = warpRedMax(t);
        if (lane == 0) bc = t;
    }
    __syncthreads();
    mx = bc;
    float sum = 0.0f;
#pragma unroll
    for (int t = 0; t < 8; t++) {
        v[t] = __expf(v[t] - mx);
        sum += v[t];
    }
    __syncthreads();
    float ws = warpRedSum(sum);
    if (lane == 0) sh[wid] = ws;
    __syncthreads();
    if (wid == 0) {
        float t = (lane < 8) ? sh[lane] : 0.0f;
        t = warpRedSum(t);
        if (lane == 0) bc = t;
    }
    __syncthreads();
    const float inv = 1.0f / bc;
    const size_t pbase = (size_t)row * 1024 + threadIdx.x * 4;
#pragma unroll
    for (int p = 0; p < 4; p++)
        g_p1[pbase + p] = cvtH2(v[2 * p] * inv, v[2 * p + 1] * inv);
}

// ---------------- launch ----------------
extern "C" void kernel_launch(void* const* d_in, const int* in_sizes, int n_in,
                              void* d_out, int out_size) {
    const float* q_fp  = (const float*)d_in[0];
    const float* v_ret = (const float*)d_in[1];
    const float* pi    = (const float*)d_in[2];
    const float* Wqs = (const float*)d_in[3];  const float* bqs = (const float*)d_in[4];
    const float* Wks = (const float*)d_in[5];  const float* bks = (const float*)d_in[6];
    const float* Wvs = (const float*)d_in[7];  const float* bvs = (const float*)d_in[8];
    const float* Wqe = (const float*)d_in[9];  const float* bqe = (const float*)d_in[10];
    const float* Wke = (const float*)d_in[11]; const float* bke = (const float*)d_in[12];
    const float* Wve = (const float*)d_in[13]; const float* bve = (const float*)d_in[14];
    const float* W1  = (const float*)d_in[15]; const float* b1  = (const float*)d_in[16];
    const float* W2  = (const float*)d_in[17]; const float* b2  = (const float*)d_in[18];
    const float* gamma = (const float*)d_in[19];
    const float* ew    = (const float*)d_in[20];
    float* out = (float*)d_out;

    uint32_t *qf1, *vr1, *w1p, *f1, *h1;
    uint2 *qp, *kp, *vT2;
    float *q2_p, *k2_p;
    cudaGetSymbolAddress((void**)&qf1, g_qf1);
    cudaGetSymbolAddress((void**)&vr1, g_vr1);
    cudaGetSymbolAddress((void**)&w1p, g_w1p);
    cudaGetSymbolAddress((void**)&qp, g_qp);
    cudaGetSymbolAddress((void**)&kp, g_kp);
    cudaGetSymbolAddress((void**)&vT2, g_vT2);
    cudaGetSymbolAddress((void**)&f1, g_f1);
    cudaGetSymbolAddress((void**)&h1, g_h1);
    cudaGetSymbolAddress((void**)&q2_p, g_q2);
    cudaGetSymbolAddress((void**)&k2_p, g_k2);

    const int G2_SMEM    = 6144 * 4;
    const int GEMM_SMEM  = 10240 * 4;
    const int LOGIT_SMEM = 9216 * 4;
    const int CTX_SMEM   = 15360 * 4;
    cudaFuncSetAttribute(gemm2_kernel,   cudaFuncAttributeMaxDynamicSharedMemorySize, G2_SMEM);
    cudaFuncSetAttribute(gemmP_kernel,   cudaFuncAttributeMaxDynamicSharedMemorySize, GEMM_SMEM);
    cudaFuncSetAttribute(logitsP_kernel, cudaFuncAttributeMaxDynamicSharedMemorySize, LOGIT_SMEM);
    cudaFuncSetAttribute(ctxP_kernel,    cudaFuncAttributeMaxDynamicSharedMemorySize, CTX_SMEM);

    uint32_t* wo[8] = {w1p, w1p+65536, w1p+131072, w1p+196608, w1p+262144, w1p+327680,
                       w1p+393216, w1p+524288};

    dim3 gp(4, (Bb * Nn) / 128);

    // merged prep: 3 launches instead of 13
    dim3 gr((Bb*Nn*DIN/2 + 255)/256, 2);
    pack_rows_kernel<<<gr, 256>>>(q_fp, v_ret, qf1, vr1, Bb*Nn*DIN/2);
    pack_all_weights_kernel<<<(557056 + 255)/256, 256>>>(
        Wqs, Wks, Wvs, Wqe, Wke, Wve, W1, W2, w1p);

    gemm2_kernel<<<gp, 256, G2_SMEM>>>(qf1, wo[0], wo[3], bqs, bqe, qp, nullptr, 256);
    gemm2_kernel<<<gp, 256, G2_SMEM>>>(vr1, wo[1], wo[4], bks, bke, kp, nullptr, 256);
    gemm2_kernel<<<gp, 256, G2_SMEM>>>(vr1, wo[2], wo[5], bvs, bve, nullptr, vT2, 256);

    dim3 gs(Bb * Nn, 2);
    rowsumsq_kernel<<<gs, 128>>>(qp, kp, q2_p, k2_p);

    dim3 gl(Mm / 64, Nn / 128, Bb);
    logitsP_kernel<<<gl, 256, LOGIT_SMEM>>>();

    softmax_kernel<<<Bb * Nn, 256>>>(pi, gamma, ew);

    dim3 gc(Hh / 64, Nn / 128, Bb);
    ctxP_kernel<<<gc, 256, CTX_SMEM>>>();

    dim3 gm(2, (Bb * Nn) / 128);
    gemmP_kernel<<<gm, 256, GEMM_SMEM>>>(f1, wo[6], b1, nullptr, h1, 512, 256, 1);
    gemmP_kernel<<<gm, 256, GEMM_SMEM>>>(h1, wo[7], b2, out, nullptr, 128, 256, 0);
}

// round 15
// speedup vs baseline: 2.2495x; 1.0691x over previous
#include <cuda_runtime.h>
#include <cuda_fp16.h>
#include <cstdint>

#define Bb 8
#define Nn 2048
#define Mm 2048
#define DIN 512
#define Hh 256

// ---------------- scratch (device globals; no allocs allowed) ----------------
__device__ uint32_t g_qf1[(size_t)Bb*Nn*(DIN/2)];
__device__ uint32_t g_vr1[(size_t)Bb*Mm*(DIN/2)];
__device__ uint32_t g_w1p[6*65536 + 131072 + 32768];
__device__ uint2 g_qp[(size_t)Bb*Nn*128];                 // {qsH, qeH}
__device__ uint2 g_kp[(size_t)Bb*Mm*128];                 // {ksH, keH}
__device__ uint2 g_vT2[(size_t)Bb*Hh*1024];               // {vsH, veH} [b][h][mp]
__device__ uint32_t g_SE[(size_t)Bb*Nn*Mm];               // {S_scaled fp16, E fp16}
__device__ uint32_t g_p1[(size_t)Bb*Nn*1024];
__device__ uint32_t g_f1[(size_t)Bb*Nn*512];
__device__ uint32_t g_h1[(size_t)Bb*Nn*128];
__device__ float g_q2[Bb*Nn], g_k2[Bb*Mm], g_dsum[Bb];

// ---------------- helpers ----------------
__device__ __forceinline__ uint32_t cvtH2(float f0, float f1) {
    __half h0 = __float2half(f0), h1 = __float2half(f1);
    return (uint32_t)__half_as_ushort(h0) | ((uint32_t)__half_as_ushort(h1) << 16);
}
__device__ __forceinline__ float hlo(uint32_t u) {
    return __half2float(__ushort_as_half((unsigned short)(u & 0xffff)));
}
__device__ __forceinline__ float hhi(uint32_t u) {
    return __half2float(__ushort_as_half((unsigned short)(u >> 16)));
}
__device__ __forceinline__ void mmah(float* d, const uint32_t* a, uint32_t b0, uint32_t b1) {
    asm volatile(
        "mma.sync.aligned.m16n8k16.row.col.f32.f16.f16.f32 "
        "{%0,%1,%2,%3}, {%4,%5,%6,%7}, {%8,%9}, {%0,%1,%2,%3};\n"
        : "+f"(d[0]), "+f"(d[1]), "+f"(d[2]), "+f"(d[3])
        : "r"(a[0]), "r"(a[1]), "r"(a[2]), "r"(a[3]), "r"(b0), "r"(b1));
}
__device__ __forceinline__ void cpa16(void* smem, const void* gmem) {
    uint32_t s = (uint32_t)__cvta_generic_to_shared(smem);
    asm volatile("cp.async.cg.shared.global [%0], [%1], 16;\n" :: "r"(s), "l"(gmem));
}
#define CP_COMMIT() asm volatile("cp.async.commit_group;\n")
#define CP_WAIT2()  asm volatile("cp.async.wait_group 2;\n")
#define CP_WAIT1()  asm volatile("cp.async.wait_group 1;\n")
#define CP_WAIT0()  asm volatile("cp.async.wait_group 0;\n")

__device__ __forceinline__ float warpRedSum(float v) {
#pragma unroll
    for (int o = 16; o > 0; o >>= 1) v += __shfl_xor_sync(0xffffffffu, v, o);
    return v;
}
__device__ __forceinline__ float warpRedMax(float v) {
#pragma unroll
    for (int o = 16; o > 0; o >>= 1) v = fmaxf(v, __shfl_xor_sync(0xffffffffu, v, o));
    return v;
}

// ---------------- merged prep kernels ----------------
__global__ void pack_rows_kernel(const float* __restrict__ srcA,
                                 const float* __restrict__ srcB,
                                 uint32_t* __restrict__ dstA,
                                 uint32_t* __restrict__ dstB, int npairs) {
    int i = blockIdx.x * 256 + threadIdx.x;
    if (i >= npairs) return;
    const float* src = blockIdx.y ? srcB : srcA;
    uint32_t* dst = blockIdx.y ? dstB : dstA;
    float2 f = ((const float2*)src)[i];
    dst[i] = cvtH2(f.x, f.y);
}
__global__ void pack_all_weights_kernel(
    const float* __restrict__ W0, const float* __restrict__ W1_,
    const float* __restrict__ W2_, const float* __restrict__ W3,
    const float* __restrict__ W4, const float* __restrict__ W5,
    const float* __restrict__ W6, const float* __restrict__ W7,
    uint32_t* __restrict__ dst) {
    int i = blockIdx.x * 256 + threadIdx.x;
    if (i >= 557056) return;
    const float* W;
    int n, kp;
    if (i < 393216) {
        const float* Ws[6] = {W0, W1_, W2_, W3, W4, W5};
        W = Ws[i >> 16];
        int li = i & 65535;
        n = li >> 8; kp = li & 255;
    } else if (i < 524288) {
        W = W6;
        int li = i - 393216;
        n = li >> 9; kp = li & 511;
    } else {
        W = W7;
        int li = i - 524288;
        n = li >> 7; kp = li & 127;
    }
    dst[i] = cvtH2(W[(size_t)(2 * kp) * 256 + n], W[(size_t)(2 * kp + 1) * 256 + n]);
}
__global__ void rowsumsq_kernel(const uint2* __restrict__ QP, const uint2* __restrict__ KP,
                                float* __restrict__ q2, float* __restrict__ k2) {
    const int row = blockIdx.x, tid = threadIdx.x;
    if (blockIdx.x == 0 && blockIdx.y == 0 && tid < Bb) g_dsum[tid] = 0.0f;
    const uint2* P2 = blockIdx.y ? KP : QP;
    float* dst = blockIdx.y ? k2 : q2;
    uint2 q = P2[(size_t)row * 128 + tid];
    float v0 = hlo(q.y), v1 = hhi(q.y);
    float s = v0 * v0 + v1 * v1;
    __shared__ float sh[4];
    int lane = tid & 31, wid = tid >> 5;
    float w = warpRedSum(s);
    if (lane == 0) sh[wid] = w;
    __syncthreads();
    if (wid == 0) {
        float t = (lane < 4) ? sh[lane] : 0.0f;
        t = warpRedSum(t);
        if (lane == 0) dst[row] = t;
    }
}

// =============================================================================
// Merged 3-way dual-output projection GEMM (fp16 1-product).
// blockIdx.z: 0 -> q-proj (out qp), 1 -> k-proj (out kp), 2 -> v-proj (out vT).
// BK=16 kp/stage (32 fp16), 16 k-iterations, 2-stage cp.async, 40960B smem.
// =============================================================================
__global__ __launch_bounds__(256, 2) void gemm2_kernel(
    const uint32_t* __restrict__ qf1, const uint32_t* __restrict__ vr1,
    const uint32_t* __restrict__ w1p,
    const float* __restrict__ bqs, const float* __restrict__ bqe,
    const float* __restrict__ bks, const float* __restrict__ bke,
    const float* __restrict__ bvs, const float* __restrict__ bve,
    uint2* __restrict__ qp, uint2* __restrict__ kp, uint2* __restrict__ vT)
{
    extern __shared__ uint32_t smu[];
    uint32_t* smA  = smu;            // [2][128][20]
    uint32_t* smB1 = smu + 5120;     // [2][64][20]
    uint32_t* smB2 = smu + 7680;     // [2][64][20]

    const int z = blockIdx.z;
    const uint32_t* a1 = (z == 0) ? qf1 : vr1;
    const uint32_t* wa = w1p + ((z == 0) ? 0 : (z == 1) ? 65536 : 131072);
    const uint32_t* wb = w1p + ((z == 0) ? 196608 : (z == 1) ? 262144 : 327680);
    const float* biasA = (z == 0) ? bqs : (z == 1) ? bks : bvs;
    const float* biasB = (z == 0) ? bqe : (z == 1) ? bke : bve;
    uint2* outQK = (z == 0) ? qp : (z == 1) ? kp : nullptr;

    const int Kp = 256;
    const int row0 = blockIdx.y * 128;
    const int col0 = blockIdx.x * 64;
    const int tid  = threadIdx.x;
    const int lane = tid & 31, warp = tid >> 5;
    const int wR = warp >> 1, wC = warp & 1;

    float acc1[2][4][4] = {}, acc2[2][4][4] = {};
    const int nk = Kp / 16;   // 16

    const int bt = tid & 127;
    const int br = bt >> 2, bc4 = (bt & 3) * 4;
    uint32_t* smBsel = (tid < 128) ? smB1 : smB2;
    const uint32_t* wsel = (tid < 128) ? wa : wb;

    {   // prologue stage 0
#pragma unroll
        for (int it = 0; it < 2; it++) {
            int i = tid + it * 256;
            int r = i >> 2, c4 = (i & 3) * 4;
            cpa16(&smA[(size_t)r * 20 + c4], a1 + (size_t)(row0 + r) * Kp + c4);
        }
        cpa16(&smBsel[(size_t)br * 20 + bc4], wsel + (size_t)(col0 + br) * Kp + bc4);
        cpa16(&smBsel[(size_t)(br + 32) * 20 + bc4], wsel + (size_t)(col0 + br + 32) * Kp + bc4);
        CP_COMMIT();
    }

    for (int kt = 0; kt < nk; kt++) {
        const int s = kt & 1;
        if (kt + 1 < nk) {
            const int sn = s ^ 1;
            const int k0 = (kt + 1) * 16;
#pragma unroll
            for (int it = 0; it < 2; it++) {
                int i = tid + it * 256;
                int r = i >> 2, c4 = (i & 3) * 4;
                cpa16(&smA[(size_t)(sn * 128 + r) * 20 + c4],
                      a1 + (size_t)(row0 + r) * Kp + k0 + c4);
            }
            cpa16(&smBsel[(size_t)(sn * 64 + br) * 20 + bc4],
                  wsel + (size_t)(col0 + br) * Kp + k0 + bc4);
            cpa16(&smBsel[(size_t)(sn * 64 + br + 32) * 20 + bc4],
                  wsel + (size_t)(col0 + br + 32) * Kp + k0 + bc4);
            CP_COMMIT();
            CP_WAIT1();
        } else {
            CP_WAIT0();
        }
        __syncthreads();

#pragma unroll
        for (int ks = 0; ks < 2; ks++) {
            const int kk = ks * 8 + (lane & 3);
            uint32_t ah[2][4];
#pragma unroll
            for (int i = 0; i < 2; i++) {
                int m = s * 128 + wR * 32 + i * 16 + (lane >> 2);
                ah[i][0] = smA[(size_t)m * 20 + kk];
                ah[i][1] = smA[(size_t)(m + 8) * 20 + kk];
                ah[i][2] = smA[(size_t)m * 20 + kk + 4];
                ah[i][3] = smA[(size_t)(m + 8) * 20 + kk + 4];
            }
#pragma unroll
            for (int j = 0; j < 4; j++) {
                int n = s * 64 + wC * 32 + j * 8 + (lane >> 2);
                uint32_t b10 = smB1[(size_t)n * 20 + kk], b11 = smB1[(size_t)n * 20 + kk + 4];
                uint32_t b20 = smB2[(size_t)n * 20 + kk], b21 = smB2[(size_t)n * 20 + kk + 4];
#pragma unroll
                for (int i = 0; i < 2; i++) {
                    mmah(acc1[i][j], ah[i], b10, b11);
                    mmah(acc2[i][j], ah[i], b20, b21);
                }
            }
        }
        __syncthreads();
    }

#pragma unroll
    for (int i = 0; i < 2; i++) {
        int r = row0 + wR * 32 + i * 16 + (lane >> 2);
#pragma unroll
        for (int j = 0; j < 4; j++) {
            int c = col0 + wC * 32 + j * 8 + 2 * (lane & 3);
            float ba0 = biasA[c], ba1 = biasA[c + 1];
            float bb0 = biasB[c], bb1 = biasB[c + 1];
#pragma unroll
            for (int half = 0; half < 2; half++) {
                int rr = r + half * 8;
                float va0 = acc1[i][j][half * 2 + 0] + ba0;
                float va1 = acc1[i][j][half * 2 + 1] + ba1;
                float vb0 = acc2[i][j][half * 2 + 0] + bb0;
                float vb1 = acc2[i][j][half * 2 + 1] + bb1;
                if (outQK) {
                    outQK[(size_t)rr * 128 + (c >> 1)] =
                        make_uint2(cvtH2(va0, va1), cvtH2(vb0, vb1));
                } else {
                    float pva0 = __shfl_xor_sync(0xffffffffu, va0, 4);
                    float pva1 = __shfl_xor_sync(0xffffffffu, va1, 4);
                    float pvb0 = __shfl_xor_sync(0xffffffffu, vb0, 4);
                    float pvb1 = __shfl_xor_sync(0xffffffffu, vb1, 4);
                    if (((lane >> 2) & 1) == 0) {
                        int bb = rr >> 11;
                        int mp = (rr & 2047) >> 1;
                        size_t base = ((size_t)bb * Hh + c) * 1024 + mp;
                        vT[base]        = make_uint2(cvtH2(va0, pva0), cvtH2(vb0, pvb0));
                        vT[base + 1024] = make_uint2(cvtH2(va1, pva1), cvtH2(vb1, pvb1));
                    }
                }
            }
        }
    }
}

// =============================================================================
// Single-output GEMM for MLP (fp16 1-product). R14 unchanged.
// =============================================================================
__global__ __launch_bounds__(256, 2) void gemmP_kernel(
    const uint32_t* __restrict__ a1, const uint32_t* __restrict__ w1p,
    const float* __restrict__ bias,
    float* __restrict__ outF, uint32_t* __restrict__ outP,
    int Kp, int Nc, int act)
{
    extern __shared__ uint32_t smu[];
    uint32_t* smA = smu;             // [2][128][20]
    uint32_t* smB = smu + 5120;      // [2][128][20]

    const int row0 = blockIdx.y * 128;
    const int col0 = blockIdx.x * 128;
    const int tid  = threadIdx.x;
    const int lane = tid & 31, warp = tid >> 5;
    const int wR = warp >> 1, wC = warp & 1;

    float acc[2][8][4] = {};
    const int nk = Kp / 16;

    {
#pragma unroll
        for (int it = 0; it < 2; it++) {
            int i = tid + it * 256;
            int r = i >> 2, c4 = (i & 3) * 4;
            cpa16(&smA[(size_t)r * 20 + c4], a1 + (size_t)(row0 + r) * Kp + c4);
            cpa16(&smB[(size_t)r * 20 + c4], w1p + (size_t)(col0 + r) * Kp + c4);
        }
        CP_COMMIT();
    }

    for (int kt = 0; kt < nk; kt++) {
        const int s = kt & 1;
        if (kt + 1 < nk) {
            const int sn = s ^ 1;
            const int k0 = (kt + 1) * 16;
#pragma unroll
            for (int it = 0; it < 2; it++) {
                int i = tid + it * 256;
                int r = i >> 2, c4 = (i & 3) * 4;
                cpa16(&smA[(size_t)(sn * 128 + r) * 20 + c4],
                      a1 + (size_t)(row0 + r) * Kp + k0 + c4);
                cpa16(&smB[(size_t)(sn * 128 + r) * 20 + c4],
                      w1p + (size_t)(col0 + r) * Kp + k0 + c4);
            }
            CP_COMMIT();
            CP_WAIT1();
        } else {
            CP_WAIT0();
        }
        __syncthreads();
#pragma unroll
        for (int ks = 0; ks < 2; ks++) {
            const int kk = ks * 8 + (lane & 3);
            uint32_t ah[2][4];
#pragma unroll
            for (int i = 0; i < 2; i++) {
                int m = s * 128 + wR * 32 + i * 16 + (lane >> 2);
                ah[i][0] = smA[(size_t)m * 20 + kk];
                ah[i][1] = smA[(size_t)(m + 8) * 20 + kk];
                ah[i][2] = smA[(size_t)m * 20 + kk + 4];
                ah[i][3] = smA[(size_t)(m + 8) * 20 + kk + 4];
            }
#pragma unroll
            for (int j = 0; j < 8; j++) {
                int n = s * 128 + wC * 64 + j * 8 + (lane >> 2);
                uint32_t b0 = smB[(size_t)n * 20 + kk];
                uint32_t b1 = smB[(size_t)n * 20 + kk + 4];
#pragma unroll
                for (int i = 0; i < 2; i++)
                    mmah(acc[i][j], ah[i], b0, b1);
            }
        }
        __syncthreads();
    }
#pragma unroll
    for (int i = 0; i < 2; i++) {
        int r = row0 + wR * 32 + i * 16 + (lane >> 2);
#pragma unroll
        for (int j = 0; j < 8; j++) {
            int c = col0 + wC * 64 + j * 8 + 2 * (lane & 3);
            float b0 = bias[c], b1 = bias[c + 1];
            float v0 = acc[i][j][0] + b0, v1 = acc[i][j][1] + b1;
            float v2 = acc[i][j][2] + b0, v3 = acc[i][j][3] + b1;
            if (act) {
                v0 = v0 / (1.0f + __expf(-v0));
                v1 = v1 / (1.0f + __expf(-v1));
                v2 = v2 / (1.0f + __expf(-v2));
                v3 = v3 / (1.0f + __expf(-v3));
            }
            if (outP) {
                outP[(size_t)r * (Nc >> 1) + (c >> 1)]       = cvtH2(v0, v1);
                outP[(size_t)(r + 8) * (Nc >> 1) + (c >> 1)] = cvtH2(v2, v3);
            } else {
                *(float2*)&outF[(size_t)r * Nc + c]       = make_float2(v0, v1);
                *(float2*)&outF[(size_t)(r + 8) * Nc + c] = make_float2(v2, v3);
            }
        }
    }
}

// =============================================================================
// Logits: dual fp16 1-product NT GEMM -> packed {S_scaled, E} + dist-sum.
// R14 unchanged.
// =============================================================================
__global__ __launch_bounds__(256, 2) void logitsP_kernel()
{
    extern __shared__ uint32_t smu[];
    uint2* smQ = (uint2*)smu;              // [2][128][12]
    uint2* smK = (uint2*)(smu + 6144);     // [2][64][12]

    const int b  = blockIdx.z;
    const int n0 = blockIdx.y * 128;
    const int m0 = blockIdx.x * 64;
    const int tid = threadIdx.x;
    const int lane = tid & 31, warp = tid >> 5;
    const int wR = warp >> 1, wC = warp & 1;

    const uint2* q2p = g_qp + (size_t)(b * Nn + n0) * 128;
    const uint2* k2p = g_kp + (size_t)(b * Mm + m0) * 128;

    float accS[2][4][4] = {}, accE[2][4][4] = {};
    const int nk = 16;

    {
#pragma unroll
        for (int it = 0; it < 2; it++) {
            int i = tid + it * 256;
            int r = i >> 2, c2 = (i & 3) * 2;
            cpa16(&smQ[(size_t)r * 12 + c2], q2p + (size_t)r * 128 + c2);
        }
        {
            int r = tid >> 2, c2 = (tid & 3) * 2;
            cpa16(&smK[(size_t)r * 12 + c2], k2p + (size_t)r * 128 + c2);
        }
        CP_COMMIT();
    }

    for (int kt = 0; kt < nk; kt++) {
        const int s = kt & 1;
        if (kt + 1 < nk) {
            const int sn = s ^ 1;
            const int k0 = (kt + 1) * 8;
#pragma unroll
            for (int it = 0; it < 2; it++) {
                int i = tid + it * 256;
                int r = i >> 2, c2 = (i & 3) * 2;
                cpa16(&smQ[(size_t)(sn * 128 + r) * 12 + c2],
                      q2p + (size_t)r * 128 + k0 + c2);
            }
            {
                int r = tid >> 2, c2 = (tid & 3) * 2;
                cpa16(&smK[(size_t)(sn * 64 + r) * 12 + c2],
                      k2p + (size_t)r * 128 + k0 + c2);
            }
            CP_COMMIT();
            CP_WAIT1();
        } else {
            CP_WAIT0();
        }
        __syncthreads();

        const int kk = lane & 3;
        uint32_t ash[2][4], aeh[2][4];
#pragma unroll
        for (int i = 0; i < 2; i++) {
            int m = s * 128 + wR * 32 + i * 16 + (lane >> 2);
            uint2 p0 = smQ[(size_t)m * 12 + kk];
            uint2 p1 = smQ[(size_t)(m + 8) * 12 + kk];
            uint2 p2 = smQ[(size_t)m * 12 + kk + 4];
            uint2 p3 = smQ[(size_t)(m + 8) * 12 + kk + 4];
            ash[i][0] = p0.x; ash[i][1] = p1.x; ash[i][2] = p2.x; ash[i][3] = p3.x;
            aeh[i][0] = p0.y; aeh[i][1] = p1.y; aeh[i][2] = p2.y; aeh[i][3] = p3.y;
        }
#pragma unroll
        for (int j = 0; j < 4; j++) {
            int n = s * 64 + wC * 32 + j * 8 + (lane >> 2);
            uint2 k0v = smK[(size_t)n * 12 + kk];
            uint2 k1v = smK[(size_t)n * 12 + kk + 4];
#pragma unroll
            for (int i = 0; i < 2; i++) {
                mmah(accS[i][j], ash[i], k0v.x, k1v.x);
                mmah(accE[i][j], aeh[i], k0v.y, k1v.y);
            }
        }
        __syncthreads();
    }

    float sumd = 0.0f;
#pragma unroll
    for (int i = 0; i < 2; i++) {
        int n_lo = n0 + wR * 32 + i * 16 + (lane >> 2);
        float q2a = g_q2[b * Nn + n_lo];
        float q2b = g_q2[b * Nn + n_lo + 8];
#pragma unroll
        for (int j = 0; j < 4; j++) {
            int m = m0 + wC * 32 + j * 8 + 2 * (lane & 3);
            float k2a = g_k2[b * Mm + m], k2b = g_k2[b * Mm + m + 1];
            size_t base0 = ((size_t)b * Nn + n_lo) * Mm + m;
            float e0 = accE[i][j][0], e1 = accE[i][j][1];
            sumd += sqrtf(fmaxf(q2a + k2a - 2.0f * e0, 1e-12f))
                  + sqrtf(fmaxf(q2a + k2b - 2.0f * e1, 1e-12f));
            *(uint2*)&g_SE[base0] = make_uint2(cvtH2(accS[i][j][0] * 0.0625f, e0),
                                               cvtH2(accS[i][j][1] * 0.0625f, e1));
            size_t base1 = ((size_t)b * Nn + n_lo + 8) * Mm + m;
            float e2 = accE[i][j][2], e3 = accE[i][j][3];
            sumd += sqrtf(fmaxf(q2b + k2a - 2.0f * e2, 1e-12f))
                  + sqrtf(fmaxf(q2b + k2b - 2.0f * e3, 1e-12f));
            *(uint2*)&g_SE[base1] = make_uint2(cvtH2(accS[i][j][2] * 0.0625f, e2),
                                               cvtH2(accS[i][j][3] * 0.0625f, e3));
        }
    }
    float* red = (float*)smu;
    red[tid] = sumd;
    __syncthreads();
    for (int sred = 128; sred > 0; sred >>= 1) {
        if (tid < sred) red[tid] += red[tid + sred];
        __syncthreads();
    }
    if (tid == 0) atomicAdd(&g_dsum[b], red[0]);
}

// =============================================================================
// Ctx: dual fp16 1-product NN GEMM, 3-stage cp.async. R14 unchanged.
// =============================================================================
__global__ __launch_bounds__(256, 2) void ctxP_kernel()
{
    extern __shared__ uint32_t smu[];
    uint32_t* smP = smu;                   // [3][128][20]
    uint2*    smV = (uint2*)(smu + 7680);  // [3][64][20]

    const int b  = blockIdx.z;
    const int n0 = blockIdx.y * 128;
    const int h0 = blockIdx.x * 64;
    const int tid = threadIdx.x;
    const int lane = tid & 31, warp = tid >> 5;
    const int wR = warp >> 1, wC = warp & 1;

    const uint32_t* p1 = g_p1 + (size_t)(b * Nn + n0) * 1024;
    const uint2* v2 = g_vT2 + ((size_t)b * Hh + h0) * 1024;

    float accS[2][4][4] = {}, accE[2][4][4] = {};
    const int nk = 64;

#pragma unroll
    for (int st = 0; st < 2; st++) {
        const int mp0 = st * 16;
#pragma unroll
        for (int it = 0; it < 2; it++) {
            int i = tid + it * 256;
            int r = i >> 2, c4 = (i & 3) * 4;
            cpa16(&smP[(size_t)(st * 128 + r) * 20 + c4], p1 + (size_t)r * 1024 + mp0 + c4);
            int rv = i >> 3, c2 = (i & 7) * 2;
            cpa16(&smV[(size_t)(st * 64 + rv) * 20 + c2], v2 + (size_t)rv * 1024 + mp0 + c2);
        }
        CP_COMMIT();
    }

    int s = 0;
    for (int kt = 0; kt < nk; kt++) {
        if (kt + 2 < nk) {
            const int sn = (s + 2 >= 3) ? s - 1 : s + 2;
            const int mp0 = (kt + 2) * 16;
#pragma unroll
            for (int it = 0; it < 2; it++) {
                int i = tid + it * 256;
                int r = i >> 2, c4 = (i & 3) * 4;
                cpa16(&smP[(size_t)(sn * 128 + r) * 20 + c4],
                      p1 + (size_t)r * 1024 + mp0 + c4);
                int rv = i >> 3, c2 = (i & 7) * 2;
                cpa16(&smV[(size_t)(sn * 64 + rv) * 20 + c2],
                      v2 + (size_t)rv * 1024 + mp0 + c2);
            }
            CP_COMMIT();
            CP_WAIT2();
        } else {
            CP_WAIT0();
        }
        __syncthreads();
#pragma unroll
        for (int ks = 0; ks < 2; ks++) {
            const int kk = ks * 8 + (lane & 3);
            uint32_t ph[2][4];
#pragma unroll
            for (int i = 0; i < 2; i++) {
                int m = s * 128 + wR * 32 + i * 16 + (lane >> 2);
                ph[i][0] = smP[(size_t)m * 20 + kk];
                ph[i][1] = smP[(size_t)(m + 8) * 20 + kk];
                ph[i][2] = smP[(size_t)m * 20 + kk + 4];
                ph[i][3] = smP[(size_t)(m + 8) * 20 + kk + 4];
            }
#pragma unroll
            for (int j = 0; j < 4; j++) {
                int n = s * 64 + wC * 32 + j * 8 + (lane >> 2);
                uint2 v0 = smV[(size_t)n * 20 + kk];
                uint2 v1 = smV[(size_t)n * 20 + kk + 4];
#pragma unroll
                for (int i = 0; i < 2; i++) {
                    mmah(accS[i][j], ph[i], v0.x, v1.x);
                    mmah(accE[i][j], ph[i], v0.y, v1.y);
                }
            }
        }
        __syncthreads();
        s = (s + 1 >= 3) ? 0 : s + 1;
    }
#pragma unroll
    for (int i = 0; i < 2; i++) {
        int n_lo = n0 + wR * 32 + i * 16 + (lane >> 2);
#pragma unroll
        for (int j = 0; j < 4; j++) {
            int h = h0 + wC * 32 + j * 8 + 2 * (lane & 3);
#pragma unroll
            for (int half = 0; half < 2; half++) {
                int n = n_lo + half * 8;
                float cs0 = accS[i][j][half * 2 + 0], cs1 = accS[i][j][half * 2 + 1];
                float ce0 = accE[i][j][half * 2 + 0], ce1 = accE[i][j][half * 2 + 1];
                size_t fb = ((size_t)b * Nn + n) * 512;
                g_f1[fb + (h >> 1)]       = cvtH2(cs0, cs1);
                g_f1[fb + 128 + (h >> 1)] = cvtH2(ce0, ce1);
                g_f1[fb + 256 + (h >> 1)] = cvtH2(cs0 - ce0, cs1 - ce1);
                g_f1[fb + 384 + (h >> 1)] = cvtH2(cs0 * ce0, cs1 * ce1);
            }
        }
    }
}

// ---------------- softmax: rebuild logits from packed {S,E} + pi ----------------
__global__ void softmax_kernel(const float* __restrict__ pi_star,
                               const float* __restrict__ gamma_p,
                               const float* __restrict__ ew_p) {
    const int row = blockIdx.x;
    const int b   = row / Nn;
    const float sc = fmaxf(g_dsum[b] * (1.0f / ((float)Nn * (float)Mm)), 1e-4f);
    const float invsc = ew_p[0] / sc;
    const float g = gamma_p[0];
    const float q2v = g_q2[row];
    const size_t base = (size_t)row * Mm;
    const int c0 = threadIdx.x * 8;
    float v[8];
    float mx = -1e30f;
#pragma unroll
    for (int q = 0; q < 2; q++) {
        uint4 se = *(const uint4*)&g_SE[base + c0 + q * 4];
        float4 piv = *(const float4*)&pi_star[base + c0 + q * 4];
        float4 k2v = *(const float4*)&g_k2[b * Mm + c0 + q * 4];
        uint32_t ses[4] = {se.x, se.y, se.z, se.w};
        float pis[4] = {piv.x, piv.y, piv.z, piv.w};
        float k2s[4] = {k2v.x, k2v.y, k2v.z, k2v.w};
#pragma unroll
        for (int t = 0; t < 4; t++) {
            float S = hlo(ses[t]), E = hhi(ses[t]);
            float d = sqrtf(fmaxf(q2v + k2s[t] - 2.0f * E, 1e-12f));
            v[q * 4 + t] = S + g * __logf(fmaxf(pis[t], 1e-9f)) - d * invsc;
        }
    }
#pragma unroll
    for (int t = 0; t < 8; t++) mx = fmaxf(mx, v[t]);
    __shared__ float sh[8];
    __shared__ float bc;
    int lane = threadIdx.x & 31, wid = threadIdx.x >> 5;
    float wm = warpRedMax(mx);
    if (lane == 0) sh[wid] = wm;
    __syncthreads();
    if (wid == 0) {
        float t = (lane < 8) ? sh[lane] : -1e30f;
        t = warpRedMax(t);
        if (lane == 0) bc = t;
    }
    __syncthreads();
    mx = bc;
    float sum = 0.0f;
#pragma unroll
    for (int t = 0; t < 8; t++) {
        v[t] = __expf(v[t] - mx);
        sum += v[t];
    }
    __syncthreads();
    float ws = warpRedSum(sum);
    if (lane == 0) sh[wid] = ws;
    __syncthreads();
    if (wid == 0) {
        float t = (lane < 8) ? sh[lane] : 0.0f;
        t = warpRedSum(t);
        if (lane == 0) bc = t;
    }
    __syncthreads();
    const float inv = 1.0f / bc;
    const size_t pbase = (size_t)row * 1024 + threadIdx.x * 4;
#pragma unroll
    for (int p = 0; p < 4; p++)
        g_p1[pbase + p] = cvtH2(v[2 * p] * inv, v[2 * p + 1] * inv);
}

// ---------------- launch ----------------
extern "C" void kernel_launch(void* const* d_in, const int* in_sizes, int n_in,
                              void* d_out, int out_size) {
    const float* q_fp  = (const float*)d_in[0];
    const float* v_ret = (const float*)d_in[1];
    const float* pi    = (const float*)d_in[2];
    const float* Wqs = (const float*)d_in[3];  const float* bqs = (const float*)d_in[4];
    const float* Wks = (const float*)d_in[5];  const float* bks = (const float*)d_in[6];
    const float* Wvs = (const float*)d_in[7];  const float* bvs = (const float*)d_in[8];
    const float* Wqe = (const float*)d_in[9];  const float* bqe = (const float*)d_in[10];
    const float* Wke = (const float*)d_in[11]; const float* bke = (const float*)d_in[12];
    const float* Wve = (const float*)d_in[13]; const float* bve = (const float*)d_in[14];
    const float* W1  = (const float*)d_in[15]; const float* b1  = (const float*)d_in[16];
    const float* W2  = (const float*)d_in[17]; const float* b2  = (const float*)d_in[18];
    const float* gamma = (const float*)d_in[19];
    const float* ew    = (const float*)d_in[20];
    float* out = (float*)d_out;

    uint32_t *qf1, *vr1, *w1p, *f1, *h1;
    uint2 *qp, *kp, *vT2;
    float *q2_p, *k2_p;
    cudaGetSymbolAddress((void**)&qf1, g_qf1);
    cudaGetSymbolAddress((void**)&vr1, g_vr1);
    cudaGetSymbolAddress((void**)&w1p, g_w1p);
    cudaGetSymbolAddress((void**)&qp, g_qp);
    cudaGetSymbolAddress((void**)&kp, g_kp);
    cudaGetSymbolAddress((void**)&vT2, g_vT2);
    cudaGetSymbolAddress((void**)&f1, g_f1);
    cudaGetSymbolAddress((void**)&h1, g_h1);
    cudaGetSymbolAddress((void**)&q2_p, g_q2);
    cudaGetSymbolAddress((void**)&k2_p, g_k2);

    const int G2_SMEM    = 10240 * 4;    // 40960
    const int GEMM_SMEM  = 10240 * 4;
    const int LOGIT_SMEM = 9216 * 4;
    const int CTX_SMEM   = 15360 * 4;
    cudaFuncSetAttribute(gemm2_kernel,   cudaFuncAttributeMaxDynamicSharedMemorySize, G2_SMEM);
    cudaFuncSetAttribute(gemmP_kernel,   cudaFuncAttributeMaxDynamicSharedMemorySize, GEMM_SMEM);
    cudaFuncSetAttribute(logitsP_kernel, cudaFuncAttributeMaxDynamicSharedMemorySize, LOGIT_SMEM);
    cudaFuncSetAttribute(ctxP_kernel,    cudaFuncAttributeMaxDynamicSharedMemorySize, CTX_SMEM);

    uint32_t* wo[8] = {w1p, w1p+65536, w1p+131072, w1p+196608, w1p+262144, w1p+327680,
                       w1p+393216, w1p+524288};

    // merged prep
    dim3 gr((Bb*Nn*DIN/2 + 255)/256, 2);
    pack_rows_kernel<<<gr, 256>>>(q_fp, v_ret, qf1, vr1, Bb*Nn*DIN/2);
    pack_all_weights_kernel<<<(557056 + 255)/256, 256>>>(
        Wqs, Wks, Wvs, Wqe, Wke, Wve, W1, W2, w1p);

    // merged 3-way projections
    dim3 gp(4, (Bb * Nn) / 128, 3);
    gemm2_kernel<<<gp, 256, G2_SMEM>>>(qf1, vr1, w1p,
                                       bqs, bqe, bks, bke, bvs, bve,
                                       qp, kp, vT2);

    dim3 gs(Bb * Nn, 2);
    rowsumsq_kernel<<<gs, 128>>>(qp, kp, q2_p, k2_p);

    dim3 gl(Mm / 64, Nn / 128, Bb);
    logitsP_kernel<<<gl, 256, LOGIT_SMEM>>>();

    softmax_kernel<<<Bb * Nn, 256>>>(pi, gamma, ew);

    dim3 gc(Hh / 64, Nn / 128, Bb);
    ctxP_kernel<<<gc, 256, CTX_SMEM>>>();

    dim3 gm(2, (Bb * Nn) / 128);
    gemmP_kernel<<<gm, 256, GEMM_SMEM>>>(f1, wo[6], b1, nullptr, h1, 512, 256, 1);
    gemmP_kernel<<<gm, 256, GEMM_SMEM>>>(h1, wo[7], b2, out, nullptr, 128, 256, 0);
}

// round 16
// speedup vs baseline: 2.4224x; 1.0769x over previous
#include <cuda_runtime.h>
#include <cuda_fp16.h>
#include <cstdint>

#define Bb 8
#define Nn 2048
#define Mm 2048
#define DIN 512
#define Hh 256

// ---------------- scratch (device globals; no allocs allowed) ----------------
__device__ uint32_t g_qf1[(size_t)Bb*Nn*(DIN/2)];
__device__ uint32_t g_vr1[(size_t)Bb*Mm*(DIN/2)];
__device__ uint32_t g_w1p[6*65536 + 131072 + 32768];
__device__ uint2 g_qp[(size_t)Bb*Nn*128];                 // {qsH, qeH}
__device__ uint2 g_kp[(size_t)Bb*Mm*128];                 // {ksH, keH}
__device__ uint2 g_vT2[(size_t)Bb*Hh*1024];               // {vsH, veH} [b][h][mp]
__device__ uint32_t g_SE[(size_t)Bb*Nn*Mm];               // {S_scaled fp16, E fp16}
__device__ uint32_t g_p1[(size_t)Bb*Nn*1024];
__device__ uint32_t g_f1[(size_t)Bb*Nn*512];
__device__ uint32_t g_h1[(size_t)Bb*Nn*128];
__device__ float g_q2[Bb*Nn], g_k2[Bb*Mm], g_dsum[Bb];

// ---------------- helpers ----------------
__device__ __forceinline__ uint32_t cvtH2(float f0, float f1) {
    __half h0 = __float2half(f0), h1 = __float2half(f1);
    return (uint32_t)__half_as_ushort(h0) | ((uint32_t)__half_as_ushort(h1) << 16);
}
__device__ __forceinline__ float hlo(uint32_t u) {
    return __half2float(__ushort_as_half((unsigned short)(u & 0xffff)));
}
__device__ __forceinline__ float hhi(uint32_t u) {
    return __half2float(__ushort_as_half((unsigned short)(u >> 16)));
}
__device__ __forceinline__ void mmah(float* d, const uint32_t* a, uint32_t b0, uint32_t b1) {
    asm volatile(
        "mma.sync.aligned.m16n8k16.row.col.f32.f16.f16.f32 "
        "{%0,%1,%2,%3}, {%4,%5,%6,%7}, {%8,%9}, {%0,%1,%2,%3};\n"
        : "+f"(d[0]), "+f"(d[1]), "+f"(d[2]), "+f"(d[3])
        : "r"(a[0]), "r"(a[1]), "r"(a[2]), "r"(a[3]), "r"(b0), "r"(b1));
}
__device__ __forceinline__ void cpa16(void* smem, const void* gmem) {
    uint32_t s = (uint32_t)__cvta_generic_to_shared(smem);
    asm volatile("cp.async.cg.shared.global [%0], [%1], 16;\n" :: "r"(s), "l"(gmem));
}
#define CP_COMMIT() asm volatile("cp.async.commit_group;\n")
#define CP_WAIT1()  asm volatile("cp.async.wait_group 1;\n")
#define CP_WAIT0()  asm volatile("cp.async.wait_group 0;\n")

__device__ __forceinline__ float warpRedSum(float v) {
#pragma unroll
    for (int o = 16; o > 0; o >>= 1) v += __shfl_xor_sync(0xffffffffu, v, o);
    return v;
}
__device__ __forceinline__ float warpRedMax(float v) {
#pragma unroll
    for (int o = 16; o > 0; o >>= 1) v = fmaxf(v, __shfl_xor_sync(0xffffffffu, v, o));
    return v;
}

// ---------------- merged prep kernels ----------------
// packs both inputs; also zeroes q2/k2/dsum (consumed later by gemm2 atomics)
__global__ void pack_rows_kernel(const float* __restrict__ srcA,
                                 const float* __restrict__ srcB,
                                 uint32_t* __restrict__ dstA,
                                 uint32_t* __restrict__ dstB, int npairs) {
    int i = blockIdx.x * 256 + threadIdx.x;
    if (i >= npairs) return;
    if (blockIdx.y == 0) {
        if (i < Bb * Nn) g_q2[i] = 0.0f;
        if (i < Bb * Mm) g_k2[i] = 0.0f;
        if (i < Bb) g_dsum[i] = 0.0f;
    }
    const float* src = blockIdx.y ? srcB : srcA;
    uint32_t* dst = blockIdx.y ? dstB : dstA;
    float2 f = ((const float2*)src)[i];
    dst[i] = cvtH2(f.x, f.y);
}
__global__ void pack_all_weights_kernel(
    const float* __restrict__ W0, const float* __restrict__ W1_,
    const float* __restrict__ W2_, const float* __restrict__ W3,
    const float* __restrict__ W4, const float* __restrict__ W5,
    const float* __restrict__ W6, const float* __restrict__ W7,
    uint32_t* __restrict__ dst) {
    int i = blockIdx.x * 256 + threadIdx.x;
    if (i >= 557056) return;
    const float* W;
    int n, kp;
    if (i < 393216) {
        const float* Ws[6] = {W0, W1_, W2_, W3, W4, W5};
        W = Ws[i >> 16];
        int li = i & 65535;
        n = li >> 8; kp = li & 255;
    } else if (i < 524288) {
        W = W6;
        int li = i - 393216;
        n = li >> 9; kp = li & 511;
    } else {
        W = W7;
        int li = i - 524288;
        n = li >> 7; kp = li & 127;
    }
    dst[i] = cvtH2(W[(size_t)(2 * kp) * 256 + n], W[(size_t)(2 * kp + 1) * 256 + n]);
}

// =============================================================================
// Merged 3-way dual-output projection GEMM (fp16 1-product) + e-plane row sums.
// blockIdx.z: 0 -> q-proj, 1 -> k-proj, 2 -> v-proj (transposed write).
// BK=16 kp/stage, 2-stage cp.async, 40960B smem.
// =============================================================================
__global__ __launch_bounds__(256, 2) void gemm2_kernel(
    const uint32_t* __restrict__ qf1, const uint32_t* __restrict__ vr1,
    const uint32_t* __restrict__ w1p,
    const float* __restrict__ bqs, const float* __restrict__ bqe,
    const float* __restrict__ bks, const float* __restrict__ bke,
    const float* __restrict__ bvs, const float* __restrict__ bve,
    uint2* __restrict__ qp, uint2* __restrict__ kp, uint2* __restrict__ vT)
{
    extern __shared__ uint32_t smu[];
    uint32_t* smA  = smu;            // [2][128][20]
    uint32_t* smB1 = smu + 5120;     // [2][64][20]
    uint32_t* smB2 = smu + 7680;     // [2][64][20]

    const int z = blockIdx.z;
    const uint32_t* a1 = (z == 0) ? qf1 : vr1;
    const uint32_t* wa = w1p + ((z == 0) ? 0 : (z == 1) ? 65536 : 131072);
    const uint32_t* wb = w1p + ((z == 0) ? 196608 : (z == 1) ? 262144 : 327680);
    const float* biasA = (z == 0) ? bqs : (z == 1) ? bks : bvs;
    const float* biasB = (z == 0) ? bqe : (z == 1) ? bke : bve;
    uint2* outQK = (z == 0) ? qp : (z == 1) ? kp : nullptr;

    const int Kp = 256;
    const int row0 = blockIdx.y * 128;
    const int col0 = blockIdx.x * 64;
    const int tid  = threadIdx.x;
    const int lane = tid & 31, warp = tid >> 5;
    const int wR = warp >> 1, wC = warp & 1;

    float acc1[2][4][4] = {}, acc2[2][4][4] = {};
    const int nk = Kp / 16;

    const int bt = tid & 127;
    const int br = bt >> 2, bc4 = (bt & 3) * 4;
    uint32_t* smBsel = (tid < 128) ? smB1 : smB2;
    const uint32_t* wsel = (tid < 128) ? wa : wb;

    {
#pragma unroll
        for (int it = 0; it < 2; it++) {
            int i = tid + it * 256;
            int r = i >> 2, c4 = (i & 3) * 4;
            cpa16(&smA[(size_t)r * 20 + c4], a1 + (size_t)(row0 + r) * Kp + c4);
        }
        cpa16(&smBsel[(size_t)br * 20 + bc4], wsel + (size_t)(col0 + br) * Kp + bc4);
        cpa16(&smBsel[(size_t)(br + 32) * 20 + bc4], wsel + (size_t)(col0 + br + 32) * Kp + bc4);
        CP_COMMIT();
    }

    for (int kt = 0; kt < nk; kt++) {
        const int s = kt & 1;
        if (kt + 1 < nk) {
            const int sn = s ^ 1;
            const int k0 = (kt + 1) * 16;
#pragma unroll
            for (int it = 0; it < 2; it++) {
                int i = tid + it * 256;
                int r = i >> 2, c4 = (i & 3) * 4;
                cpa16(&smA[(size_t)(sn * 128 + r) * 20 + c4],
                      a1 + (size_t)(row0 + r) * Kp + k0 + c4);
            }
            cpa16(&smBsel[(size_t)(sn * 64 + br) * 20 + bc4],
                  wsel + (size_t)(col0 + br) * Kp + k0 + bc4);
            cpa16(&smBsel[(size_t)(sn * 64 + br + 32) * 20 + bc4],
                  wsel + (size_t)(col0 + br + 32) * Kp + k0 + bc4);
            CP_COMMIT();
            CP_WAIT1();
        } else {
            CP_WAIT0();
        }
        __syncthreads();

#pragma unroll
        for (int ks = 0; ks < 2; ks++) {
            const int kk = ks * 8 + (lane & 3);
            uint32_t ah[2][4];
#pragma unroll
            for (int i = 0; i < 2; i++) {
                int m = s * 128 + wR * 32 + i * 16 + (lane >> 2);
                ah[i][0] = smA[(size_t)m * 20 + kk];
                ah[i][1] = smA[(size_t)(m + 8) * 20 + kk];
                ah[i][2] = smA[(size_t)m * 20 + kk + 4];
                ah[i][3] = smA[(size_t)(m + 8) * 20 + kk + 4];
            }
#pragma unroll
            for (int j = 0; j < 4; j++) {
                int n = s * 64 + wC * 32 + j * 8 + (lane >> 2);
                uint32_t b10 = smB1[(size_t)n * 20 + kk], b11 = smB1[(size_t)n * 20 + kk + 4];
                uint32_t b20 = smB2[(size_t)n * 20 + kk], b21 = smB2[(size_t)n * 20 + kk + 4];
#pragma unroll
                for (int i = 0; i < 2; i++) {
                    mmah(acc1[i][j], ah[i], b10, b11);
                    mmah(acc2[i][j], ah[i], b20, b21);
                }
            }
        }
        __syncthreads();
    }

    float esum[2][2] = {};
#pragma unroll
    for (int i = 0; i < 2; i++) {
        int r = row0 + wR * 32 + i * 16 + (lane >> 2);
#pragma unroll
        for (int j = 0; j < 4; j++) {
            int c = col0 + wC * 32 + j * 8 + 2 * (lane & 3);
            float ba0 = biasA[c], ba1 = biasA[c + 1];
            float bb0 = biasB[c], bb1 = biasB[c + 1];
#pragma unroll
            for (int half = 0; half < 2; half++) {
                int rr = r + half * 8;
                float va0 = acc1[i][j][half * 2 + 0] + ba0;
                float va1 = acc1[i][j][half * 2 + 1] + ba1;
                float vb0 = acc2[i][j][half * 2 + 0] + bb0;
                float vb1 = acc2[i][j][half * 2 + 1] + bb1;
                esum[i][half] += vb0 * vb0 + vb1 * vb1;
                if (outQK) {
                    outQK[(size_t)rr * 128 + (c >> 1)] =
                        make_uint2(cvtH2(va0, va1), cvtH2(vb0, vb1));
                } else {
                    float pva0 = __shfl_xor_sync(0xffffffffu, va0, 4);
                    float pva1 = __shfl_xor_sync(0xffffffffu, va1, 4);
                    float pvb0 = __shfl_xor_sync(0xffffffffu, vb0, 4);
                    float pvb1 = __shfl_xor_sync(0xffffffffu, vb1, 4);
                    if (((lane >> 2) & 1) == 0) {
                        int bb = rr >> 11;
                        int mp = (rr & 2047) >> 1;
                        size_t base = ((size_t)bb * Hh + c) * 1024 + mp;
                        vT[base]        = make_uint2(cvtH2(va0, pva0), cvtH2(vb0, pvb0));
                        vT[base + 1024] = make_uint2(cvtH2(va1, pva1), cvtH2(vb1, pvb1));
                    }
                }
            }
        }
    }
    if (z < 2) {
        float* dst = (z == 0) ? g_q2 : g_k2;
#pragma unroll
        for (int i = 0; i < 2; i++)
#pragma unroll
            for (int half = 0; half < 2; half++) {
                float s2 = esum[i][half];
                s2 += __shfl_xor_sync(0xffffffffu, s2, 1);
                s2 += __shfl_xor_sync(0xffffffffu, s2, 2);
                if ((lane & 3) == 0) {
                    int rr = row0 + wR * 32 + i * 16 + (lane >> 2) + half * 8;
                    atomicAdd(&dst[rr], s2);
                }
            }
    }
}

// =============================================================================
// Single-output GEMM for MLP (fp16 1-product). Unchanged.
// =============================================================================
__global__ __launch_bounds__(256, 2) void gemmP_kernel(
    const uint32_t* __restrict__ a1, const uint32_t* __restrict__ w1p,
    const float* __restrict__ bias,
    float* __restrict__ outF, uint32_t* __restrict__ outP,
    int Kp, int Nc, int act)
{
    extern __shared__ uint32_t smu[];
    uint32_t* smA = smu;             // [2][128][20]
    uint32_t* smB = smu + 5120;      // [2][128][20]

    const int row0 = blockIdx.y * 128;
    const int col0 = blockIdx.x * 128;
    const int tid  = threadIdx.x;
    const int lane = tid & 31, warp = tid >> 5;
    const int wR = warp >> 1, wC = warp & 1;

    float acc[2][8][4] = {};
    const int nk = Kp / 16;

    {
#pragma unroll
        for (int it = 0; it < 2; it++) {
            int i = tid + it * 256;
            int r = i >> 2, c4 = (i & 3) * 4;
            cpa16(&smA[(size_t)r * 20 + c4], a1 + (size_t)(row0 + r) * Kp + c4);
            cpa16(&smB[(size_t)r * 20 + c4], w1p + (size_t)(col0 + r) * Kp + c4);
        }
        CP_COMMIT();
    }

    for (int kt = 0; kt < nk; kt++) {
        const int s = kt & 1;
        if (kt + 1 < nk) {
            const int sn = s ^ 1;
            const int k0 = (kt + 1) * 16;
#pragma unroll
            for (int it = 0; it < 2; it++) {
                int i = tid + it * 256;
                int r = i >> 2, c4 = (i & 3) * 4;
                cpa16(&smA[(size_t)(sn * 128 + r) * 20 + c4],
                      a1 + (size_t)(row0 + r) * Kp + k0 + c4);
                cpa16(&smB[(size_t)(sn * 128 + r) * 20 + c4],
                      w1p + (size_t)(col0 + r) * Kp + k0 + c4);
            }
            CP_COMMIT();
            CP_WAIT1();
        } else {
            CP_WAIT0();
        }
        __syncthreads();
#pragma unroll
        for (int ks = 0; ks < 2; ks++) {
            const int kk = ks * 8 + (lane & 3);
            uint32_t ah[2][4];
#pragma unroll
            for (int i = 0; i < 2; i++) {
                int m = s * 128 + wR * 32 + i * 16 + (lane >> 2);
                ah[i][0] = smA[(size_t)m * 20 + kk];
                ah[i][1] = smA[(size_t)(m + 8) * 20 + kk];
                ah[i][2] = smA[(size_t)m * 20 + kk + 4];
                ah[i][3] = smA[(size_t)(m + 8) * 20 + kk + 4];
            }
#pragma unroll
            for (int j = 0; j < 8; j++) {
                int n = s * 128 + wC * 64 + j * 8 + (lane >> 2);
                uint32_t b0 = smB[(size_t)n * 20 + kk];
                uint32_t b1 = smB[(size_t)n * 20 + kk + 4];
#pragma unroll
                for (int i = 0; i < 2; i++)
                    mmah(acc[i][j], ah[i], b0, b1);
            }
        }
        __syncthreads();
    }
#pragma unroll
    for (int i = 0; i < 2; i++) {
        int r = row0 + wR * 32 + i * 16 + (lane >> 2);
#pragma unroll
        for (int j = 0; j < 8; j++) {
            int c = col0 + wC * 64 + j * 8 + 2 * (lane & 3);
            float b0 = bias[c], b1 = bias[c + 1];
            float v0 = acc[i][j][0] + b0, v1 = acc[i][j][1] + b1;
            float v2 = acc[i][j][2] + b0, v3 = acc[i][j][3] + b1;
            if (act) {
                v0 = v0 / (1.0f + __expf(-v0));
                v1 = v1 / (1.0f + __expf(-v1));
                v2 = v2 / (1.0f + __expf(-v2));
                v3 = v3 / (1.0f + __expf(-v3));
            }
            if (outP) {
                outP[(size_t)r * (Nc >> 1) + (c >> 1)]       = cvtH2(v0, v1);
                outP[(size_t)(r + 8) * (Nc >> 1) + (c >> 1)] = cvtH2(v2, v3);
            } else {
                *(float2*)&outF[(size_t)r * Nc + c]       = make_float2(v0, v1);
                *(float2*)&outF[(size_t)(r + 8) * Nc + c] = make_float2(v2, v3);
            }
        }
    }
}

// =============================================================================
// Logits: dual fp16 1-product NT GEMM. BK=16 kp/stage (8 stages, 32 mma/stage).
// smQ [2][128][20] uint2 + smK [2][64][20] uint2 = 61440 B.
// =============================================================================
__global__ __launch_bounds__(256, 2) void logitsP_kernel()
{
    extern __shared__ uint32_t smu[];
    uint2* smQ = (uint2*)smu;               // [2][128][20]
    uint2* smK = (uint2*)(smu + 10240);     // [2][64][20]

    const int b  = blockIdx.z;
    const int n0 = blockIdx.y * 128;
    const int m0 = blockIdx.x * 64;
    const int tid = threadIdx.x;
    const int lane = tid & 31, warp = tid >> 5;
    const int wR = warp >> 1, wC = warp & 1;

    const uint2* q2p = g_qp + (size_t)(b * Nn + n0) * 128;
    const uint2* k2p = g_kp + (size_t)(b * Mm + m0) * 128;

    float accS[2][4][4] = {}, accE[2][4][4] = {};
    const int nk = 8;   // 128 kp / 16

    {
#pragma unroll
        for (int it = 0; it < 4; it++) {
            int i = tid + it * 256;          // 0..1023
            int r = i >> 3, c2 = (i & 7) * 2;
            cpa16(&smQ[(size_t)r * 20 + c2], q2p + (size_t)r * 128 + c2);
        }
#pragma unroll
        for (int it = 0; it < 2; it++) {
            int i = tid + it * 256;          // 0..511
            int r = i >> 3, c2 = (i & 7) * 2;
            cpa16(&smK[(size_t)r * 20 + c2], k2p + (size_t)r * 128 + c2);
        }
        CP_COMMIT();
    }

    for (int kt = 0; kt < nk; kt++) {
        const int s = kt & 1;
        if (kt + 1 < nk) {
            const int sn = s ^ 1;
            const int k0 = (kt + 1) * 16;
#pragma unroll
            for (int it = 0; it < 4; it++) {
                int i = tid + it * 256;
                int r = i >> 3, c2 = (i & 7) * 2;
                cpa16(&smQ[(size_t)(sn * 128 + r) * 20 + c2],
                      q2p + (size_t)r * 128 + k0 + c2);
            }
#pragma unroll
            for (int it = 0; it < 2; it++) {
                int i = tid + it * 256;
                int r = i >> 3, c2 = (i & 7) * 2;
                cpa16(&smK[(size_t)(sn * 64 + r) * 20 + c2],
                      k2p + (size_t)r * 128 + k0 + c2);
            }
            CP_COMMIT();
            CP_WAIT1();
        } else {
            CP_WAIT0();
        }
        __syncthreads();

#pragma unroll
        for (int ks = 0; ks < 2; ks++) {
            const int kk = ks * 8 + (lane & 3);
            uint32_t ash[2][4], aeh[2][4];
#pragma unroll
            for (int i = 0; i < 2; i++) {
                int m = s * 128 + wR * 32 + i * 16 + (lane >> 2);
                uint2 p0 = smQ[(size_t)m * 20 + kk];
                uint2 p1 = smQ[(size_t)(m + 8) * 20 + kk];
                uint2 p2 = smQ[(size_t)m * 20 + kk + 4];
                uint2 p3 = smQ[(size_t)(m + 8) * 20 + kk + 4];
                ash[i][0] = p0.x; ash[i][1] = p1.x; ash[i][2] = p2.x; ash[i][3] = p3.x;
                aeh[i][0] = p0.y; aeh[i][1] = p1.y; aeh[i][2] = p2.y; aeh[i][3] = p3.y;
            }
#pragma unroll
            for (int j = 0; j < 4; j++) {
                int n = s * 64 + wC * 32 + j * 8 + (lane >> 2);
                uint2 k0v = smK[(size_t)n * 20 + kk];
                uint2 k1v = smK[(size_t)n * 20 + kk + 4];
#pragma unroll
                for (int i = 0; i < 2; i++) {
                    mmah(accS[i][j], ash[i], k0v.x, k1v.x);
                    mmah(accE[i][j], aeh[i], k0v.y, k1v.y);
                }
            }
        }
        __syncthreads();
    }

    float sumd = 0.0f;
#pragma unroll
    for (int i = 0; i < 2; i++) {
        int n_lo = n0 + wR * 32 + i * 16 + (lane >> 2);
        float q2a = g_q2[b * Nn + n_lo];
        float q2b = g_q2[b * Nn + n_lo + 8];
#pragma unroll
        for (int j = 0; j < 4; j++) {
            int m = m0 + wC * 32 + j * 8 + 2 * (lane & 3);
            float k2a = g_k2[b * Mm + m], k2b = g_k2[b * Mm + m + 1];
            size_t base0 = ((size_t)b * Nn + n_lo) * Mm + m;
            float e0 = accE[i][j][0], e1 = accE[i][j][1];
            sumd += sqrtf(fmaxf(q2a + k2a - 2.0f * e0, 1e-12f))
                  + sqrtf(fmaxf(q2a + k2b - 2.0f * e1, 1e-12f));
            *(uint2*)&g_SE[base0] = make_uint2(cvtH2(accS[i][j][0] * 0.0625f, e0),
                                               cvtH2(accS[i][j][1] * 0.0625f, e1));
            size_t base1 = ((size_t)b * Nn + n_lo + 8) * Mm + m;
            float e2 = accE[i][j][2], e3 = accE[i][j][3];
            sumd += sqrtf(fmaxf(q2b + k2a - 2.0f * e2, 1e-12f))
                  + sqrtf(fmaxf(q2b + k2b - 2.0f * e3, 1e-12f));
            *(uint2*)&g_SE[base1] = make_uint2(cvtH2(accS[i][j][2] * 0.0625f, e2),
                                               cvtH2(accS[i][j][3] * 0.0625f, e3));
        }
    }
    float* red = (float*)smu;
    red[tid] = sumd;
    __syncthreads();
    for (int sred = 128; sred > 0; sred >>= 1) {
        if (tid < sred) red[tid] += red[tid + sred];
        __syncthreads();
    }
    if (tid == 0) atomicAdd(&g_dsum[b], red[0]);
}

// =============================================================================
// Ctx: dual fp16 1-product NN GEMM. BK=32 kp/stage (32 stages, 64 mma/stage).
// smP [2][128][36] u32 + smV [2][64][36] uint2 = 73728 B, 2-stage.
// =============================================================================
__global__ __launch_bounds__(256, 2) void ctxP_kernel()
{
    extern __shared__ uint32_t smu[];
    uint32_t* smP = smu;                    // [2][128][36]
    uint2*    smV = (uint2*)(smu + 9216);   // [2][64][36]

    const int b  = blockIdx.z;
    const int n0 = blockIdx.y * 128;
    const int h0 = blockIdx.x * 64;
    const int tid = threadIdx.x;
    const int lane = tid & 31, warp = tid >> 5;
    const int wR = warp >> 1, wC = warp & 1;

    const uint32_t* p1 = g_p1 + (size_t)(b * Nn + n0) * 1024;
    const uint2* v2 = g_vT2 + ((size_t)b * Hh + h0) * 1024;

    float accS[2][4][4] = {}, accE[2][4][4] = {};
    const int nk = 32;   // 1024 kp / 32

    {
#pragma unroll
        for (int it = 0; it < 4; it++) {
            int i = tid + it * 256;          // 0..1023
            int r = i >> 3, c4 = (i & 7) * 4;
            cpa16(&smP[(size_t)r * 36 + c4], p1 + (size_t)r * 1024 + c4);
            int rv = i >> 4, c2 = (i & 15) * 2;
            cpa16(&smV[(size_t)rv * 36 + c2], v2 + (size_t)rv * 1024 + c2);
        }
        CP_COMMIT();
    }

    for (int kt = 0; kt < nk; kt++) {
        const int s = kt & 1;
        if (kt + 1 < nk) {
            const int sn = s ^ 1;
            const int mp0 = (kt + 1) * 32;
#pragma unroll
            for (int it = 0; it < 4; it++) {
                int i = tid + it * 256;
                int r = i >> 3, c4 = (i & 7) * 4;
                cpa16(&smP[(size_t)(sn * 128 + r) * 36 + c4],
                      p1 + (size_t)r * 1024 + mp0 + c4);
                int rv = i >> 4, c2 = (i & 15) * 2;
                cpa16(&smV[(size_t)(sn * 64 + rv) * 36 + c2],
                      v2 + (size_t)rv * 1024 + mp0 + c2);
            }
            CP_COMMIT();
            CP_WAIT1();
        } else {
            CP_WAIT0();
        }
        __syncthreads();
#pragma unroll
        for (int ks = 0; ks < 4; ks++) {
            const int kk = ks * 8 + (lane & 3);
            uint32_t ph[2][4];
#pragma unroll
            for (int i = 0; i < 2; i++) {
                int m = s * 128 + wR * 32 + i * 16 + (lane >> 2);
                ph[i][0] = smP[(size_t)m * 36 + kk];
                ph[i][1] = smP[(size_t)(m + 8) * 36 + kk];
                ph[i][2] = smP[(size_t)m * 36 + kk + 4];
                ph[i][3] = smP[(size_t)(m + 8) * 36 + kk + 4];
            }
#pragma unroll
            for (int j = 0; j < 4; j++) {
                int n = s * 64 + wC * 32 + j * 8 + (lane >> 2);
                uint2 v0 = smV[(size_t)n * 36 + kk];
                uint2 v1 = smV[(size_t)n * 36 + kk + 4];
#pragma unroll
                for (int i = 0; i < 2; i++) {
                    mmah(accS[i][j], ph[i], v0.x, v1.x);
                    mmah(accE[i][j], ph[i], v0.y, v1.y);
                }
            }
        }
        __syncthreads();
    }
#pragma unroll
    for (int i = 0; i < 2; i++) {
        int n_lo = n0 + wR * 32 + i * 16 + (lane >> 2);
#pragma unroll
        for (int j = 0; j < 4; j++) {
            int h = h0 + wC * 32 + j * 8 + 2 * (lane & 3);
#pragma unroll
            for (int half = 0; half < 2; half++) {
                int n = n_lo + half * 8;
                float cs0 = accS[i][j][half * 2 + 0], cs1 = accS[i][j][half * 2 + 1];
                float ce0 = accE[i][j][half * 2 + 0], ce1 = accE[i][j][half * 2 + 1];
                size_t fb = ((size_t)b * Nn + n) * 512;
                g_f1[fb + (h >> 1)]       = cvtH2(cs0, cs1);
                g_f1[fb + 128 + (h >> 1)] = cvtH2(ce0, ce1);
                g_f1[fb + 256 + (h >> 1)] = cvtH2(cs0 - ce0, cs1 - ce1);
                g_f1[fb + 384 + (h >> 1)] = cvtH2(cs0 * ce0, cs1 * ce1);
            }
        }
    }
}

// ---------------- softmax: rebuild logits from packed {S,E} + pi ----------------
__global__ void softmax_kernel(const float* __restrict__ pi_star,
                               const float* __restrict__ gamma_p,
                               const float* __restrict__ ew_p) {
    const int row = blockIdx.x;
    const int b   = row / Nn;
    const float sc = fmaxf(g_dsum[b] * (1.0f / ((float)Nn * (float)Mm)), 1e-4f);
    const float invsc = ew_p[0] / sc;
    const float g = gamma_p[0];
    const float q2v = g_q2[row];
    const size_t base = (size_t)row * Mm;
    const int c0 = threadIdx.x * 8;
    float v[8];
    float mx = -1e30f;
#pragma unroll
    for (int q = 0; q < 2; q++) {
        uint4 se = *(const uint4*)&g_SE[base + c0 + q * 4];
        float4 piv = *(const float4*)&pi_star[base + c0 + q * 4];
        float4 k2v = *(const float4*)&g_k2[b * Mm + c0 + q * 4];
        uint32_t ses[4] = {se.x, se.y, se.z, se.w};
        float pis[4] = {piv.x, piv.y, piv.z, piv.w};
        float k2s[4] = {k2v.x, k2v.y, k2v.z, k2v.w};
#pragma unroll
        for (int t = 0; t < 4; t++) {
            float S = hlo(ses[t]), E = hhi(ses[t]);
            float d = sqrtf(fmaxf(q2v + k2s[t] - 2.0f * E, 1e-12f));
            v[q * 4 + t] = S + g * __logf(fmaxf(pis[t], 1e-9f)) - d * invsc;
        }
    }
#pragma unroll
    for (int t = 0; t < 8; t++) mx = fmaxf(mx, v[t]);
    __shared__ float sh[8];
    __shared__ float bc;
    int lane = threadIdx.x & 31, wid = threadIdx.x >> 5;
    float wm = warpRedMax(mx);
    if (lane == 0) sh[wid] = wm;
    __syncthreads();
    if (wid == 0) {
        float t = (lane < 8) ? sh[lane] : -1e30f;
        t = warpRedMax(t);
        if (lane == 0) bc = t;
    }
    __syncthreads();
    mx = bc;
    float sum = 0.0f;
#pragma unroll
    for (int t = 0; t < 8; t++) {
        v[t] = __expf(v[t] - mx);
        sum += v[t];
    }
    __syncthreads();
    float ws = warpRedSum(sum);
    if (lane == 0) sh[wid] = ws;
    __syncthreads();
    if (wid == 0) {
        float t = (lane < 8) ? sh[lane] : 0.0f;
        t = warpRedSum(t);
        if (lane == 0) bc = t;
    }
    __syncthreads();
    const float inv = 1.0f / bc;
    const size_t pbase = (size_t)row * 1024 + threadIdx.x * 4;
#pragma unroll
    for (int p = 0; p < 4; p++)
        g_p1[pbase + p] = cvtH2(v[2 * p] * inv, v[2 * p + 1] * inv);
}

// ---------------- launch ----------------
extern "C" void kernel_launch(void* const* d_in, const int* in_sizes, int n_in,
                              void* d_out, int out_size) {
    const float* q_fp  = (const float*)d_in[0];
    const float* v_ret = (const float*)d_in[1];
    const float* pi    = (const float*)d_in[2];
    const float* Wqs = (const float*)d_in[3];  const float* bqs = (const float*)d_in[4];
    const float* Wks = (const float*)d_in[5];  const float* bks = (const float*)d_in[6];
    const float* Wvs = (const float*)d_in[7];  const float* bvs = (const float*)d_in[8];
    const float* Wqe = (const float*)d_in[9];  const float* bqe = (const float*)d_in[10];
    const float* Wke = (const float*)d_in[11]; const float* bke = (const float*)d_in[12];
    const float* Wve = (const float*)d_in[13]; const float* bve = (const float*)d_in[14];
    const float* W1  = (const float*)d_in[15]; const float* b1  = (const float*)d_in[16];
    const float* W2  = (const float*)d_in[17]; const float* b2  = (const float*)d_in[18];
    const float* gamma = (const float*)d_in[19];
    const float* ew    = (const float*)d_in[20];
    float* out = (float*)d_out;

    uint32_t *qf1, *vr1, *w1p, *f1, *h1;
    uint2 *qp, *kp, *vT2;
    cudaGetSymbolAddress((void**)&qf1, g_qf1);
    cudaGetSymbolAddress((void**)&vr1, g_vr1);
    cudaGetSymbolAddress((void**)&w1p, g_w1p);
    cudaGetSymbolAddress((void**)&qp, g_qp);
    cudaGetSymbolAddress((void**)&kp, g_kp);
    cudaGetSymbolAddress((void**)&vT2, g_vT2);
    cudaGetSymbolAddress((void**)&f1, g_f1);
    cudaGetSymbolAddress((void**)&h1, g_h1);

    const int G2_SMEM    = 10240 * 4;    // 40960
    const int GEMM_SMEM  = 10240 * 4;
    const int LOGIT_SMEM = 15360 * 4;    // 61440
    const int CTX_SMEM   = 18432 * 4;    // 73728
    cudaFuncSetAttribute(gemm2_kernel,   cudaFuncAttributeMaxDynamicSharedMemorySize, G2_SMEM);
    cudaFuncSetAttribute(gemmP_kernel,   cudaFuncAttributeMaxDynamicSharedMemorySize, GEMM_SMEM);
    cudaFuncSetAttribute(logitsP_kernel, cudaFuncAttributeMaxDynamicSharedMemorySize, LOGIT_SMEM);
    cudaFuncSetAttribute(ctxP_kernel,    cudaFuncAttributeMaxDynamicSharedMemorySize, CTX_SMEM);

    uint32_t* wo[8] = {w1p, w1p+65536, w1p+131072, w1p+196608, w1p+262144, w1p+327680,
                       w1p+393216, w1p+524288};

    // merged prep (also zeroes q2/k2/dsum)
    dim3 gr((Bb*Nn*DIN/2 + 255)/256, 2);
    pack_rows_kernel<<<gr, 256>>>(q_fp, v_ret, qf1, vr1, Bb*Nn*DIN/2);
    pack_all_weights_kernel<<<(557056 + 255)/256, 256>>>(
        Wqs, Wks, Wvs, Wqe, Wke, Wve, W1, W2, w1p);

    // merged 3-way projections (+ q2/k2 row sums via atomics)
    dim3 gp(4, (Bb * Nn) / 128, 3);
    gemm2_kernel<<<gp, 256, G2_SMEM>>>(qf1, vr1, w1p,
                                       bqs, bqe, bks, bke, bvs, bve,
                                       qp, kp, vT2);

    dim3 gl(Mm / 64, Nn / 128, Bb);
    logitsP_kernel<<<gl, 256, LOGIT_SMEM>>>();

    softmax_kernel<<<Bb * Nn, 256>>>(pi, gamma, ew);

    dim3 gc(Hh / 64, Nn / 128, Bb);
    ctxP_kernel<<<gc, 256, CTX_SMEM>>>();

    dim3 gm(2, (Bb * Nn) / 128);
    gemmP_kernel<<<gm, 256, GEMM_SMEM>>>(f1, wo[6], b1, nullptr, h1, 512, 256, 1);
    gemmP_kernel<<<gm, 256, GEMM_SMEM>>>(h1, wo[7], b2, out, nullptr, 128, 256, 0);
}

// round 17
// speedup vs baseline: 2.4519x; 1.0122x over previous
#include <cuda_runtime.h>
#include <cuda_fp16.h>
#include <cstdint>

#define Bb 8
#define Nn 2048
#define Mm 2048
#define DIN 512
#define Hh 256

// ---------------- scratch (device globals; no allocs allowed) ----------------
__device__ uint32_t g_qf1[(size_t)Bb*Nn*(DIN/2)];
__device__ uint32_t g_vr1[(size_t)Bb*Mm*(DIN/2)];
__device__ uint32_t g_w1p[6*65536 + 131072 + 32768];
__device__ uint2 g_qp[(size_t)Bb*Nn*128];
__device__ uint2 g_kp[(size_t)Bb*Mm*128];
__device__ uint2 g_vT2[(size_t)Bb*Hh*1024];
__device__ uint32_t g_SE[(size_t)Bb*Nn*Mm];
__device__ uint32_t g_p1[(size_t)Bb*Nn*1024];
__device__ uint32_t g_f1[(size_t)Bb*Nn*512];
__device__ uint32_t g_h1[(size_t)Bb*Nn*128];
__device__ float g_q2[Bb*Nn], g_k2[Bb*Mm], g_dsum[Bb];

// ---------------- helpers ----------------
__device__ __forceinline__ uint32_t cvtH2(float f0, float f1) {
    __half h0 = __float2half(f0), h1 = __float2half(f1);
    return (uint32_t)__half_as_ushort(h0) | ((uint32_t)__half_as_ushort(h1) << 16);
}
__device__ __forceinline__ float hlo(uint32_t u) {
    return __half2float(__ushort_as_half((unsigned short)(u & 0xffff)));
}
__device__ __forceinline__ float hhi(uint32_t u) {
    return __half2float(__ushort_as_half((unsigned short)(u >> 16)));
}
__device__ __forceinline__ void mmah(float* d, const uint32_t* a, uint32_t b0, uint32_t b1) {
    asm volatile(
        "mma.sync.aligned.m16n8k16.row.col.f32.f16.f16.f32 "
        "{%0,%1,%2,%3}, {%4,%5,%6,%7}, {%8,%9}, {%0,%1,%2,%3};\n"
        : "+f"(d[0]), "+f"(d[1]), "+f"(d[2]), "+f"(d[3])
        : "r"(a[0]), "r"(a[1]), "r"(a[2]), "r"(a[3]), "r"(b0), "r"(b1));
}
__device__ __forceinline__ void cpa16(void* smem, const void* gmem) {
    uint32_t s = (uint32_t)__cvta_generic_to_shared(smem);
    asm volatile("cp.async.cg.shared.global [%0], [%1], 16;\n" :: "r"(s), "l"(gmem));
}
#define CP_COMMIT() asm volatile("cp.async.commit_group;\n")
#define CP_WAIT1()  asm volatile("cp.async.wait_group 1;\n")
#define CP_WAIT0()  asm volatile("cp.async.wait_group 0;\n")

__device__ __forceinline__ float warpRedSum(float v) {
#pragma unroll
    for (int o = 16; o > 0; o >>= 1) v += __shfl_xor_sync(0xffffffffu, v, o);
    return v;
}
__device__ __forceinline__ float warpRedMax(float v) {
#pragma unroll
    for (int o = 16; o > 0; o >>= 1) v = fmaxf(v, __shfl_xor_sync(0xffffffffu, v, o));
    return v;
}

// ---------------- merged prep kernels ----------------
__global__ void pack_rows_kernel(const float* __restrict__ srcA,
                                 const float* __restrict__ srcB,
                                 uint32_t* __restrict__ dstA,
                                 uint32_t* __restrict__ dstB, int npairs) {
    int i = blockIdx.x * 256 + threadIdx.x;
    if (i >= npairs) return;
    if (blockIdx.y == 0) {
        if (i < Bb * Nn) g_q2[i] = 0.0f;
        if (i < Bb * Mm) g_k2[i] = 0.0f;
        if (i < Bb) g_dsum[i] = 0.0f;
    }
    const float* src = blockIdx.y ? srcB : srcA;
    uint32_t* dst = blockIdx.y ? dstB : dstA;
    float2 f = ((const float2*)src)[i];
    dst[i] = cvtH2(f.x, f.y);
}
__global__ void pack_all_weights_kernel(
    const float* __restrict__ W0, const float* __restrict__ W1_,
    const float* __restrict__ W2_, const float* __restrict__ W3,
    const float* __restrict__ W4, const float* __restrict__ W5,
    const float* __restrict__ W6, const float* __restrict__ W7,
    uint32_t* __restrict__ dst) {
    int i = blockIdx.x * 256 + threadIdx.x;
    if (i >= 557056) return;
    const float* W;
    int n, kp;
    if (i < 393216) {
        const float* Ws[6] = {W0, W1_, W2_, W3, W4, W5};
        W = Ws[i >> 16];
        int li = i & 65535;
        n = li >> 8; kp = li & 255;
    } else if (i < 524288) {
        W = W6;
        int li = i - 393216;
        n = li >> 9; kp = li & 511;
    } else {
        W = W7;
        int li = i - 524288;
        n = li >> 7; kp = li & 127;
    }
    dst[i] = cvtH2(W[(size_t)(2 * kp) * 256 + n], W[(size_t)(2 * kp + 1) * 256 + n]);
}

// =============================================================================
// Merged 3-way dual-output projection GEMM (fp16 1-product) + e-plane row sums.
// BK=16 kp/stage, 2-stage, 40960B smem. 32-bit immediate-friendly indexing.
// =============================================================================
__global__ __launch_bounds__(256, 2) void gemm2_kernel(
    const uint32_t* __restrict__ qf1, const uint32_t* __restrict__ vr1,
    const uint32_t* __restrict__ w1p,
    const float* __restrict__ bqs, const float* __restrict__ bqe,
    const float* __restrict__ bks, const float* __restrict__ bke,
    const float* __restrict__ bvs, const float* __restrict__ bve,
    uint2* __restrict__ qp, uint2* __restrict__ kp, uint2* __restrict__ vT)
{
    extern __shared__ uint32_t smu[];
    uint32_t* smA  = smu;            // [2][128][20]
    uint32_t* smB1 = smu + 5120;     // [2][64][20]
    uint32_t* smB2 = smu + 7680;     // [2][64][20]

    const int z = blockIdx.z;
    const uint32_t* a1 = (z == 0) ? qf1 : vr1;
    const uint32_t* wa = w1p + ((z == 0) ? 0 : (z == 1) ? 65536 : 131072);
    const uint32_t* wb = w1p + ((z == 0) ? 196608 : (z == 1) ? 262144 : 327680);
    const float* biasA = (z == 0) ? bqs : (z == 1) ? bks : bvs;
    const float* biasB = (z == 0) ? bqe : (z == 1) ? bke : bve;
    uint2* outQK = (z == 0) ? qp : (z == 1) ? kp : nullptr;

    const int Kp = 256;
    const int row0 = blockIdx.y * 128;
    const int col0 = blockIdx.x * 64;
    const int tid  = threadIdx.x;
    const int lane = tid & 31, warp = tid >> 5;
    const int wR = warp >> 1, wC = warp & 1;

    float acc1[2][4][4] = {}, acc2[2][4][4] = {};
    const int nk = Kp / 16;

    const int bt = tid & 127;
    const int br = bt >> 2, bc4 = (bt & 3) * 4;
    uint32_t* smBsel = (tid < 128) ? smB1 : smB2;
    const uint32_t* wsel = (tid < 128) ? wa : wb;

    const int aBase0 = (wR * 32 + (lane >> 2)) * 20 + (lane & 3);   // stage 0
    const int bBase0 = (wC * 32 + (lane >> 2)) * 20 + (lane & 3);

    {
#pragma unroll
        for (int it = 0; it < 2; it++) {
            int i = tid + it * 256;
            int r = i >> 2, c4 = (i & 3) * 4;
            cpa16(&smA[r * 20 + c4], a1 + (size_t)(row0 + r) * Kp + c4);
        }
        cpa16(&smBsel[br * 20 + bc4], wsel + (size_t)(col0 + br) * Kp + bc4);
        cpa16(&smBsel[(br + 32) * 20 + bc4], wsel + (size_t)(col0 + br + 32) * Kp + bc4);
        CP_COMMIT();
    }

    for (int kt = 0; kt < nk; kt++) {
        const int s = kt & 1;
        if (kt + 1 < nk) {
            const int sn = s ^ 1;
            const int k0 = (kt + 1) * 16;
#pragma unroll
            for (int it = 0; it < 2; it++) {
                int i = tid + it * 256;
                int r = i >> 2, c4 = (i & 3) * 4;
                cpa16(&smA[(sn * 128 + r) * 20 + c4],
                      a1 + (size_t)(row0 + r) * Kp + k0 + c4);
            }
            cpa16(&smBsel[(sn * 64 + br) * 20 + bc4],
                  wsel + (size_t)(col0 + br) * Kp + k0 + bc4);
            cpa16(&smBsel[(sn * 64 + br + 32) * 20 + bc4],
                  wsel + (size_t)(col0 + br + 32) * Kp + k0 + bc4);
            CP_COMMIT();
            CP_WAIT1();
        } else {
            CP_WAIT0();
        }
        __syncthreads();

        const int aS = aBase0 + s * 2560;
        const int bS = bBase0 + s * 1280;
#pragma unroll
        for (int ks = 0; ks < 2; ks++) {
            const int ab = aS + ks * 8;
            uint32_t ah[2][4];
#pragma unroll
            for (int i = 0; i < 2; i++) {
                const int o = ab + i * 320;
                ah[i][0] = smA[o];       ah[i][1] = smA[o + 160];
                ah[i][2] = smA[o + 4];   ah[i][3] = smA[o + 164];
            }
            const int bb = bS + ks * 8;
#pragma unroll
            for (int j = 0; j < 4; j++) {
                const int o = bb + j * 160;
                uint32_t b10 = smB1[o], b11 = smB1[o + 4];
                uint32_t b20 = smB2[o], b21 = smB2[o + 4];
#pragma unroll
                for (int i = 0; i < 2; i++) {
                    mmah(acc1[i][j], ah[i], b10, b11);
                    mmah(acc2[i][j], ah[i], b20, b21);
                }
            }
        }
        __syncthreads();
    }

    float esum[2][2] = {};
#pragma unroll
    for (int i = 0; i < 2; i++) {
        int r = row0 + wR * 32 + i * 16 + (lane >> 2);
#pragma unroll
        for (int j = 0; j < 4; j++) {
            int c = col0 + wC * 32 + j * 8 + 2 * (lane & 3);
            float ba0 = biasA[c], ba1 = biasA[c + 1];
            float bb0 = biasB[c], bb1 = biasB[c + 1];
#pragma unroll
            for (int half = 0; half < 2; half++) {
                int rr = r + half * 8;
                float va0 = acc1[i][j][half * 2 + 0] + ba0;
                float va1 = acc1[i][j][half * 2 + 1] + ba1;
                float vb0 = acc2[i][j][half * 2 + 0] + bb0;
                float vb1 = acc2[i][j][half * 2 + 1] + bb1;
                esum[i][half] += vb0 * vb0 + vb1 * vb1;
                if (outQK) {
                    outQK[(size_t)rr * 128 + (c >> 1)] =
                        make_uint2(cvtH2(va0, va1), cvtH2(vb0, vb1));
                } else {
                    float pva0 = __shfl_xor_sync(0xffffffffu, va0, 4);
                    float pva1 = __shfl_xor_sync(0xffffffffu, va1, 4);
                    float pvb0 = __shfl_xor_sync(0xffffffffu, vb0, 4);
                    float pvb1 = __shfl_xor_sync(0xffffffffu, vb1, 4);
                    if (((lane >> 2) & 1) == 0) {
                        int bb = rr >> 11;
                        int mp = (rr & 2047) >> 1;
                        size_t base = ((size_t)bb * Hh + c) * 1024 + mp;
                        vT[base]        = make_uint2(cvtH2(va0, pva0), cvtH2(vb0, pvb0));
                        vT[base + 1024] = make_uint2(cvtH2(va1, pva1), cvtH2(vb1, pvb1));
                    }
                }
            }
        }
    }
    if (z < 2) {
        float* dst = (z == 0) ? g_q2 : g_k2;
#pragma unroll
        for (int i = 0; i < 2; i++)
#pragma unroll
            for (int half = 0; half < 2; half++) {
                float s2 = esum[i][half];
                s2 += __shfl_xor_sync(0xffffffffu, s2, 1);
                s2 += __shfl_xor_sync(0xffffffffu, s2, 2);
                if ((lane & 3) == 0) {
                    int rr = row0 + wR * 32 + i * 16 + (lane >> 2) + half * 8;
                    atomicAdd(&dst[rr], s2);
                }
            }
    }
}

// =============================================================================
// Single-output GEMM for MLP (fp16 1-product). 32-bit indexing.
// =============================================================================
__global__ __launch_bounds__(256, 2) void gemmP_kernel(
    const uint32_t* __restrict__ a1, const uint32_t* __restrict__ w1p,
    const float* __restrict__ bias,
    float* __restrict__ outF, uint32_t* __restrict__ outP,
    int Kp, int Nc, int act)
{
    extern __shared__ uint32_t smu[];
    uint32_t* smA = smu;             // [2][128][20]
    uint32_t* smB = smu + 5120;      // [2][128][20]

    const int row0 = blockIdx.y * 128;
    const int col0 = blockIdx.x * 128;
    const int tid  = threadIdx.x;
    const int lane = tid & 31, warp = tid >> 5;
    const int wR = warp >> 1, wC = warp & 1;

    float acc[2][8][4] = {};
    const int nk = Kp / 16;

    const int aBase0 = (wR * 32 + (lane >> 2)) * 20 + (lane & 3);
    const int bBase0 = (wC * 64 + (lane >> 2)) * 20 + (lane & 3);

    {
#pragma unroll
        for (int it = 0; it < 2; it++) {
            int i = tid + it * 256;
            int r = i >> 2, c4 = (i & 3) * 4;
            cpa16(&smA[r * 20 + c4], a1 + (size_t)(row0 + r) * Kp + c4);
            cpa16(&smB[r * 20 + c4], w1p + (size_t)(col0 + r) * Kp + c4);
        }
        CP_COMMIT();
    }

    for (int kt = 0; kt < nk; kt++) {
        const int s = kt & 1;
        if (kt + 1 < nk) {
            const int sn = s ^ 1;
            const int k0 = (kt + 1) * 16;
#pragma unroll
            for (int it = 0; it < 2; it++) {
                int i = tid + it * 256;
                int r = i >> 2, c4 = (i & 3) * 4;
                cpa16(&smA[(sn * 128 + r) * 20 + c4],
                      a1 + (size_t)(row0 + r) * Kp + k0 + c4);
                cpa16(&smB[(sn * 128 + r) * 20 + c4],
                      w1p + (size_t)(col0 + r) * Kp + k0 + c4);
            }
            CP_COMMIT();
            CP_WAIT1();
        } else {
            CP_WAIT0();
        }
        __syncthreads();
        const int aS = aBase0 + s * 2560;
        const int bS = bBase0 + s * 2560;
#pragma unroll
        for (int ks = 0; ks < 2; ks++) {
            const int ab = aS + ks * 8;
            uint32_t ah[2][4];
#pragma unroll
            for (int i = 0; i < 2; i++) {
                const int o = ab + i * 320;
                ah[i][0] = smA[o];       ah[i][1] = smA[o + 160];
                ah[i][2] = smA[o + 4];   ah[i][3] = smA[o + 164];
            }
            const int bb = bS + ks * 8;
#pragma unroll
            for (int j = 0; j < 8; j++) {
                const int o = bb + j * 160;
                uint32_t b0 = smB[o];
                uint32_t b1 = smB[o + 4];
#pragma unroll
                for (int i = 0; i < 2; i++)
                    mmah(acc[i][j], ah[i], b0, b1);
            }
        }
        __syncthreads();
    }
#pragma unroll
    for (int i = 0; i < 2; i++) {
        int r = row0 + wR * 32 + i * 16 + (lane >> 2);
#pragma unroll
        for (int j = 0; j < 8; j++) {
            int c = col0 + wC * 64 + j * 8 + 2 * (lane & 3);
            float b0 = bias[c], b1 = bias[c + 1];
            float v0 = acc[i][j][0] + b0, v1 = acc[i][j][1] + b1;
            float v2 = acc[i][j][2] + b0, v3 = acc[i][j][3] + b1;
            if (act) {
                v0 = v0 / (1.0f + __expf(-v0));
                v1 = v1 / (1.0f + __expf(-v1));
                v2 = v2 / (1.0f + __expf(-v2));
                v3 = v3 / (1.0f + __expf(-v3));
            }
            if (outP) {
                outP[(size_t)r * (Nc >> 1) + (c >> 1)]       = cvtH2(v0, v1);
                outP[(size_t)(r + 8) * (Nc >> 1) + (c >> 1)] = cvtH2(v2, v3);
            } else {
                *(float2*)&outF[(size_t)r * Nc + c]       = make_float2(v0, v1);
                *(float2*)&outF[(size_t)(r + 8) * Nc + c] = make_float2(v2, v3);
            }
        }
    }
}

// =============================================================================
// Logits: dual fp16 1-product NT GEMM. BK=16 kp/stage, 61440B smem.
// 32-bit immediate-friendly indexing (uint2 strides: row=20 uint2).
// =============================================================================
__global__ __launch_bounds__(256, 2) void logitsP_kernel()
{
    extern __shared__ uint32_t smu[];
    uint2* smQ = (uint2*)smu;               // [2][128][20]
    uint2* smK = (uint2*)(smu + 10240);     // [2][64][20]

    const int b  = blockIdx.z;
    const int n0 = blockIdx.y * 128;
    const int m0 = blockIdx.x * 64;
    const int tid = threadIdx.x;
    const int lane = tid & 31, warp = tid >> 5;
    const int wR = warp >> 1, wC = warp & 1;

    const uint2* q2p = g_qp + (size_t)(b * Nn + n0) * 128;
    const uint2* k2p = g_kp + (size_t)(b * Mm + m0) * 128;

    float accS[2][4][4] = {}, accE[2][4][4] = {};
    const int nk = 8;

    const int aBase0 = (wR * 32 + (lane >> 2)) * 20 + (lane & 3);
    const int bBase0 = (wC * 32 + (lane >> 2)) * 20 + (lane & 3);

    {
#pragma unroll
        for (int it = 0; it < 4; it++) {
            int i = tid + it * 256;
            int r = i >> 3, c2 = (i & 7) * 2;
            cpa16(&smQ[r * 20 + c2], q2p + (size_t)r * 128 + c2);
        }
#pragma unroll
        for (int it = 0; it < 2; it++) {
            int i = tid + it * 256;
            int r = i >> 3, c2 = (i & 7) * 2;
            cpa16(&smK[r * 20 + c2], k2p + (size_t)r * 128 + c2);
        }
        CP_COMMIT();
    }

    for (int kt = 0; kt < nk; kt++) {
        const int s = kt & 1;
        if (kt + 1 < nk) {
            const int sn = s ^ 1;
            const int k0 = (kt + 1) * 16;
#pragma unroll
            for (int it = 0; it < 4; it++) {
                int i = tid + it * 256;
                int r = i >> 3, c2 = (i & 7) * 2;
                cpa16(&smQ[(sn * 128 + r) * 20 + c2],
                      q2p + (size_t)r * 128 + k0 + c2);
            }
#pragma unroll
            for (int it = 0; it < 2; it++) {
                int i = tid + it * 256;
                int r = i >> 3, c2 = (i & 7) * 2;
                cpa16(&smK[(sn * 64 + r) * 20 + c2],
                      k2p + (size_t)r * 128 + k0 + c2);
            }
            CP_COMMIT();
            CP_WAIT1();
        } else {
            CP_WAIT0();
        }
        __syncthreads();

        const int aS = aBase0 + s * 2560;
        const int bS = bBase0 + s * 1280;
#pragma unroll
        for (int ks = 0; ks < 2; ks++) {
            const int ab = aS + ks * 8;
            uint32_t ash[2][4], aeh[2][4];
#pragma unroll
            for (int i = 0; i < 2; i++) {
                const int o = ab + i * 320;
                uint2 p0 = smQ[o];
                uint2 p1 = smQ[o + 160];
                uint2 p2 = smQ[o + 4];
                uint2 p3 = smQ[o + 164];
                ash[i][0] = p0.x; ash[i][1] = p1.x; ash[i][2] = p2.x; ash[i][3] = p3.x;
                aeh[i][0] = p0.y; aeh[i][1] = p1.y; aeh[i][2] = p2.y; aeh[i][3] = p3.y;
            }
            const int bb = bS + ks * 8;
#pragma unroll
            for (int j = 0; j < 4; j++) {
                const int o = bb + j * 160;
                uint2 k0v = smK[o];
                uint2 k1v = smK[o + 4];
#pragma unroll
                for (int i = 0; i < 2; i++) {
                    mmah(accS[i][j], ash[i], k0v.x, k1v.x);
                    mmah(accE[i][j], aeh[i], k0v.y, k1v.y);
                }
            }
        }
        __syncthreads();
    }

    float sumd = 0.0f;
#pragma unroll
    for (int i = 0; i < 2; i++) {
        int n_lo = n0 + wR * 32 + i * 16 + (lane >> 2);
        float q2a = g_q2[b * Nn + n_lo];
        float q2b = g_q2[b * Nn + n_lo + 8];
#pragma unroll
        for (int j = 0; j < 4; j++) {
            int m = m0 + wC * 32 + j * 8 + 2 * (lane & 3);
            float k2a = g_k2[b * Mm + m], k2b = g_k2[b * Mm + m + 1];
            size_t base0 = ((size_t)b * Nn + n_lo) * Mm + m;
            float e0 = accE[i][j][0], e1 = accE[i][j][1];
            sumd += sqrtf(fmaxf(q2a + k2a - 2.0f * e0, 1e-12f))
                  + sqrtf(fmaxf(q2a + k2b - 2.0f * e1, 1e-12f));
            *(uint2*)&g_SE[base0] = make_uint2(cvtH2(accS[i][j][0] * 0.0625f, e0),
                                               cvtH2(accS[i][j][1] * 0.0625f, e1));
            size_t base1 = ((size_t)b * Nn + n_lo + 8) * Mm + m;
            float e2 = accE[i][j][2], e3 = accE[i][j][3];
            sumd += sqrtf(fmaxf(q2b + k2a - 2.0f * e2, 1e-12f))
                  + sqrtf(fmaxf(q2b + k2b - 2.0f * e3, 1e-12f));
            *(uint2*)&g_SE[base1] = make_uint2(cvtH2(accS[i][j][2] * 0.0625f, e2),
                                               cvtH2(accS[i][j][3] * 0.0625f, e3));
        }
    }
    float* red = (float*)smu;
    red[tid] = sumd;
    __syncthreads();
    for (int sred = 128; sred > 0; sred >>= 1) {
        if (tid < sred) red[tid] += red[tid + sred];
        __syncthreads();
    }
    if (tid == 0) atomicAdd(&g_dsum[b], red[0]);
}

// =============================================================================
// Ctx: dual fp16 1-product NN GEMM. BK=32 kp/stage, 73728B smem, 2-stage.
// 32-bit immediate-friendly indexing.
// =============================================================================
__global__ __launch_bounds__(256, 2) void ctxP_kernel()
{
    extern __shared__ uint32_t smu[];
    uint32_t* smP = smu;                    // [2][128][36]
    uint2*    smV = (uint2*)(smu + 9216);   // [2][64][36]

    const int b  = blockIdx.z;
    const int n0 = blockIdx.y * 128;
    const int h0 = blockIdx.x * 64;
    const int tid = threadIdx.x;
    const int lane = tid & 31, warp = tid >> 5;
    const int wR = warp >> 1, wC = warp & 1;

    const uint32_t* p1 = g_p1 + (size_t)(b * Nn + n0) * 1024;
    const uint2* v2 = g_vT2 + ((size_t)b * Hh + h0) * 1024;

    float accS[2][4][4] = {}, accE[2][4][4] = {};
    const int nk = 32;

    const int aBase0 = (wR * 32 + (lane >> 2)) * 36 + (lane & 3);
    const int bBase0 = (wC * 32 + (lane >> 2)) * 36 + (lane & 3);

    {
#pragma unroll
        for (int it = 0; it < 4; it++) {
            int i = tid + it * 256;
            int r = i >> 3, c4 = (i & 7) * 4;
            cpa16(&smP[r * 36 + c4], p1 + (size_t)r * 1024 + c4);
            int rv = i >> 4, c2 = (i & 15) * 2;
            cpa16(&smV[rv * 36 + c2], v2 + (size_t)rv * 1024 + c2);
        }
        CP_COMMIT();
    }

    for (int kt = 0; kt < nk; kt++) {
        const int s = kt & 1;
        if (kt + 1 < nk) {
            const int sn = s ^ 1;
            const int mp0 = (kt + 1) * 32;
#pragma unroll
            for (int it = 0; it < 4; it++) {
                int i = tid + it * 256;
                int r = i >> 3, c4 = (i & 7) * 4;
                cpa16(&smP[(sn * 128 + r) * 36 + c4],
                      p1 + (size_t)r * 1024 + mp0 + c4);
                int rv = i >> 4, c2 = (i & 15) * 2;
                cpa16(&smV[(sn * 64 + rv) * 36 + c2],
                      v2 + (size_t)rv * 1024 + mp0 + c2);
            }
            CP_COMMIT();
            CP_WAIT1();
        } else {
            CP_WAIT0();
        }
        __syncthreads();
        const int aS = aBase0 + s * 4608;
        const int bS = bBase0 + s * 2304;
#pragma unroll
        for (int ks = 0; ks < 4; ks++) {
            const int ab = aS + ks * 8;
            uint32_t ph[2][4];
#pragma unroll
            for (int i = 0; i < 2; i++) {
                const int o = ab + i * 576;
                ph[i][0] = smP[o];       ph[i][1] = smP[o + 288];
                ph[i][2] = smP[o + 4];   ph[i][3] = smP[o + 292];
            }
            const int bb = bS + ks * 8;
#pragma unroll
            for (int j = 0; j < 4; j++) {
                const int o = bb + j * 288;
                uint2 v0 = smV[o];
                uint2 v1 = smV[o + 4];
#pragma unroll
                for (int i = 0; i < 2; i++) {
                    mmah(accS[i][j], ph[i], v0.x, v1.x);
                    mmah(accE[i][j], ph[i], v0.y, v1.y);
                }
            }
        }
        __syncthreads();
    }
#pragma unroll
    for (int i = 0; i < 2; i++) {
        int n_lo = n0 + wR * 32 + i * 16 + (lane >> 2);
#pragma unroll
        for (int j = 0; j < 4; j++) {
            int h = h0 + wC * 32 + j * 8 + 2 * (lane & 3);
#pragma unroll
            for (int half = 0; half < 2; half++) {
                int n = n_lo + half * 8;
                float cs0 = accS[i][j][half * 2 + 0], cs1 = accS[i][j][half * 2 + 1];
                float ce0 = accE[i][j][half * 2 + 0], ce1 = accE[i][j][half * 2 + 1];
                size_t fb = ((size_t)b * Nn + n) * 512;
                g_f1[fb + (h >> 1)]       = cvtH2(cs0, cs1);
                g_f1[fb + 128 + (h >> 1)] = cvtH2(ce0, ce1);
                g_f1[fb + 256 + (h >> 1)] = cvtH2(cs0 - ce0, cs1 - ce1);
                g_f1[fb + 384 + (h >> 1)] = cvtH2(cs0 * ce0, cs1 * ce1);
            }
        }
    }
}

// ---------------- softmax ----------------
__global__ void softmax_kernel(const float* __restrict__ pi_star,
                               const float* __restrict__ gamma_p,
                               const float* __restrict__ ew_p) {
    const int row = blockIdx.x;
    const int b   = row / Nn;
    const float sc = fmaxf(g_dsum[b] * (1.0f / ((float)Nn * (float)Mm)), 1e-4f);
    const float invsc = ew_p[0] / sc;
    const float g = gamma_p[0];
    const float q2v = g_q2[row];
    const size_t base = (size_t)row * Mm;
    const int c0 = threadIdx.x * 8;
    float v[8];
    float mx = -1e30f;
#pragma unroll
    for (int q = 0; q < 2; q++) {
        uint4 se = *(const uint4*)&g_SE[base + c0 + q * 4];
        float4 piv = *(const float4*)&pi_star[base + c0 + q * 4];
        float4 k2v = *(const float4*)&g_k2[b * Mm + c0 + q * 4];
        uint32_t ses[4] = {se.x, se.y, se.z, se.w};
        float pis[4] = {piv.x, piv.y, piv.z, piv.w};
        float k2s[4] = {k2v.x, k2v.y, k2v.z, k2v.w};
#pragma unroll
        for (int t = 0; t < 4; t++) {
            float S = hlo(ses[t]), E = hhi(ses[t]);
            float d = sqrtf(fmaxf(q2v + k2s[t] - 2.0f * E, 1e-12f));
            v[q * 4 + t] = S + g * __logf(fmaxf(pis[t], 1e-9f)) - d * invsc;
        }
    }
#pragma unroll
    for (int t = 0; t < 8; t++) mx = fmaxf(mx, v[t]);
    __shared__ float sh[8];
    __shared__ float bc;
    int lane = threadIdx.x & 31, wid = threadIdx.x >> 5;
    float wm = warpRedMax(mx);
    if (lane == 0) sh[wid] = wm;
    __syncthreads();
    if (wid == 0) {
        float t = (lane < 8) ? sh[lane] : -1e30f;
        t = warpRedMax(t);
        if (lane == 0) bc = t;
    }
    __syncthreads();
    mx = bc;
    float sum = 0.0f;
#pragma unroll
    for (int t = 0; t < 8; t++) {
        v[t] = __expf(v[t] - mx);
        sum += v[t];
    }
    __syncthreads();
    float ws = warpRedSum(sum);
    if (lane == 0) sh[wid] = ws;
    __syncthreads();
    if (wid == 0) {
        float t = (lane < 8) ? sh[lane] : 0.0f;
        t = warpRedSum(t);
        if (lane == 0) bc = t;
    }
    __syncthreads();
    const float inv = 1.0f / bc;
    const size_t pbase = (size_t)row * 1024 + threadIdx.x * 4;
#pragma unroll
    for (int p = 0; p < 4; p++)
        g_p1[pbase + p] = cvtH2(v[2 * p] * inv, v[2 * p + 1] * inv);
}

// ---------------- launch ----------------
extern "C" void kernel_launch(void* const* d_in, const int* in_sizes, int n_in,
                              void* d_out, int out_size) {
    const float* q_fp  = (const float*)d_in[0];
    const float* v_ret = (const float*)d_in[1];
    const float* pi    = (const float*)d_in[2];
    const float* Wqs = (const float*)d_in[3];  const float* bqs = (const float*)d_in[4];
    const float* Wks = (const float*)d_in[5];  const float* bks = (const float*)d_in[6];
    const float* Wvs = (const float*)d_in[7];  const float* bvs = (const float*)d_in[8];
    const float* Wqe = (const float*)d_in[9];  const float* bqe = (const float*)d_in[10];
    const float* Wke = (const float*)d_in[11]; const float* bke = (const float*)d_in[12];
    const float* Wve = (const float*)d_in[13]; const float* bve = (const float*)d_in[14];
    const float* W1  = (const float*)d_in[15]; const float* b1  = (const float*)d_in[16];
    const float* W2  = (const float*)d_in[17]; const float* b2  = (const float*)d_in[18];
    const float* gamma = (const float*)d_in[19];
    const float* ew    = (const float*)d_in[20];
    float* out = (float*)d_out;

    uint32_t *qf1, *vr1, *w1p, *f1, *h1;
    uint2 *qp, *kp, *vT2;
    cudaGetSymbolAddress((void**)&qf1, g_qf1);
    cudaGetSymbolAddress((void**)&vr1, g_vr1);
    cudaGetSymbolAddress((void**)&w1p, g_w1p);
    cudaGetSymbolAddress((void**)&qp, g_qp);
    cudaGetSymbolAddress((void**)&kp, g_kp);
    cudaGetSymbolAddress((void**)&vT2, g_vT2);
    cudaGetSymbolAddress((void**)&f1, g_f1);
    cudaGetSymbolAddress((void**)&h1, g_h1);

    const int G2_SMEM    = 10240 * 4;
    const int GEMM_SMEM  = 10240 * 4;
    const int LOGIT_SMEM = 15360 * 4;
    const int CTX_SMEM   = 18432 * 4;
    cudaFuncSetAttribute(gemm2_kernel,   cudaFuncAttributeMaxDynamicSharedMemorySize, G2_SMEM);
    cudaFuncSetAttribute(gemmP_kernel,   cudaFuncAttributeMaxDynamicSharedMemorySize, GEMM_SMEM);
    cudaFuncSetAttribute(logitsP_kernel, cudaFuncAttributeMaxDynamicSharedMemorySize, LOGIT_SMEM);
    cudaFuncSetAttribute(ctxP_kernel,    cudaFuncAttributeMaxDynamicSharedMemorySize, CTX_SMEM);

    uint32_t* wo[8] = {w1p, w1p+65536, w1p+131072, w1p+196608, w1p+262144, w1p+327680,
                       w1p+393216, w1p+524288};

    dim3 gr((Bb*Nn*DIN/2 + 255)/256, 2);
    pack_rows_kernel<<<gr, 256>>>(q_fp, v_ret, qf1, vr1, Bb*Nn*DIN/2);
    pack_all_weights_kernel<<<(557056 + 255)/256, 256>>>(
        Wqs, Wks, Wvs, Wqe, Wke, Wve, W1, W2, w1p);

    dim3 gp(4, (Bb * Nn) / 128, 3);
    gemm2_kernel<<<gp, 256, G2_SMEM>>>(qf1, vr1, w1p,
                                       bqs, bqe, bks, bke, bvs, bve,
                                       qp, kp, vT2);

    dim3 gl(Mm / 64, Nn / 128, Bb);
    logitsP_kernel<<<gl, 256, LOGIT_SMEM>>>();

    softmax_kernel<<<Bb * Nn, 256>>>(pi, gamma, ew);

    dim3 gc(Hh / 64, Nn / 128, Bb);
    ctxP_kernel<<<gc, 256, CTX_SMEM>>>();

    dim3 gm(2, (Bb * Nn) / 128);
    gemmP_kernel<<<gm, 256, GEMM_SMEM>>>(f1, wo[6], b1, nullptr, h1, 512, 256, 1);
    gemmP_kernel<<<gm, 256, GEMM_SMEM>>>(h1, wo[7], b2, out, nullptr, 128, 256, 0);
}